// round 6
// baseline (speedup 1.0000x reference)
#include <cuda_runtime.h>
#include <cstdint>

// Problem constants
#define BB   16
#define CC   128
#define C4C  32
#define NPIX 2304                      // H*W = 48*48
#define NT   18                        // NPIX / 128
#define BN_EPS 1e-5f

static const size_t N2 = (size_t)NPIX * (size_t)NPIX;

// -------- scratch (device globals; no allocation allowed) --------
__device__ float    g_K [BB * C4C * NPIX];           // [b][k][n]
__device__ float    g_Q [BB * C4C * NPIX];           // [b][k][m]
__device__ float    g_V [BB * CC  * NPIX];           // [b][c][m]
__device__ uint16_t g_P [(size_t)BB * NPIX * NPIX];  // bf16 P[b][m][n], 170 MB
__device__ float    g_pZ[BB * NT];
__device__ float    g_M [BB];

// -------- packed f32x2 helpers --------
__device__ __forceinline__ unsigned long long pk2(float lo, float hi) {
    unsigned long long r;
    asm("mov.b64 %0, {%1,%2};" : "=l"(r) : "f"(lo), "f"(hi));
    return r;
}
__device__ __forceinline__ float2 up2(unsigned long long v) {
    float2 r;
    asm("mov.b64 {%0,%1}, %2;" : "=f"(r.x), "=f"(r.y) : "l"(v));
    return r;
}
__device__ __forceinline__ void fma2(unsigned long long& d,
                                     unsigned long long a,
                                     unsigned long long b) {
    asm("fma.rn.f32x2 %0, %1, %2, %0;" : "+l"(d) : "l"(a), "l"(b));
}
__device__ __forceinline__ uint32_t smem_to_u32(const void* p) {
    uint32_t a;
    asm("{ .reg .u64 t; cvta.to.shared.u64 t, %1; cvt.u32.u64 %0, t; }"
        : "=r"(a) : "l"(p));
    return a;
}
__device__ __forceinline__ void cp16(uint32_t dst, const void* src) {
    asm volatile("cp.async.cg.shared.global [%0], [%1], 16;"
                 :: "r"(dst), "l"(src) : "memory");
}
#define CP_COMMIT() asm volatile("cp.async.commit_group;" ::: "memory")
#define CP_WAIT0()  asm volatile("cp.async.wait_group 0;" ::: "memory")

// pack two f32 -> bf16x2 (lo = p0, hi = p1)
__device__ __forceinline__ uint32_t bfpack(float p0, float p1) {
    uint32_t u;
    asm("cvt.rn.bf16x2.f32 %0, %1, %2;" : "=r"(u) : "f"(p1), "f"(p0));
    return u;
}
// unpack bf16x2 -> packed f32x2 (lo, hi)
__device__ __forceinline__ unsigned long long bf2f2(uint32_t x) {
    unsigned long long r;
    asm("mov.b64 %0, {%1,%2};" : "=l"(r)
        : "r"(x << 16), "r"(x & 0xFFFF0000u));
    return r;
}

// ============================================================================
// conv128: Y[b,o,n] = relu( scale[o] * (sum_c W[o,c]*X[b,c,n]) + bias[o] )
// 128(o) x 128(n) tile, cp.async double-buffered k-chunks of 16,
// conflict-free n mapping (n = 2tx + 32j). grid (NT, B), 256 thr.
// ============================================================================
__global__ void __launch_bounds__(256, 2) conv128_kernel(
    const float* __restrict__ X, size_t xStride, int CIN,
    const float* __restrict__ W,
    const float* __restrict__ gam, const float* __restrict__ bet,
    const float* __restrict__ mean, const float* __restrict__ var,
    float* __restrict__ Y, size_t yStride)
{
    __shared__ __align__(16) float Ws[2][128 * 20];   // [o][k] pad 20
    __shared__ __align__(16) float Xs[2][16 * 132];   // [k][n] pad 132
    __shared__ float scale_s[128], bias_s[128];

    const int t  = threadIdx.x;
    const int b  = blockIdx.y;
    const int n0 = blockIdx.x * 128;
    const int ty = t >> 4, tx = t & 15;

    if (t < 128) {
        float s = gam[t] * rsqrtf(var[t] + BN_EPS);
        scale_s[t] = s;
        bias_s[t]  = bet[t] - mean[t] * s;
    }

    const float* Xb = X + (size_t)b * xStride + n0;
    const uint32_t sW = smem_to_u32(Ws), sX = smem_to_u32(Xs);
    const int NCHK = CIN >> 4;

    // loader: W rows o (16 floats), X rows k (128 floats)
    auto load_chunk = [&](int c0, int buf) {
        {
            int o = t >> 1, h = t & 1;                 // 2 cp16 per thread
            uint32_t dst = sW + (uint32_t)(buf * 128 * 20 + o * 20 + h * 8) * 4;
            const float* src = W + (size_t)o * CIN + c0 + h * 8;
            cp16(dst, src); cp16(dst + 16, src + 4);
        }
        {
            int k = t >> 4, seg = t & 15;              // 2 cp16 per thread
            uint32_t dst = sX + (uint32_t)(buf * 16 * 132 + k * 132 + seg * 8) * 4;
            const float* src = Xb + (size_t)(c0 + k) * NPIX + seg * 8;
            cp16(dst, src); cp16(dst + 16, src + 4);
        }
    };

    load_chunk(0, 0);
    CP_COMMIT();

    unsigned long long acc[8][4];
#pragma unroll
    for (int i = 0; i < 8; i++)
#pragma unroll
        for (int j = 0; j < 4; j++) acc[i][j] = 0ull;

    for (int ch = 0; ch < NCHK; ch++) {
        const int buf = ch & 1;
        CP_WAIT0();
        __syncthreads();
        if (ch + 1 < NCHK) { load_chunk((ch + 1) << 4, buf ^ 1); CP_COMMIT(); }

        const float* Wb2 = Ws[buf];
        const float* Xb2 = Xs[buf];
#pragma unroll
        for (int k4 = 0; k4 < 4; k4++) {
            unsigned long long bx[4][4];
#pragma unroll
            for (int kk = 0; kk < 4; kk++)
#pragma unroll
                for (int j = 0; j < 4; j++)
                    bx[kk][j] = *(const unsigned long long*)
                        &Xb2[(k4 * 4 + kk) * 132 + 2 * tx + 32 * j];
#pragma unroll
            for (int i = 0; i < 8; i++) {
                float4 w4 = *(const float4*)&Wb2[(ty * 8 + i) * 20 + k4 * 4];
                unsigned long long d0 = pk2(w4.x, w4.x);
                unsigned long long d1 = pk2(w4.y, w4.y);
                unsigned long long d2 = pk2(w4.z, w4.z);
                unsigned long long d3 = pk2(w4.w, w4.w);
#pragma unroll
                for (int j = 0; j < 4; j++) {
                    fma2(acc[i][j], d0, bx[0][j]);
                    fma2(acc[i][j], d1, bx[1][j]);
                    fma2(acc[i][j], d2, bx[2][j]);
                    fma2(acc[i][j], d3, bx[3][j]);
                }
            }
        }
        __syncthreads();
    }

    float* Yb = Y + (size_t)b * yStride + n0 + 2 * tx;
#pragma unroll
    for (int i = 0; i < 8; i++) {
        int o = ty * 8 + i;
        float s = scale_s[o], bi = bias_s[o];
#pragma unroll
        for (int j = 0; j < 4; j++) {
            float2 p = up2(acc[i][j]);
            *(float2*)&Yb[(size_t)o * NPIX + 32 * j] =
                make_float2(fmaxf(p.x * s + bi, 0.f), fmaxf(p.y * s + bi, 0.f));
        }
    }
}

// ============================================================================
// conv_kq: K/Q = relu(BN(w_kq @ x)),  O = 32, CIN = 128, both stored [k][pix]
// grid (NT, B, 2): z=0 -> K from x_en, z=1 -> Q from x_de
// ============================================================================
__global__ void __launch_bounds__(256, 2) conv_kq_kernel(
    const float* __restrict__ Xen, const float* __restrict__ Xde,
    const float* __restrict__ W,
    const float* __restrict__ gam, const float* __restrict__ bet,
    const float* __restrict__ mean, const float* __restrict__ var)
{
    __shared__ __align__(16) float Ws[2][32 * 20];
    __shared__ __align__(16) float Xs[2][16 * 132];
    __shared__ float scale_s[32], bias_s[32];

    const int t  = threadIdx.x;
    const int b  = blockIdx.y;
    const int n0 = blockIdx.x * 128;
    const int ty = t >> 4, tx = t & 15;
    const float* X = (blockIdx.z == 0) ? Xen : Xde;
    float* Yg      = (blockIdx.z == 0) ? g_K : g_Q;

    if (t < 32) {
        float s = gam[t] * rsqrtf(var[t] + BN_EPS);
        scale_s[t] = s;
        bias_s[t]  = bet[t] - mean[t] * s;
    }

    const float* Xb = X + (size_t)b * CC * NPIX + n0;
    const uint32_t sW = smem_to_u32(Ws), sX = smem_to_u32(Xs);

    auto load_chunk = [&](int c0, int buf) {
        if (t < 128) {
            int o = t >> 2, q = t & 3;                 // 1 cp16
            cp16(sW + (uint32_t)(buf * 32 * 20 + o * 20 + q * 4) * 4,
                 W + (size_t)o * CC + c0 + q * 4);
        }
        {
            int k = t >> 4, seg = t & 15;
            uint32_t dst = sX + (uint32_t)(buf * 16 * 132 + k * 132 + seg * 8) * 4;
            const float* src = Xb + (size_t)(c0 + k) * NPIX + seg * 8;
            cp16(dst, src); cp16(dst + 16, src + 4);
        }
    };

    load_chunk(0, 0);
    CP_COMMIT();

    unsigned long long acc[2][4];
#pragma unroll
    for (int i = 0; i < 2; i++)
#pragma unroll
        for (int j = 0; j < 4; j++) acc[i][j] = 0ull;

    for (int ch = 0; ch < 8; ch++) {
        const int buf = ch & 1;
        CP_WAIT0();
        __syncthreads();
        if (ch + 1 < 8) { load_chunk((ch + 1) << 4, buf ^ 1); CP_COMMIT(); }

        const float* Wb2 = Ws[buf];
        const float* Xb2 = Xs[buf];
#pragma unroll
        for (int k4 = 0; k4 < 4; k4++) {
            unsigned long long bx[4][4];
#pragma unroll
            for (int kk = 0; kk < 4; kk++)
#pragma unroll
                for (int j = 0; j < 4; j++)
                    bx[kk][j] = *(const unsigned long long*)
                        &Xb2[(k4 * 4 + kk) * 132 + 2 * tx + 32 * j];
#pragma unroll
            for (int i = 0; i < 2; i++) {
                float4 w4 = *(const float4*)&Wb2[(ty * 2 + i) * 20 + k4 * 4];
                unsigned long long d0 = pk2(w4.x, w4.x);
                unsigned long long d1 = pk2(w4.y, w4.y);
                unsigned long long d2 = pk2(w4.z, w4.z);
                unsigned long long d3 = pk2(w4.w, w4.w);
#pragma unroll
                for (int j = 0; j < 4; j++) {
                    fma2(acc[i][j], d0, bx[0][j]);
                    fma2(acc[i][j], d1, bx[1][j]);
                    fma2(acc[i][j], d2, bx[2][j]);
                    fma2(acc[i][j], d3, bx[3][j]);
                }
            }
        }
        __syncthreads();
    }

    float* Yb = Yg + (size_t)b * C4C * NPIX + n0 + 2 * tx;
#pragma unroll
    for (int i = 0; i < 2; i++) {
        int o = ty * 2 + i;
        float s = scale_s[o], bi = bias_s[o];
#pragma unroll
        for (int j = 0; j < 4; j++) {
            float2 p = up2(acc[i][j]);
            *(float2*)&Yb[(size_t)o * NPIX + 32 * j] =
                make_float2(fmaxf(p.x * s + bi, 0.f), fmaxf(p.y * s + bi, 0.f));
        }
    }
}

// ============================================================================
// norm: M'[b] = max_n ||K[b,:,n]|| * max_m ||Q[b,:,m]||  (Cauchy-Schwarz bound)
// ============================================================================
__global__ void __launch_bounds__(256) norm_kernel()
{
    __shared__ float r1[256], r2[256];
    const int b = blockIdx.x, t = threadIdx.x;
    const float* Kb = g_K + (size_t)b * C4C * NPIX;
    const float* Qb = g_Q + (size_t)b * C4C * NPIX;

    float mk = 0.f, mq = 0.f;
    for (int n = t; n < NPIX; n += 256) {
        float sk = 0.f, sq = 0.f;
#pragma unroll
        for (int k = 0; k < C4C; k++) {
            float vk = Kb[(size_t)k * NPIX + n];
            float vq = Qb[(size_t)k * NPIX + n];
            sk += vk * vk;
            sq += vq * vq;
        }
        mk = fmaxf(mk, sk);
        mq = fmaxf(mq, sq);
    }
    r1[t] = mk; r2[t] = mq;
    __syncthreads();
    for (int s = 128; s > 0; s >>= 1) {
        if (t < s) { r1[t] = fmaxf(r1[t], r1[t + s]); r2[t] = fmaxf(r2[t], r2[t + s]); }
        __syncthreads();
    }
    if (t == 0) g_M[b] = sqrtf(r1[0]) * sqrtf(r2[0]);
}

// ============================================================================
// pgemm: P[b,m,n] = exp( sum_k Q[b,k,m]*K[b,k,n] - M'[b] ), stored bf16.
// Block = n-tile (128); K-tile resident in smem; 18 m-tiles streamed with
// cp.async double buffering. Accumulates Z partial per block.
// grid (NT, B), 256 thr.  smem dyn: Ks[32*136] + Qs[2][32*136]
// ============================================================================
#define PG_K_OFF  0
#define PG_Q_OFF  (32 * 136)
#define PG_SMEM_FLOATS (3 * 32 * 136)
#define PG_SMEM_BYTES  (PG_SMEM_FLOATS * 4)

__global__ void __launch_bounds__(256, 2) pgemm_kernel()
{
    extern __shared__ __align__(16) float ps[];
    __shared__ float zred[256];

    const int t  = threadIdx.x;
    const int b  = blockIdx.y;
    const int n0 = blockIdx.x * 128;
    const int ty = t >> 4, tx = t & 15;
    const float Mb = g_M[b];

    const float* Kg = g_K + (size_t)b * C4C * NPIX + n0;
    const float* Qg = g_Q + (size_t)b * C4C * NPIX;
    const uint32_t sb = smem_to_u32(ps);

    // K tile: 32 rows x 128 floats (4 cp16/thread)
    {
        int k = t >> 3, seg = t & 7;
        uint32_t dst = sb + (uint32_t)(PG_K_OFF + k * 136 + seg * 16) * 4;
        const float* src = Kg + (size_t)k * NPIX + seg * 16;
        cp16(dst, src); cp16(dst + 16, src + 4);
        cp16(dst + 32, src + 8); cp16(dst + 48, src + 12);
    }
    // Q tile loader
    auto load_q = [&](int mt, int buf) {
        int k = t >> 3, seg = t & 7;
        uint32_t dst = sb + (uint32_t)(PG_Q_OFF + buf * 32 * 136 + k * 136 + seg * 16) * 4;
        const float* src = Qg + (size_t)k * NPIX + mt * 128 + seg * 16;
        cp16(dst, src); cp16(dst + 16, src + 4);
        cp16(dst + 32, src + 8); cp16(dst + 48, src + 12);
    };
    load_q(0, 0);
    CP_COMMIT();

    float zacc = 0.f;
    const float* Ks = ps + PG_K_OFF;

    for (int mt = 0; mt < NT; mt++) {
        const int buf = mt & 1;
        CP_WAIT0();
        __syncthreads();
        if (mt + 1 < NT) { load_q(mt + 1, buf ^ 1); CP_COMMIT(); }

        const float* Qs = ps + PG_Q_OFF + buf * 32 * 136;

        unsigned long long acc[8][4];
#pragma unroll
        for (int i = 0; i < 8; i++)
#pragma unroll
            for (int j = 0; j < 4; j++) acc[i][j] = 0ull;

#pragma unroll 4
        for (int k = 0; k < 32; k++) {
            unsigned long long bv[4];
#pragma unroll
            for (int j = 0; j < 4; j++)
                bv[j] = *(const unsigned long long*)&Ks[k * 136 + 2 * tx + 32 * j];
            float4 a0 = *(const float4*)&Qs[k * 136 + ty * 8];
            float4 a1 = *(const float4*)&Qs[k * 136 + ty * 8 + 4];
            unsigned long long ad[8] = {
                pk2(a0.x, a0.x), pk2(a0.y, a0.y), pk2(a0.z, a0.z), pk2(a0.w, a0.w),
                pk2(a1.x, a1.x), pk2(a1.y, a1.y), pk2(a1.z, a1.z), pk2(a1.w, a1.w)};
#pragma unroll
            for (int i = 0; i < 8; i++)
#pragma unroll
                for (int j = 0; j < 4; j++) fma2(acc[i][j], ad[i], bv[j]);
        }

        // epilogue: exp, Z, bf16 store (P[b][m][n])
#pragma unroll
        for (int i = 0; i < 8; i++) {
            int m = mt * 128 + ty * 8 + i;
            uint16_t* Pr = g_P + ((size_t)b * NPIX + m) * NPIX + n0 + 2 * tx;
#pragma unroll
            for (int j = 0; j < 4; j++) {
                float2 p = up2(acc[i][j]);
                float e0 = __expf(p.x - Mb);
                float e1 = __expf(p.y - Mb);
                zacc += e0 + e1;
                *(uint32_t*)&Pr[32 * j] = bfpack(e0, e1);
            }
        }
        __syncthreads();   // keep Q buffer safe for next cp.async round
    }

    zred[t] = zacc;
    __syncthreads();
    for (int s = 128; s > 0; s >>= 1) {
        if (t < s) zred[t] += zred[t + s];
        __syncthreads();
    }
    if (t == 0) g_pZ[b * NT + blockIdx.x] = zred[0];
}

// ============================================================================
// feat: out[b,C+c,n] = (1/Z) * sum_m V[b,c,m] * P_bf16[b,m,n]
// Block = n-tile (128) x all c (128); m-chunks of 32, cp.async double buffer.
// No exp, no transpose: V [c][m] direct, P [m][n] direct.
// grid (NT, B), 256 thr.  smem dyn: Vs[2][128*36] f32 + Pu[2][32*64] u32
// ============================================================================
#define FT_V_OFF  0
#define FT_P_OFF  (2 * 128 * 36)                 // 9216
#define FT_SMEM_FLOATS (2 * 128 * 36 + 2 * 32 * 64)
#define FT_SMEM_BYTES  (FT_SMEM_FLOATS * 4)

__global__ void __launch_bounds__(256, 2) feat_kernel(float* __restrict__ out)
{
    extern __shared__ __align__(16) float fsm[];
    __shared__ float zs;

    const int t  = threadIdx.x;
    const int b  = blockIdx.y;
    const int n0 = blockIdx.x * 128;
    const int ty = t >> 4, tx = t & 15;

    if (t == 0) {
        float z = 0.f;
#pragma unroll
        for (int j = 0; j < NT; j++) z += g_pZ[b * NT + j];
        zs = 1.f / z;
    }

    const float*    Vg = g_V + (size_t)b * CC * NPIX;
    const uint16_t* Pg = g_P + (size_t)b * NPIX * NPIX + n0;
    const uint32_t  sbv = smem_to_u32(fsm);
    const uint32_t  sbp = sbv + FT_P_OFF * 4;

    auto load_chunk = [&](int m0, int buf) {
        {
            int c = t >> 1, h = t & 1;                       // V: 4 cp16
            uint32_t dst = sbv + (uint32_t)(buf * 128 * 36 + c * 36 + h * 16) * 4;
            const float* src = Vg + (size_t)c * NPIX + m0 + h * 16;
            cp16(dst, src); cp16(dst + 16, src + 4);
            cp16(dst + 32, src + 8); cp16(dst + 48, src + 12);
        }
        {
            int k = t >> 3, seg = t & 7;                     // P: 2 cp16
            uint32_t dst = sbp + (uint32_t)(buf * 32 * 64 + k * 64 + seg * 8) * 4;
            const uint16_t* src = Pg + (size_t)(m0 + k) * NPIX + seg * 16;
            cp16(dst, src); cp16(dst + 16, (const char*)src + 16);
        }
    };

    load_chunk(0, 0);
    CP_COMMIT();

    unsigned long long acc[8][4];
#pragma unroll
    for (int i = 0; i < 8; i++)
#pragma unroll
        for (int j = 0; j < 4; j++) acc[i][j] = 0ull;

    for (int ch = 0; ch < 72; ch++) {
        const int buf = ch & 1;
        CP_WAIT0();
        __syncthreads();
        if (ch + 1 < 72) { load_chunk((ch + 1) * 32, buf ^ 1); CP_COMMIT(); }

        const float*    Vs = fsm + buf * 128 * 36;
        const uint32_t* Pu = (const uint32_t*)(fsm + FT_P_OFF) + buf * 32 * 64;

#pragma unroll
        for (int k4 = 0; k4 < 8; k4++) {
            unsigned long long bx[4][4];
#pragma unroll
            for (int kk = 0; kk < 4; kk++)
#pragma unroll
                for (int j = 0; j < 4; j++)
                    bx[kk][j] = bf2f2(Pu[(k4 * 4 + kk) * 64 + tx + 16 * j]);
#pragma unroll
            for (int i = 0; i < 8; i++) {
                float4 v4 = *(const float4*)&Vs[(ty * 8 + i) * 36 + k4 * 4];
                unsigned long long d0 = pk2(v4.x, v4.x);
                unsigned long long d1 = pk2(v4.y, v4.y);
                unsigned long long d2 = pk2(v4.z, v4.z);
                unsigned long long d3 = pk2(v4.w, v4.w);
#pragma unroll
                for (int j = 0; j < 4; j++) {
                    fma2(acc[i][j], d0, bx[0][j]);
                    fma2(acc[i][j], d1, bx[1][j]);
                    fma2(acc[i][j], d2, bx[2][j]);
                    fma2(acc[i][j], d3, bx[3][j]);
                }
            }
        }
        __syncthreads();
    }

    const float invZ = zs;
    float* Ob = out + (size_t)b * (2 * CC) * NPIX + (size_t)CC * NPIX + n0 + 2 * tx;
#pragma unroll
    for (int i = 0; i < 8; i++) {
        int c = ty * 8 + i;
#pragma unroll
        for (int j = 0; j < 4; j++) {
            float2 p = up2(acc[i][j]);
            *(float2*)&Ob[(size_t)c * NPIX + 32 * j] =
                make_float2(p.x * invZ, p.y * invZ);
        }
    }
}

// ============================================================================
// launch
// ============================================================================
extern "C" void kernel_launch(void* const* d_in, const int* in_sizes, int n_in,
                              void* d_out, int out_size)
{
    const float* x_en   = (const float*)d_in[0];
    const float* x_de   = (const float*)d_in[1];
    const float* x_cat  = (const float*)d_in[2];
    const float* w_kq   = (const float*)d_in[3];
    const float* kq_g   = (const float*)d_in[4];
    const float* kq_b   = (const float*)d_in[5];
    const float* kq_m   = (const float*)d_in[6];
    const float* kq_v   = (const float*)d_in[7];
    const float* w_v    = (const float*)d_in[8];
    const float* v_g    = (const float*)d_in[9];
    const float* v_b    = (const float*)d_in[10];
    const float* v_m    = (const float*)d_in[11];
    const float* v_v    = (const float*)d_in[12];
    const float* w_red  = (const float*)d_in[13];
    const float* red_g  = (const float*)d_in[14];
    const float* red_b  = (const float*)d_in[15];
    const float* red_m  = (const float*)d_in[16];
    const float* red_v  = (const float*)d_in[17];
    float* out = (float*)d_out;

    float* pV = nullptr;
    cudaGetSymbolAddress((void**)&pV, g_V);

    cudaFuncSetAttribute(pgemm_kernel,
                         cudaFuncAttributeMaxDynamicSharedMemorySize, PG_SMEM_BYTES);
    cudaFuncSetAttribute(feat_kernel,
                         cudaFuncAttributeMaxDynamicSharedMemorySize, FT_SMEM_BYTES);

    const size_t twoCN = (size_t)2 * CC * NPIX;
    const size_t CN    = (size_t)CC * NPIX;

    // K, Q  (both [k][pix])
    conv_kq_kernel<<<dim3(NT, BB, 2), 256>>>(x_en, x_de, w_kq,
                                             kq_g, kq_b, kq_m, kq_v);
    // M' per batch (Cauchy-Schwarz upper bound)
    norm_kernel<<<BB, 256>>>();
    // x = relu(BN(w_red @ x_cat)) -> output channels [0, C)
    conv128_kernel<<<dim3(NT, BB), 256>>>(x_cat, twoCN, 2 * CC, w_red,
                                          red_g, red_b, red_m, red_v,
                                          out, twoCN);
    // V = relu(BN(w_v @ x))
    conv128_kernel<<<dim3(NT, BB), 256>>>(out, twoCN, CC, w_v,
                                          v_g, v_b, v_m, v_v,
                                          pV, CN);
    // P = exp(QK - M') in bf16 + Z partials (fused, single pass)
    pgemm_kernel<<<dim3(NT, BB), 256, PG_SMEM_BYTES>>>();
    // feat = V @ P / Z -> output channels [C, 2C)
    feat_kernel<<<dim3(NT, BB), 256, FT_SMEM_BYTES>>>(out);
}

// round 7
// speedup vs baseline: 2.0396x; 2.0396x over previous
#include <cuda_runtime.h>
#include <cstdint>

// Problem constants
#define BB   16
#define CC   128
#define C4C  32
#define NPIX 2304                      // H*W = 48*48
#define NT   18                        // NPIX / 128
#define BN_EPS 1e-5f

static const size_t N2 = (size_t)NPIX * (size_t)NPIX;

// -------- scratch (device globals; no allocation allowed) --------
__device__ float    g_K [BB * C4C * NPIX];           // [b][k][n]
__device__ float    g_Q [BB * C4C * NPIX];           // [b][k][m]
__device__ uint16_t g_Vh[BB * CC  * NPIX];           // bf16 V [b][c][m]
__device__ uint16_t g_P [(size_t)BB * NPIX * NPIX];  // bf16 P[b][m][n], 170 MB
__device__ float    g_pZ[BB * NT];
__device__ float    g_M [BB];

// -------- packed f32x2 helpers --------
__device__ __forceinline__ unsigned long long pk2(float lo, float hi) {
    unsigned long long r;
    asm("mov.b64 %0, {%1,%2};" : "=l"(r) : "f"(lo), "f"(hi));
    return r;
}
__device__ __forceinline__ float2 up2(unsigned long long v) {
    float2 r;
    asm("mov.b64 {%0,%1}, %2;" : "=f"(r.x), "=f"(r.y) : "l"(v));
    return r;
}
__device__ __forceinline__ void fma2(unsigned long long& d,
                                     unsigned long long a,
                                     unsigned long long b) {
    asm("fma.rn.f32x2 %0, %1, %2, %0;" : "+l"(d) : "l"(a), "l"(b));
}
__device__ __forceinline__ uint32_t smem_to_u32(const void* p) {
    uint32_t a;
    asm("{ .reg .u64 t; cvta.to.shared.u64 t, %1; cvt.u32.u64 %0, t; }"
        : "=r"(a) : "l"(p));
    return a;
}
__device__ __forceinline__ void cp16(uint32_t dst, const void* src) {
    asm volatile("cp.async.cg.shared.global [%0], [%1], 16;"
                 :: "r"(dst), "l"(src) : "memory");
}
#define CP_COMMIT() asm volatile("cp.async.commit_group;" ::: "memory")
#define CP_WAIT0()  asm volatile("cp.async.wait_group 0;" ::: "memory")

// pack two f32 -> bf16x2 (lo = p0, hi = p1)
__device__ __forceinline__ uint32_t bfpack(float p0, float p1) {
    uint32_t u;
    asm("cvt.rn.bf16x2.f32 %0, %1, %2;" : "=r"(u) : "f"(p1), "f"(p0));
    return u;
}
__device__ __forceinline__ void stcs32(uint16_t* p, uint32_t v) {
    asm volatile("st.global.cs.b32 [%0], %1;" :: "l"(p), "r"(v) : "memory");
}

// -------- mma.sync bf16 + ldmatrix (family-portable, sm_80+) --------
__device__ __forceinline__ void ldsm_x4(uint32_t* r, uint32_t a) {
    asm volatile("ldmatrix.sync.aligned.m8n8.x4.shared.b16 {%0,%1,%2,%3}, [%4];"
        : "=r"(r[0]), "=r"(r[1]), "=r"(r[2]), "=r"(r[3]) : "r"(a));
}
__device__ __forceinline__ void ldsm_x2t(uint32_t* r, uint32_t a) {
    asm volatile("ldmatrix.sync.aligned.m8n8.x2.trans.shared.b16 {%0,%1}, [%2];"
        : "=r"(r[0]), "=r"(r[1]) : "r"(a));
}
__device__ __forceinline__ void mma_bf16(float* d, const uint32_t* a,
                                         const uint32_t* b) {
    asm volatile(
        "mma.sync.aligned.m16n8k16.row.col.f32.bf16.bf16.f32 "
        "{%0,%1,%2,%3},{%4,%5,%6,%7},{%8,%9},{%0,%1,%2,%3};"
        : "+f"(d[0]), "+f"(d[1]), "+f"(d[2]), "+f"(d[3])
        : "r"(a[0]), "r"(a[1]), "r"(a[2]), "r"(a[3]), "r"(b[0]), "r"(b[1]));
}

// ============================================================================
// conv128: Y = relu( scale * (W @ X) + bias ),  O = 128.
// fp32 out (Yf) OR bf16 out (Yh, stride NPIX). cp.async double-buffered,
// conflict-free n mapping. grid (NT, B), 256 thr.
// ============================================================================
__global__ void __launch_bounds__(256, 2) conv128_kernel(
    const float* __restrict__ X, size_t xStride, int CIN,
    const float* __restrict__ W,
    const float* __restrict__ gam, const float* __restrict__ bet,
    const float* __restrict__ mean, const float* __restrict__ var,
    float* __restrict__ Yf, size_t yStride, uint16_t* __restrict__ Yh)
{
    __shared__ __align__(16) float Ws[2][128 * 20];   // [o][k] pad 20
    __shared__ __align__(16) float Xs[2][16 * 132];   // [k][n] pad 132
    __shared__ float scale_s[128], bias_s[128];

    const int t  = threadIdx.x;
    const int b  = blockIdx.y;
    const int n0 = blockIdx.x * 128;
    const int ty = t >> 4, tx = t & 15;

    if (t < 128) {
        float s = gam[t] * rsqrtf(var[t] + BN_EPS);
        scale_s[t] = s;
        bias_s[t]  = bet[t] - mean[t] * s;
    }

    const float* Xb = X + (size_t)b * xStride + n0;
    const uint32_t sW = smem_to_u32(Ws), sX = smem_to_u32(Xs);
    const int NCHK = CIN >> 4;

    auto load_chunk = [&](int c0, int buf) {
        {
            int o = t >> 1, h = t & 1;
            uint32_t dst = sW + (uint32_t)(buf * 128 * 20 + o * 20 + h * 8) * 4;
            const float* src = W + (size_t)o * CIN + c0 + h * 8;
            cp16(dst, src); cp16(dst + 16, src + 4);
        }
        {
            int k = t >> 4, seg = t & 15;
            uint32_t dst = sX + (uint32_t)(buf * 16 * 132 + k * 132 + seg * 8) * 4;
            const float* src = Xb + (size_t)(c0 + k) * NPIX + seg * 8;
            cp16(dst, src); cp16(dst + 16, src + 4);
        }
    };

    load_chunk(0, 0);
    CP_COMMIT();

    unsigned long long acc[8][4];
#pragma unroll
    for (int i = 0; i < 8; i++)
#pragma unroll
        for (int j = 0; j < 4; j++) acc[i][j] = 0ull;

    for (int ch = 0; ch < NCHK; ch++) {
        const int buf = ch & 1;
        CP_WAIT0();
        __syncthreads();
        if (ch + 1 < NCHK) { load_chunk((ch + 1) << 4, buf ^ 1); CP_COMMIT(); }

        const float* Wb2 = Ws[buf];
        const float* Xb2 = Xs[buf];
#pragma unroll
        for (int k4 = 0; k4 < 4; k4++) {
            unsigned long long bx[4][4];
#pragma unroll
            for (int kk = 0; kk < 4; kk++)
#pragma unroll
                for (int j = 0; j < 4; j++)
                    bx[kk][j] = *(const unsigned long long*)
                        &Xb2[(k4 * 4 + kk) * 132 + 2 * tx + 32 * j];
#pragma unroll
            for (int i = 0; i < 8; i++) {
                float4 w4 = *(const float4*)&Wb2[(ty * 8 + i) * 20 + k4 * 4];
                unsigned long long d0 = pk2(w4.x, w4.x);
                unsigned long long d1 = pk2(w4.y, w4.y);
                unsigned long long d2 = pk2(w4.z, w4.z);
                unsigned long long d3 = pk2(w4.w, w4.w);
#pragma unroll
                for (int j = 0; j < 4; j++) {
                    fma2(acc[i][j], d0, bx[0][j]);
                    fma2(acc[i][j], d1, bx[1][j]);
                    fma2(acc[i][j], d2, bx[2][j]);
                    fma2(acc[i][j], d3, bx[3][j]);
                }
            }
        }
        __syncthreads();
    }

    if (Yh == nullptr) {
        float* Yb = Yf + (size_t)b * yStride + n0 + 2 * tx;
#pragma unroll
        for (int i = 0; i < 8; i++) {
            int o = ty * 8 + i;
            float s = scale_s[o], bi = bias_s[o];
#pragma unroll
            for (int j = 0; j < 4; j++) {
                float2 p = up2(acc[i][j]);
                *(float2*)&Yb[(size_t)o * NPIX + 32 * j] =
                    make_float2(fmaxf(p.x * s + bi, 0.f), fmaxf(p.y * s + bi, 0.f));
            }
        }
    } else {
        uint16_t* Yb = Yh + (size_t)b * CC * NPIX + n0 + 2 * tx;
#pragma unroll
        for (int i = 0; i < 8; i++) {
            int o = ty * 8 + i;
            float s = scale_s[o], bi = bias_s[o];
#pragma unroll
            for (int j = 0; j < 4; j++) {
                float2 p = up2(acc[i][j]);
                *(uint32_t*)&Yb[(size_t)o * NPIX + 32 * j] =
                    bfpack(fmaxf(p.x * s + bi, 0.f), fmaxf(p.y * s + bi, 0.f));
            }
        }
    }
}

// ============================================================================
// conv_kq: K/Q = relu(BN(w_kq @ x)),  O = 32, CIN = 128, both stored [k][pix]
// ============================================================================
__global__ void __launch_bounds__(256, 2) conv_kq_kernel(
    const float* __restrict__ Xen, const float* __restrict__ Xde,
    const float* __restrict__ W,
    const float* __restrict__ gam, const float* __restrict__ bet,
    const float* __restrict__ mean, const float* __restrict__ var)
{
    __shared__ __align__(16) float Ws[2][32 * 20];
    __shared__ __align__(16) float Xs[2][16 * 132];
    __shared__ float scale_s[32], bias_s[32];

    const int t  = threadIdx.x;
    const int b  = blockIdx.y;
    const int n0 = blockIdx.x * 128;
    const int ty = t >> 4, tx = t & 15;
    const float* X = (blockIdx.z == 0) ? Xen : Xde;
    float* Yg      = (blockIdx.z == 0) ? g_K : g_Q;

    if (t < 32) {
        float s = gam[t] * rsqrtf(var[t] + BN_EPS);
        scale_s[t] = s;
        bias_s[t]  = bet[t] - mean[t] * s;
    }

    const float* Xb = X + (size_t)b * CC * NPIX + n0;
    const uint32_t sW = smem_to_u32(Ws), sX = smem_to_u32(Xs);

    auto load_chunk = [&](int c0, int buf) {
        if (t < 128) {
            int o = t >> 2, q = t & 3;
            cp16(sW + (uint32_t)(buf * 32 * 20 + o * 20 + q * 4) * 4,
                 W + (size_t)o * CC + c0 + q * 4);
        }
        {
            int k = t >> 4, seg = t & 15;
            uint32_t dst = sX + (uint32_t)(buf * 16 * 132 + k * 132 + seg * 8) * 4;
            const float* src = Xb + (size_t)(c0 + k) * NPIX + seg * 8;
            cp16(dst, src); cp16(dst + 16, src + 4);
        }
    };

    load_chunk(0, 0);
    CP_COMMIT();

    unsigned long long acc[2][4];
#pragma unroll
    for (int i = 0; i < 2; i++)
#pragma unroll
        for (int j = 0; j < 4; j++) acc[i][j] = 0ull;

    for (int ch = 0; ch < 8; ch++) {
        const int buf = ch & 1;
        CP_WAIT0();
        __syncthreads();
        if (ch + 1 < 8) { load_chunk((ch + 1) << 4, buf ^ 1); CP_COMMIT(); }

        const float* Wb2 = Ws[buf];
        const float* Xb2 = Xs[buf];
#pragma unroll
        for (int k4 = 0; k4 < 4; k4++) {
            unsigned long long bx[4][4];
#pragma unroll
            for (int kk = 0; kk < 4; kk++)
#pragma unroll
                for (int j = 0; j < 4; j++)
                    bx[kk][j] = *(const unsigned long long*)
                        &Xb2[(k4 * 4 + kk) * 132 + 2 * tx + 32 * j];
#pragma unroll
            for (int i = 0; i < 2; i++) {
                float4 w4 = *(const float4*)&Wb2[(ty * 2 + i) * 20 + k4 * 4];
                unsigned long long d0 = pk2(w4.x, w4.x);
                unsigned long long d1 = pk2(w4.y, w4.y);
                unsigned long long d2 = pk2(w4.z, w4.z);
                unsigned long long d3 = pk2(w4.w, w4.w);
#pragma unroll
                for (int j = 0; j < 4; j++) {
                    fma2(acc[i][j], d0, bx[0][j]);
                    fma2(acc[i][j], d1, bx[1][j]);
                    fma2(acc[i][j], d2, bx[2][j]);
                    fma2(acc[i][j], d3, bx[3][j]);
                }
            }
        }
        __syncthreads();
    }

    float* Yb = Yg + (size_t)b * C4C * NPIX + n0 + 2 * tx;
#pragma unroll
    for (int i = 0; i < 2; i++) {
        int o = ty * 2 + i;
        float s = scale_s[o], bi = bias_s[o];
#pragma unroll
        for (int j = 0; j < 4; j++) {
            float2 p = up2(acc[i][j]);
            *(float2*)&Yb[(size_t)o * NPIX + 32 * j] =
                make_float2(fmaxf(p.x * s + bi, 0.f), fmaxf(p.y * s + bi, 0.f));
        }
    }
}

// ============================================================================
// norm: M'[b] = max_n ||K[b,:,n]|| * max_m ||Q[b,:,m]||  (Cauchy-Schwarz)
// ============================================================================
__global__ void __launch_bounds__(256) norm_kernel()
{
    __shared__ float r1[256], r2[256];
    const int b = blockIdx.x, t = threadIdx.x;
    const float* Kb = g_K + (size_t)b * C4C * NPIX;
    const float* Qb = g_Q + (size_t)b * C4C * NPIX;

    float mk = 0.f, mq = 0.f;
    for (int n = t; n < NPIX; n += 256) {
        float sk = 0.f, sq = 0.f;
#pragma unroll
        for (int k = 0; k < C4C; k++) {
            float vk = Kb[(size_t)k * NPIX + n];
            float vq = Qb[(size_t)k * NPIX + n];
            sk += vk * vk;
            sq += vq * vq;
        }
        mk = fmaxf(mk, sk);
        mq = fmaxf(mq, sq);
    }
    r1[t] = mk; r2[t] = mq;
    __syncthreads();
    for (int s = 128; s > 0; s >>= 1) {
        if (t < s) { r1[t] = fmaxf(r1[t], r1[t + s]); r2[t] = fmaxf(r2[t], r2[t + s]); }
        __syncthreads();
    }
    if (t == 0) g_M[b] = sqrtf(r1[0]) * sqrtf(r2[0]);
}

// ============================================================================
// pgemm: P[b,m,n] = exp( sum_k Q[b,k,m]*K[b,k,n] - M'[b] ), bf16 out (streaming).
// K-tile resident; 18 m-tiles double-buffered. Z partial per block.
// ============================================================================
#define PG_K_OFF  0
#define PG_Q_OFF  (32 * 136)
#define PG_SMEM_BYTES  (3 * 32 * 136 * 4)

__global__ void __launch_bounds__(256, 2) pgemm_kernel()
{
    extern __shared__ __align__(16) float ps[];
    __shared__ float zred[256];

    const int t  = threadIdx.x;
    const int b  = blockIdx.y;
    const int n0 = blockIdx.x * 128;
    const int ty = t >> 4, tx = t & 15;
    const float Mb = g_M[b];

    const float* Kg = g_K + (size_t)b * C4C * NPIX + n0;
    const float* Qg = g_Q + (size_t)b * C4C * NPIX;
    const uint32_t sb = smem_to_u32(ps);

    {
        int k = t >> 3, seg = t & 7;
        uint32_t dst = sb + (uint32_t)(PG_K_OFF + k * 136 + seg * 16) * 4;
        const float* src = Kg + (size_t)k * NPIX + seg * 16;
        cp16(dst, src); cp16(dst + 16, src + 4);
        cp16(dst + 32, src + 8); cp16(dst + 48, src + 12);
    }
    auto load_q = [&](int mt, int buf) {
        int k = t >> 3, seg = t & 7;
        uint32_t dst = sb + (uint32_t)(PG_Q_OFF + buf * 32 * 136 + k * 136 + seg * 16) * 4;
        const float* src = Qg + (size_t)k * NPIX + mt * 128 + seg * 16;
        cp16(dst, src); cp16(dst + 16, src + 4);
        cp16(dst + 32, src + 8); cp16(dst + 48, src + 12);
    };
    load_q(0, 0);
    CP_COMMIT();

    float zacc = 0.f;
    const float* Ks = ps + PG_K_OFF;

    for (int mt = 0; mt < NT; mt++) {
        const int buf = mt & 1;
        CP_WAIT0();
        __syncthreads();
        if (mt + 1 < NT) { load_q(mt + 1, buf ^ 1); CP_COMMIT(); }

        const float* Qs = ps + PG_Q_OFF + buf * 32 * 136;

        unsigned long long acc[8][4];
#pragma unroll
        for (int i = 0; i < 8; i++)
#pragma unroll
            for (int j = 0; j < 4; j++) acc[i][j] = 0ull;

#pragma unroll 4
        for (int k = 0; k < 32; k++) {
            unsigned long long bv[4];
#pragma unroll
            for (int j = 0; j < 4; j++)
                bv[j] = *(const unsigned long long*)&Ks[k * 136 + 2 * tx + 32 * j];
            float4 a0 = *(const float4*)&Qs[k * 136 + ty * 8];
            float4 a1 = *(const float4*)&Qs[k * 136 + ty * 8 + 4];
            unsigned long long ad[8] = {
                pk2(a0.x, a0.x), pk2(a0.y, a0.y), pk2(a0.z, a0.z), pk2(a0.w, a0.w),
                pk2(a1.x, a1.x), pk2(a1.y, a1.y), pk2(a1.z, a1.z), pk2(a1.w, a1.w)};
#pragma unroll
            for (int i = 0; i < 8; i++)
#pragma unroll
                for (int j = 0; j < 4; j++) fma2(acc[i][j], ad[i], bv[j]);
        }

#pragma unroll
        for (int i = 0; i < 8; i++) {
            int m = mt * 128 + ty * 8 + i;
            uint16_t* Pr = g_P + ((size_t)b * NPIX + m) * NPIX + n0 + 2 * tx;
#pragma unroll
            for (int j = 0; j < 4; j++) {
                float2 p = up2(acc[i][j]);
                float e0 = __expf(p.x - Mb);
                float e1 = __expf(p.y - Mb);
                zacc += e0 + e1;
                stcs32(Pr + 32 * j, bfpack(e0, e1));
            }
        }
        __syncthreads();
    }

    zred[t] = zacc;
    __syncthreads();
    for (int s = 128; s > 0; s >>= 1) {
        if (t < s) zred[t] += zred[t + s];
        __syncthreads();
    }
    if (t == 0) g_pZ[b * NT + blockIdx.x] = zred[0];
}

// ============================================================================
// feat: out[b,C+c,n] = (1/Z) * sum_m Vh[b,c,m] * P[b,m,n]  -- bf16 mma.sync.
// Block 128c x 128n; m chunks of 64; cp.async double buffer; ldmatrix feeds.
// Warp grid 2(c) x 4(n): warp tile 64c x 32n = 4x4 m16n8k16 tiles.
// grid (NT, B), 256 thr.
// ============================================================================
#define FH_VST 72                       // bf16 per V smem row (64 + 8 pad)
#define FH_PST 136                      // bf16 per P smem row (128 + 8 pad)
#define FH_VSZ (128 * FH_VST)           // 9216 elems / buf
#define FH_PSZ (64 * FH_PST)            // 8704 elems / buf
#define FH_SMEM_BYTES ((2 * FH_VSZ + 2 * FH_PSZ) * 2)   // 71680

__global__ void __launch_bounds__(256, 2) feat_kernel(float* __restrict__ out)
{
    extern __shared__ __align__(16) uint16_t hsm[];
    __shared__ float zs;

    const int t  = threadIdx.x;
    const int b  = blockIdx.y;
    const int n0 = blockIdx.x * 128;
    const int lane = t & 31, wid = t >> 5;
    const int wc = wid >> 2, wn = wid & 3;
    const int g = lane >> 2, t2 = lane & 3;

    if (t == 0) {
        float z = 0.f;
#pragma unroll
        for (int j = 0; j < NT; j++) z += g_pZ[b * NT + j];
        zs = 1.f / z;
    }

    const uint16_t* Vg = g_Vh + (size_t)b * CC * NPIX;
    const uint16_t* Pg = g_P  + (size_t)b * NPIX * NPIX + n0;
    const uint32_t sbV = smem_to_u32(hsm);
    const uint32_t sbP = sbV + 2 * FH_VSZ * 2;

    auto load_chunk = [&](int m0, int buf) {
        {
            int c = t >> 1, h = t & 1;                    // V: 128 rows x 128B
            uint32_t dst = sbV + (uint32_t)(buf * FH_VSZ + c * FH_VST + h * 32) * 2;
            const uint16_t* src = Vg + (size_t)c * NPIX + m0 + h * 32;
            cp16(dst, src);      cp16(dst + 16, src + 8);
            cp16(dst + 32, src + 16); cp16(dst + 48, src + 24);
        }
        {
            int m = t >> 2, sg = t & 3;                   // P: 64 rows x 256B
            uint32_t dst = sbP + (uint32_t)(buf * FH_PSZ + m * FH_PST + sg * 32) * 2;
            const uint16_t* src = Pg + (size_t)(m0 + m) * NPIX + sg * 32;
            cp16(dst, src);      cp16(dst + 16, src + 8);
            cp16(dst + 32, src + 16); cp16(dst + 48, src + 24);
        }
    };

    load_chunk(0, 0);
    CP_COMMIT();

    // ldmatrix lane addressing
    const int arow = wc * 64 + ((lane >> 3) & 1) * 8 + (lane & 7);
    const int acol = (lane >> 4) * 8;
    const uint32_t aBase0 = sbV + (uint32_t)(arow * FH_VST + acol) * 2;
    const int l16 = lane & 15;
    const uint32_t bBase0 = sbP + (uint32_t)(l16 * FH_PST + wn * 32) * 2;

    float acc[4][4][4];
#pragma unroll
    for (int ct = 0; ct < 4; ct++)
#pragma unroll
        for (int nt = 0; nt < 4; nt++)
#pragma unroll
            for (int j = 0; j < 4; j++) acc[ct][nt][j] = 0.f;

    for (int ch = 0; ch < 36; ch++) {
        const int buf = ch & 1;
        CP_WAIT0();
        __syncthreads();
        if (ch + 1 < 36) { load_chunk((ch + 1) * 64, buf ^ 1); CP_COMMIT(); }

        const uint32_t aB = aBase0 + (uint32_t)(buf * FH_VSZ) * 2;
        const uint32_t bB = bBase0 + (uint32_t)(buf * FH_PSZ) * 2;

#pragma unroll
        for (int kk = 0; kk < 4; kk++) {
            uint32_t A[4][4];
#pragma unroll
            for (int ct = 0; ct < 4; ct++)
                ldsm_x4(A[ct], aB + (uint32_t)(ct * 16 * FH_VST) * 2 + kk * 32);
            uint32_t Bf[4][2];
#pragma unroll
            for (int nt = 0; nt < 4; nt++)
                ldsm_x2t(Bf[nt], bB + (uint32_t)(kk * 16 * FH_PST) * 2 + nt * 16);
#pragma unroll
            for (int ct = 0; ct < 4; ct++)
#pragma unroll
                for (int nt = 0; nt < 4; nt++)
                    mma_bf16(acc[ct][nt], A[ct], Bf[nt]);
        }
    }

    const float invZ = zs;
    float* Ob = out + (size_t)b * (2 * CC) * NPIX + (size_t)CC * NPIX + n0;
#pragma unroll
    for (int ct = 0; ct < 4; ct++) {
        int row = wc * 64 + ct * 16 + g;
#pragma unroll
        for (int nt = 0; nt < 4; nt++) {
            int col = wn * 32 + nt * 8 + 2 * t2;
            *(float2*)&Ob[(size_t)row * NPIX + col] =
                make_float2(acc[ct][nt][0] * invZ, acc[ct][nt][1] * invZ);
            *(float2*)&Ob[(size_t)(row + 8) * NPIX + col] =
                make_float2(acc[ct][nt][2] * invZ, acc[ct][nt][3] * invZ);
        }
    }
}

// ============================================================================
// launch
// ============================================================================
extern "C" void kernel_launch(void* const* d_in, const int* in_sizes, int n_in,
                              void* d_out, int out_size)
{
    const float* x_en   = (const float*)d_in[0];
    const float* x_de   = (const float*)d_in[1];
    const float* x_cat  = (const float*)d_in[2];
    const float* w_kq   = (const float*)d_in[3];
    const float* kq_g   = (const float*)d_in[4];
    const float* kq_b   = (const float*)d_in[5];
    const float* kq_m   = (const float*)d_in[6];
    const float* kq_v   = (const float*)d_in[7];
    const float* w_v    = (const float*)d_in[8];
    const float* v_g    = (const float*)d_in[9];
    const float* v_b    = (const float*)d_in[10];
    const float* v_m    = (const float*)d_in[11];
    const float* v_v    = (const float*)d_in[12];
    const float* w_red  = (const float*)d_in[13];
    const float* red_g  = (const float*)d_in[14];
    const float* red_b  = (const float*)d_in[15];
    const float* red_m  = (const float*)d_in[16];
    const float* red_v  = (const float*)d_in[17];
    float* out = (float*)d_out;

    uint16_t* pVh = nullptr;
    cudaGetSymbolAddress((void**)&pVh, g_Vh);

    cudaFuncSetAttribute(pgemm_kernel,
                         cudaFuncAttributeMaxDynamicSharedMemorySize, PG_SMEM_BYTES);
    cudaFuncSetAttribute(feat_kernel,
                         cudaFuncAttributeMaxDynamicSharedMemorySize, FH_SMEM_BYTES);

    const size_t twoCN = (size_t)2 * CC * NPIX;

    // K, Q  (both [k][pix])
    conv_kq_kernel<<<dim3(NT, BB, 2), 256>>>(x_en, x_de, w_kq,
                                             kq_g, kq_b, kq_m, kq_v);
    // M' per batch
    norm_kernel<<<BB, 256>>>();
    // x = relu(BN(w_red @ x_cat)) -> output channels [0, C), fp32
    conv128_kernel<<<dim3(NT, BB), 256>>>(x_cat, twoCN, 2 * CC, w_red,
                                          red_g, red_b, red_m, red_v,
                                          out, twoCN, nullptr);
    // V = relu(BN(w_v @ x)) -> bf16
    conv128_kernel<<<dim3(NT, BB), 256>>>(out, twoCN, CC, w_v,
                                          v_g, v_b, v_m, v_v,
                                          nullptr, 0, pVh);
    // P = exp(QK - M') bf16 + Z partials
    pgemm_kernel<<<dim3(NT, BB), 256, PG_SMEM_BYTES>>>();
    // feat = Vh @ P / Z  (bf16 tensor cores)
    feat_kernel<<<dim3(NT, BB), 256, FH_SMEM_BYTES>>>(out);
}

// round 8
// speedup vs baseline: 2.2132x; 1.0851x over previous
#include <cuda_runtime.h>
#include <cstdint>

// Problem constants
#define BB   16
#define CC   128
#define C4C  32
#define NPIX 2304                      // H*W = 48*48
#define NT   18                        // NPIX / 128
#define BN_EPS 1e-5f

static const size_t N2 = (size_t)NPIX * (size_t)NPIX;

// -------- scratch (device globals; no allocation allowed) --------
__device__ float    g_K [BB * C4C * NPIX];           // [b][k][n]
__device__ float    g_QT[BB * NPIX * C4C];           // [b][m][k]
__device__ uint16_t g_Vh[BB * CC  * NPIX];           // bf16 V [b][c][m]
__device__ uint16_t g_P [(size_t)BB * NPIX * NPIX];  // bf16 P[b][m][n], 170 MB
__device__ float    g_pZ[BB * NT];
__device__ float    g_M [BB];

// -------- packed f32x2 helpers --------
__device__ __forceinline__ unsigned long long pk2(float lo, float hi) {
    unsigned long long r;
    asm("mov.b64 %0, {%1,%2};" : "=l"(r) : "f"(lo), "f"(hi));
    return r;
}
__device__ __forceinline__ float2 up2(unsigned long long v) {
    float2 r;
    asm("mov.b64 {%0,%1}, %2;" : "=f"(r.x), "=f"(r.y) : "l"(v));
    return r;
}
__device__ __forceinline__ void fma2(unsigned long long& d,
                                     unsigned long long a,
                                     unsigned long long b) {
    asm("fma.rn.f32x2 %0, %1, %2, %0;" : "+l"(d) : "l"(a), "l"(b));
}
__device__ __forceinline__ uint32_t smem_to_u32(const void* p) {
    uint32_t a;
    asm("{ .reg .u64 t; cvta.to.shared.u64 t, %1; cvt.u32.u64 %0, t; }"
        : "=r"(a) : "l"(p));
    return a;
}
__device__ __forceinline__ void cp16(uint32_t dst, const void* src) {
    asm volatile("cp.async.cg.shared.global [%0], [%1], 16;"
                 :: "r"(dst), "l"(src) : "memory");
}
#define CP_COMMIT() asm volatile("cp.async.commit_group;" ::: "memory")
#define CP_WAIT0()  asm volatile("cp.async.wait_group 0;" ::: "memory")

// pack two f32 -> bf16x2 (lo = p0, hi = p1)
__device__ __forceinline__ uint32_t bfpack(float p0, float p1) {
    uint32_t u;
    asm("cvt.rn.bf16x2.f32 %0, %1, %2;" : "=r"(u) : "f"(p1), "f"(p0));
    return u;
}
__device__ __forceinline__ void stcs32(uint16_t* p, uint32_t v) {
    asm volatile("st.global.cs.b32 [%0], %1;" :: "l"(p), "r"(v) : "memory");
}

// -------- mma.sync + ldmatrix (family-portable, sm_80+) --------
__device__ __forceinline__ void ldsm_x4(uint32_t* r, uint32_t a) {
    asm volatile("ldmatrix.sync.aligned.m8n8.x4.shared.b16 {%0,%1,%2,%3}, [%4];"
        : "=r"(r[0]), "=r"(r[1]), "=r"(r[2]), "=r"(r[3]) : "r"(a));
}
__device__ __forceinline__ void ldsm_x2t(uint32_t* r, uint32_t a) {
    asm volatile("ldmatrix.sync.aligned.m8n8.x2.trans.shared.b16 {%0,%1}, [%2];"
        : "=r"(r[0]), "=r"(r[1]) : "r"(a));
}
__device__ __forceinline__ void mma_bf16(float* d, const uint32_t* a,
                                         const uint32_t* b) {
    asm volatile(
        "mma.sync.aligned.m16n8k16.row.col.f32.bf16.bf16.f32 "
        "{%0,%1,%2,%3},{%4,%5,%6,%7},{%8,%9},{%0,%1,%2,%3};"
        : "+f"(d[0]), "+f"(d[1]), "+f"(d[2]), "+f"(d[3])
        : "r"(a[0]), "r"(a[1]), "r"(a[2]), "r"(a[3]), "r"(b[0]), "r"(b[1]));
}
__device__ __forceinline__ void mma_tf32(float* d, const uint32_t* a,
                                         const uint32_t* b) {
    asm volatile(
        "mma.sync.aligned.m16n8k8.row.col.f32.tf32.tf32.f32 "
        "{%0,%1,%2,%3},{%4,%5,%6,%7},{%8,%9},{%0,%1,%2,%3};"
        : "+f"(d[0]), "+f"(d[1]), "+f"(d[2]), "+f"(d[3])
        : "r"(a[0]), "r"(a[1]), "r"(a[2]), "r"(a[3]), "r"(b[0]), "r"(b[1]));
}

// ============================================================================
// conv128: Y = relu( scale * (W @ X) + bias ),  O = 128.
// fp32 out (Yf) OR bf16 out (Yh). cp.async double-buffered, conflict-free.
// ============================================================================
__global__ void __launch_bounds__(256, 2) conv128_kernel(
    const float* __restrict__ X, size_t xStride, int CIN,
    const float* __restrict__ W,
    const float* __restrict__ gam, const float* __restrict__ bet,
    const float* __restrict__ mean, const float* __restrict__ var,
    float* __restrict__ Yf, size_t yStride, uint16_t* __restrict__ Yh)
{
    __shared__ __align__(16) float Ws[2][128 * 20];
    __shared__ __align__(16) float Xs[2][16 * 132];
    __shared__ float scale_s[128], bias_s[128];

    const int t  = threadIdx.x;
    const int b  = blockIdx.y;
    const int n0 = blockIdx.x * 128;
    const int ty = t >> 4, tx = t & 15;

    if (t < 128) {
        float s = gam[t] * rsqrtf(var[t] + BN_EPS);
        scale_s[t] = s;
        bias_s[t]  = bet[t] - mean[t] * s;
    }

    const float* Xb = X + (size_t)b * xStride + n0;
    const uint32_t sW = smem_to_u32(Ws), sX = smem_to_u32(Xs);
    const int NCHK = CIN >> 4;

    auto load_chunk = [&](int c0, int buf) {
        {
            int o = t >> 1, h = t & 1;
            uint32_t dst = sW + (uint32_t)(buf * 128 * 20 + o * 20 + h * 8) * 4;
            const float* src = W + (size_t)o * CIN + c0 + h * 8;
            cp16(dst, src); cp16(dst + 16, src + 4);
        }
        {
            int k = t >> 4, seg = t & 15;
            uint32_t dst = sX + (uint32_t)(buf * 16 * 132 + k * 132 + seg * 8) * 4;
            const float* src = Xb + (size_t)(c0 + k) * NPIX + seg * 8;
            cp16(dst, src); cp16(dst + 16, src + 4);
        }
    };

    load_chunk(0, 0);
    CP_COMMIT();

    unsigned long long acc[8][4];
#pragma unroll
    for (int i = 0; i < 8; i++)
#pragma unroll
        for (int j = 0; j < 4; j++) acc[i][j] = 0ull;

    for (int ch = 0; ch < NCHK; ch++) {
        const int buf = ch & 1;
        CP_WAIT0();
        __syncthreads();
        if (ch + 1 < NCHK) { load_chunk((ch + 1) << 4, buf ^ 1); CP_COMMIT(); }

        const float* Wb2 = Ws[buf];
        const float* Xb2 = Xs[buf];
#pragma unroll
        for (int k4 = 0; k4 < 4; k4++) {
            unsigned long long bx[4][4];
#pragma unroll
            for (int kk = 0; kk < 4; kk++)
#pragma unroll
                for (int j = 0; j < 4; j++)
                    bx[kk][j] = *(const unsigned long long*)
                        &Xb2[(k4 * 4 + kk) * 132 + 2 * tx + 32 * j];
#pragma unroll
            for (int i = 0; i < 8; i++) {
                float4 w4 = *(const float4*)&Wb2[(ty * 8 + i) * 20 + k4 * 4];
                unsigned long long d0 = pk2(w4.x, w4.x);
                unsigned long long d1 = pk2(w4.y, w4.y);
                unsigned long long d2 = pk2(w4.z, w4.z);
                unsigned long long d3 = pk2(w4.w, w4.w);
#pragma unroll
                for (int j = 0; j < 4; j++) {
                    fma2(acc[i][j], d0, bx[0][j]);
                    fma2(acc[i][j], d1, bx[1][j]);
                    fma2(acc[i][j], d2, bx[2][j]);
                    fma2(acc[i][j], d3, bx[3][j]);
                }
            }
        }
        __syncthreads();
    }

    if (Yh == nullptr) {
        float* Yb = Yf + (size_t)b * yStride + n0 + 2 * tx;
#pragma unroll
        for (int i = 0; i < 8; i++) {
            int o = ty * 8 + i;
            float s = scale_s[o], bi = bias_s[o];
#pragma unroll
            for (int j = 0; j < 4; j++) {
                float2 p = up2(acc[i][j]);
                *(float2*)&Yb[(size_t)o * NPIX + 32 * j] =
                    make_float2(fmaxf(p.x * s + bi, 0.f), fmaxf(p.y * s + bi, 0.f));
            }
        }
    } else {
        uint16_t* Yb = Yh + (size_t)b * CC * NPIX + n0 + 2 * tx;
#pragma unroll
        for (int i = 0; i < 8; i++) {
            int o = ty * 8 + i;
            float s = scale_s[o], bi = bias_s[o];
#pragma unroll
            for (int j = 0; j < 4; j++) {
                float2 p = up2(acc[i][j]);
                *(uint32_t*)&Yb[(size_t)o * NPIX + 32 * j] =
                    bfpack(fmaxf(p.x * s + bi, 0.f), fmaxf(p.y * s + bi, 0.f));
            }
        }
    }
}

// ============================================================================
// conv_kq: z=0 -> K[b][k][n] ; z=1 -> QT[b][m][k]
// ============================================================================
__global__ void __launch_bounds__(256, 2) conv_kq_kernel(
    const float* __restrict__ Xen, const float* __restrict__ Xde,
    const float* __restrict__ W,
    const float* __restrict__ gam, const float* __restrict__ bet,
    const float* __restrict__ mean, const float* __restrict__ var)
{
    __shared__ __align__(16) float Ws[2][32 * 20];
    __shared__ __align__(16) float Xs[2][16 * 132];
    __shared__ float scale_s[32], bias_s[32];

    const int t  = threadIdx.x;
    const int b  = blockIdx.y;
    const int n0 = blockIdx.x * 128;
    const int ty = t >> 4, tx = t & 15;
    const float* X = (blockIdx.z == 0) ? Xen : Xde;

    if (t < 32) {
        float s = gam[t] * rsqrtf(var[t] + BN_EPS);
        scale_s[t] = s;
        bias_s[t]  = bet[t] - mean[t] * s;
    }

    const float* Xb = X + (size_t)b * CC * NPIX + n0;
    const uint32_t sW = smem_to_u32(Ws), sX = smem_to_u32(Xs);

    auto load_chunk = [&](int c0, int buf) {
        if (t < 128) {
            int o = t >> 2, q = t & 3;
            cp16(sW + (uint32_t)(buf * 32 * 20 + o * 20 + q * 4) * 4,
                 W + (size_t)o * CC + c0 + q * 4);
        }
        {
            int k = t >> 4, seg = t & 15;
            uint32_t dst = sX + (uint32_t)(buf * 16 * 132 + k * 132 + seg * 8) * 4;
            const float* src = Xb + (size_t)(c0 + k) * NPIX + seg * 8;
            cp16(dst, src); cp16(dst + 16, src + 4);
        }
    };

    load_chunk(0, 0);
    CP_COMMIT();

    unsigned long long acc[2][4];
#pragma unroll
    for (int i = 0; i < 2; i++)
#pragma unroll
        for (int j = 0; j < 4; j++) acc[i][j] = 0ull;

    for (int ch = 0; ch < 8; ch++) {
        const int buf = ch & 1;
        CP_WAIT0();
        __syncthreads();
        if (ch + 1 < 8) { load_chunk((ch + 1) << 4, buf ^ 1); CP_COMMIT(); }

        const float* Wb2 = Ws[buf];
        const float* Xb2 = Xs[buf];
#pragma unroll
        for (int k4 = 0; k4 < 4; k4++) {
            unsigned long long bx[4][4];
#pragma unroll
            for (int kk = 0; kk < 4; kk++)
#pragma unroll
                for (int j = 0; j < 4; j++)
                    bx[kk][j] = *(const unsigned long long*)
                        &Xb2[(k4 * 4 + kk) * 132 + 2 * tx + 32 * j];
#pragma unroll
            for (int i = 0; i < 2; i++) {
                float4 w4 = *(const float4*)&Wb2[(ty * 2 + i) * 20 + k4 * 4];
                unsigned long long d0 = pk2(w4.x, w4.x);
                unsigned long long d1 = pk2(w4.y, w4.y);
                unsigned long long d2 = pk2(w4.z, w4.z);
                unsigned long long d3 = pk2(w4.w, w4.w);
#pragma unroll
                for (int j = 0; j < 4; j++) {
                    fma2(acc[i][j], d0, bx[0][j]);
                    fma2(acc[i][j], d1, bx[1][j]);
                    fma2(acc[i][j], d2, bx[2][j]);
                    fma2(acc[i][j], d3, bx[3][j]);
                }
            }
        }
        __syncthreads();
    }

    if (blockIdx.z == 0) {
        float* Yb = g_K + (size_t)b * C4C * NPIX + n0 + 2 * tx;
#pragma unroll
        for (int i = 0; i < 2; i++) {
            int o = ty * 2 + i;
            float s = scale_s[o], bi = bias_s[o];
#pragma unroll
            for (int j = 0; j < 4; j++) {
                float2 p = up2(acc[i][j]);
                *(float2*)&Yb[(size_t)o * NPIX + 32 * j] =
                    make_float2(fmaxf(p.x * s + bi, 0.f), fmaxf(p.y * s + bi, 0.f));
            }
        }
    } else {
        float* Yb = g_QT + (size_t)b * NPIX * C4C;
#pragma unroll
        for (int i = 0; i < 2; i++) {
            int o = ty * 2 + i;
            float s = scale_s[o], bi = bias_s[o];
#pragma unroll
            for (int j = 0; j < 4; j++) {
                float2 p = up2(acc[i][j]);
                int n = n0 + 2 * tx + 32 * j;
                Yb[(size_t)n * C4C + o]       = fmaxf(p.x * s + bi, 0.f);
                Yb[(size_t)(n + 1) * C4C + o] = fmaxf(p.y * s + bi, 0.f);
            }
        }
    }
}

// ============================================================================
// norm: M'[b] = max_n ||K[b,:,n]|| * max_m ||QT[b,m,:]||  (Cauchy-Schwarz)
// ============================================================================
__global__ void __launch_bounds__(256) norm_kernel()
{
    __shared__ float r1[256], r2[256];
    const int b = blockIdx.x, t = threadIdx.x;
    const float* Kb  = g_K  + (size_t)b * C4C * NPIX;
    const float* QTb = g_QT + (size_t)b * NPIX * C4C;

    float mk = 0.f, mq = 0.f;
    for (int n = t; n < NPIX; n += 256) {
        float sk = 0.f;
#pragma unroll
        for (int k = 0; k < C4C; k++) {
            float vk = Kb[(size_t)k * NPIX + n];
            sk += vk * vk;
        }
        mk = fmaxf(mk, sk);
        float sq = 0.f;
        const float4* qr = (const float4*)(QTb + (size_t)n * C4C);
#pragma unroll
        for (int j = 0; j < 8; j++) {
            float4 q = qr[j];
            sq += q.x * q.x + q.y * q.y + q.z * q.z + q.w * q.w;
        }
        mq = fmaxf(mq, sq);
    }
    r1[t] = mk; r2[t] = mq;
    __syncthreads();
    for (int s = 128; s > 0; s >>= 1) {
        if (t < s) { r1[t] = fmaxf(r1[t], r1[t + s]); r2[t] = fmaxf(r2[t], r2[t + s]); }
        __syncthreads();
    }
    if (t == 0) g_M[b] = sqrtf(r1[0]) * sqrtf(r2[0]);
}

// ============================================================================
// pgemm (tf32 mma): P[b,m,n] = exp( sum_k QT[b,m,k]*K[b,k,n] - M'[b] ), bf16.
// K tile (32k x 128n) resident; QT m-tiles (128m x 32k) double-buffered.
// Warp grid 4m x 2n; warp tile 32m x 64n = 2x8 m16n8k8 tiles.
// Conflict-free direct LDS fragment feeds. grid (NT, B), 256 thr.
// ============================================================================
#define PGM_Q_OFF (32 * 136)            // 4352 floats
#define PGM_QSZ   (128 * 36)            // 4608 floats per buffer
#define PGM_SMEM_BYTES ((32 * 136 + 2 * 128 * 36) * 4)   // 54272

__global__ void __launch_bounds__(256, 2) pgemm_kernel()
{
    extern __shared__ __align__(16) float ps[];
    __shared__ float zred[256];

    const int t  = threadIdx.x;
    const int b  = blockIdx.y;
    const int n0 = blockIdx.x * 128;
    const int lane = t & 31, wid = t >> 5;
    const int g = lane >> 2, t2 = lane & 3;
    const int wm = wid >> 1, wn = wid & 1;
    const float Mb = g_M[b];

    const float* Kg  = g_K  + (size_t)b * C4C * NPIX + n0;
    const float* QTg = g_QT + (size_t)b * NPIX * C4C;
    const uint32_t sb = smem_to_u32(ps);

    // K tile: 32 rows x 128 floats (pad 8), 4 cp16/thread
    {
        int k = t >> 3, seg = t & 7;
        uint32_t dst = sb + (uint32_t)(k * 136 + seg * 16) * 4;
        const float* src = Kg + (size_t)k * NPIX + seg * 16;
        cp16(dst, src); cp16(dst + 16, src + 4);
        cp16(dst + 32, src + 8); cp16(dst + 48, src + 12);
    }
    // QT m-tile loader: 128 rows x 32 floats (pad 4)
    auto load_q = [&](int mt, int buf) {
        int m = t >> 1, h = t & 1;
        uint32_t dst = sb + (uint32_t)(PGM_Q_OFF + buf * PGM_QSZ + m * 36 + h * 16) * 4;
        const float* src = QTg + (size_t)(mt * 128 + m) * C4C + h * 16;
        cp16(dst, src); cp16(dst + 16, src + 4);
        cp16(dst + 32, src + 8); cp16(dst + 48, src + 12);
    };
    load_q(0, 0);
    CP_COMMIT();

    const float* Ks = ps;
    float zacc = 0.f;

    for (int mt = 0; mt < NT; mt++) {
        const int buf = mt & 1;
        CP_WAIT0();
        __syncthreads();
        if (mt + 1 < NT) { load_q(mt + 1, buf ^ 1); CP_COMMIT(); }

        const float* Qs = ps + PGM_Q_OFF + buf * PGM_QSZ;

        float d[2][8][4];
#pragma unroll
        for (int i = 0; i < 2; i++)
#pragma unroll
            for (int j = 0; j < 8; j++)
#pragma unroll
                for (int q = 0; q < 4; q++) d[i][j][q] = 0.f;

#pragma unroll
        for (int ks = 0; ks < 4; ks++) {
            const int k0 = ks * 8;
            uint32_t A[2][4];
#pragma unroll
            for (int m2 = 0; m2 < 2; m2++) {
                int m = wm * 32 + m2 * 16 + g;
                A[m2][0] = __float_as_uint(Qs[m * 36 + k0 + t2]);
                A[m2][1] = __float_as_uint(Qs[(m + 8) * 36 + k0 + t2]);
                A[m2][2] = __float_as_uint(Qs[m * 36 + k0 + 4 + t2]);
                A[m2][3] = __float_as_uint(Qs[(m + 8) * 36 + k0 + 4 + t2]);
            }
            uint32_t Bf[8][2];
#pragma unroll
            for (int nt = 0; nt < 8; nt++) {
                int n = wn * 64 + nt * 8 + g;
                Bf[nt][0] = __float_as_uint(Ks[(k0 + t2) * 136 + n]);
                Bf[nt][1] = __float_as_uint(Ks[(k0 + 4 + t2) * 136 + n]);
            }
#pragma unroll
            for (int m2 = 0; m2 < 2; m2++)
#pragma unroll
                for (int nt = 0; nt < 8; nt++)
                    mma_tf32(d[m2][nt], A[m2], Bf[nt]);
        }

        // epilogue: exp, Z, bf16 streaming store
#pragma unroll
        for (int m2 = 0; m2 < 2; m2++) {
            int mrow = mt * 128 + wm * 32 + m2 * 16 + g;
            uint16_t* Pr0 = g_P + ((size_t)b * NPIX + mrow) * NPIX + n0;
            uint16_t* Pr1 = Pr0 + (size_t)8 * NPIX;
#pragma unroll
            for (int nt = 0; nt < 8; nt++) {
                int ncol = wn * 64 + nt * 8 + 2 * t2;
                float e0 = __expf(d[m2][nt][0] - Mb);
                float e1 = __expf(d[m2][nt][1] - Mb);
                float e2 = __expf(d[m2][nt][2] - Mb);
                float e3 = __expf(d[m2][nt][3] - Mb);
                zacc += (e0 + e1) + (e2 + e3);
                stcs32(Pr0 + ncol, bfpack(e0, e1));
                stcs32(Pr1 + ncol, bfpack(e2, e3));
            }
        }
    }

    zred[t] = zacc;
    __syncthreads();
    for (int s = 128; s > 0; s >>= 1) {
        if (t < s) zred[t] += zred[t + s];
        __syncthreads();
    }
    if (t == 0) g_pZ[b * NT + blockIdx.x] = zred[0];
}

// ============================================================================
// feat: out[b,C+c,n] = (1/Z) * sum_m Vh[b,c,m] * P[b,m,n]  -- bf16 mma.sync.
// (unchanged from R7 passing kernel)
// ============================================================================
#define FH_VST 72
#define FH_PST 136
#define FH_VSZ (128 * FH_VST)
#define FH_PSZ (64 * FH_PST)
#define FH_SMEM_BYTES ((2 * FH_VSZ + 2 * FH_PSZ) * 2)

__global__ void __launch_bounds__(256, 2) feat_kernel(float* __restrict__ out)
{
    extern __shared__ __align__(16) uint16_t hsm[];
    __shared__ float zs;

    const int t  = threadIdx.x;
    const int b  = blockIdx.y;
    const int n0 = blockIdx.x * 128;
    const int lane = t & 31, wid = t >> 5;
    const int wc = wid >> 2, wn = wid & 3;
    const int g = lane >> 2, t2 = lane & 3;

    if (t == 0) {
        float z = 0.f;
#pragma unroll
        for (int j = 0; j < NT; j++) z += g_pZ[b * NT + j];
        zs = 1.f / z;
    }

    const uint16_t* Vg = g_Vh + (size_t)b * CC * NPIX;
    const uint16_t* Pg = g_P  + (size_t)b * NPIX * NPIX + n0;
    const uint32_t sbV = smem_to_u32(hsm);
    const uint32_t sbP = sbV + 2 * FH_VSZ * 2;

    auto load_chunk = [&](int m0, int buf) {
        {
            int c = t >> 1, h = t & 1;
            uint32_t dst = sbV + (uint32_t)(buf * FH_VSZ + c * FH_VST + h * 32) * 2;
            const uint16_t* src = Vg + (size_t)c * NPIX + m0 + h * 32;
            cp16(dst, src);      cp16(dst + 16, src + 8);
            cp16(dst + 32, src + 16); cp16(dst + 48, src + 24);
        }
        {
            int m = t >> 2, sg = t & 3;
            uint32_t dst = sbP + (uint32_t)(buf * FH_PSZ + m * FH_PST + sg * 32) * 2;
            const uint16_t* src = Pg + (size_t)(m0 + m) * NPIX + sg * 32;
            cp16(dst, src);      cp16(dst + 16, src + 8);
            cp16(dst + 32, src + 16); cp16(dst + 48, src + 24);
        }
    };

    load_chunk(0, 0);
    CP_COMMIT();

    const int arow = wc * 64 + ((lane >> 3) & 1) * 8 + (lane & 7);
    const int acol = (lane >> 4) * 8;
    const uint32_t aBase0 = sbV + (uint32_t)(arow * FH_VST + acol) * 2;
    const int l16 = lane & 15;
    const uint32_t bBase0 = sbP + (uint32_t)(l16 * FH_PST + wn * 32) * 2;

    float acc[4][4][4];
#pragma unroll
    for (int ct = 0; ct < 4; ct++)
#pragma unroll
        for (int nt = 0; nt < 4; nt++)
#pragma unroll
            for (int j = 0; j < 4; j++) acc[ct][nt][j] = 0.f;

    for (int ch = 0; ch < 36; ch++) {
        const int buf = ch & 1;
        CP_WAIT0();
        __syncthreads();
        if (ch + 1 < 36) { load_chunk((ch + 1) * 64, buf ^ 1); CP_COMMIT(); }

        const uint32_t aB = aBase0 + (uint32_t)(buf * FH_VSZ) * 2;
        const uint32_t bB = bBase0 + (uint32_t)(buf * FH_PSZ) * 2;

#pragma unroll
        for (int kk = 0; kk < 4; kk++) {
            uint32_t A[4][4];
#pragma unroll
            for (int ct = 0; ct < 4; ct++)
                ldsm_x4(A[ct], aB + (uint32_t)(ct * 16 * FH_VST) * 2 + kk * 32);
            uint32_t Bf[4][2];
#pragma unroll
            for (int nt = 0; nt < 4; nt++)
                ldsm_x2t(Bf[nt], bB + (uint32_t)(kk * 16 * FH_PST) * 2 + nt * 16);
#pragma unroll
            for (int ct = 0; ct < 4; ct++)
#pragma unroll
                for (int nt = 0; nt < 4; nt++)
                    mma_bf16(acc[ct][nt], A[ct], Bf[nt]);
        }
    }

    const float invZ = zs;
    float* Ob = out + (size_t)b * (2 * CC) * NPIX + (size_t)CC * NPIX + n0;
#pragma unroll
    for (int ct = 0; ct < 4; ct++) {
        int row = wc * 64 + ct * 16 + g;
#pragma unroll
        for (int nt = 0; nt < 4; nt++) {
            int col = wn * 32 + nt * 8 + 2 * t2;
            *(float2*)&Ob[(size_t)row * NPIX + col] =
                make_float2(acc[ct][nt][0] * invZ, acc[ct][nt][1] * invZ);
            *(float2*)&Ob[(size_t)(row + 8) * NPIX + col] =
                make_float2(acc[ct][nt][2] * invZ, acc[ct][nt][3] * invZ);
        }
    }
}

// ============================================================================
// launch
// ============================================================================
extern "C" void kernel_launch(void* const* d_in, const int* in_sizes, int n_in,
                              void* d_out, int out_size)
{
    const float* x_en   = (const float*)d_in[0];
    const float* x_de   = (const float*)d_in[1];
    const float* x_cat  = (const float*)d_in[2];
    const float* w_kq   = (const float*)d_in[3];
    const float* kq_g   = (const float*)d_in[4];
    const float* kq_b   = (const float*)d_in[5];
    const float* kq_m   = (const float*)d_in[6];
    const float* kq_v   = (const float*)d_in[7];
    const float* w_v    = (const float*)d_in[8];
    const float* v_g    = (const float*)d_in[9];
    const float* v_b    = (const float*)d_in[10];
    const float* v_m    = (const float*)d_in[11];
    const float* v_v    = (const float*)d_in[12];
    const float* w_red  = (const float*)d_in[13];
    const float* red_g  = (const float*)d_in[14];
    const float* red_b  = (const float*)d_in[15];
    const float* red_m  = (const float*)d_in[16];
    const float* red_v  = (const float*)d_in[17];
    float* out = (float*)d_out;

    uint16_t* pVh = nullptr;
    cudaGetSymbolAddress((void**)&pVh, g_Vh);

    cudaFuncSetAttribute(pgemm_kernel,
                         cudaFuncAttributeMaxDynamicSharedMemorySize, PGM_SMEM_BYTES);
    cudaFuncSetAttribute(feat_kernel,
                         cudaFuncAttributeMaxDynamicSharedMemorySize, FH_SMEM_BYTES);

    const size_t twoCN = (size_t)2 * CC * NPIX;

    // K [k][n], QT [m][k]
    conv_kq_kernel<<<dim3(NT, BB, 2), 256>>>(x_en, x_de, w_kq,
                                             kq_g, kq_b, kq_m, kq_v);
    // M' per batch
    norm_kernel<<<BB, 256>>>();
    // x -> output channels [0, C), fp32
    conv128_kernel<<<dim3(NT, BB), 256>>>(x_cat, twoCN, 2 * CC, w_red,
                                          red_g, red_b, red_m, red_v,
                                          out, twoCN, nullptr);
    // V -> bf16
    conv128_kernel<<<dim3(NT, BB), 256>>>(out, twoCN, CC, w_v,
                                          v_g, v_b, v_m, v_v,
                                          nullptr, 0, pVh);
    // P = exp(QK - M') bf16 via tf32 mma + Z partials
    pgemm_kernel<<<dim3(NT, BB), 256, PGM_SMEM_BYTES>>>();
    // feat = Vh @ P / Z  (bf16 tensor cores)
    feat_kernel<<<dim3(NT, BB), 256, FH_SMEM_BYTES>>>(out);
}

// round 9
// speedup vs baseline: 2.5267x; 1.1417x over previous
#include <cuda_runtime.h>
#include <cstdint>

// Problem constants
#define BB   16
#define CC   128
#define C4C  32
#define NPIX 2304                      // H*W = 48*48
#define NT   18                        // NPIX / 128
#define BN_EPS 1e-5f

// -------- scratch (device globals; no allocation allowed) --------
__device__ float    g_K [BB * C4C * NPIX];           // [b][k][n]
__device__ float    g_QT[BB * NPIX * C4C];           // [b][m][k]
__device__ uint16_t g_Vh[BB * CC  * NPIX];           // bf16 V [b][c][m]
__device__ float    g_pZ[BB * NT];
__device__ float    g_M [BB];

// -------- packed f32x2 helpers --------
__device__ __forceinline__ unsigned long long pk2(float lo, float hi) {
    unsigned long long r;
    asm("mov.b64 %0, {%1,%2};" : "=l"(r) : "f"(lo), "f"(hi));
    return r;
}
__device__ __forceinline__ float2 up2(unsigned long long v) {
    float2 r;
    asm("mov.b64 {%0,%1}, %2;" : "=f"(r.x), "=f"(r.y) : "l"(v));
    return r;
}
__device__ __forceinline__ void fma2(unsigned long long& d,
                                     unsigned long long a,
                                     unsigned long long b) {
    asm("fma.rn.f32x2 %0, %1, %2, %0;" : "+l"(d) : "l"(a), "l"(b));
}
__device__ __forceinline__ uint32_t smem_to_u32(const void* p) {
    uint32_t a;
    asm("{ .reg .u64 t; cvta.to.shared.u64 t, %1; cvt.u32.u64 %0, t; }"
        : "=r"(a) : "l"(p));
    return a;
}
__device__ __forceinline__ void cp16(uint32_t dst, const void* src) {
    asm volatile("cp.async.cg.shared.global [%0], [%1], 16;"
                 :: "r"(dst), "l"(src) : "memory");
}
#define CP_COMMIT() asm volatile("cp.async.commit_group;" ::: "memory")
#define CP_WAIT0()  asm volatile("cp.async.wait_group 0;" ::: "memory")

// pack two f32 -> bf16x2 (lo = p0, hi = p1)
__device__ __forceinline__ uint32_t bfpack(float p0, float p1) {
    uint32_t u;
    asm("cvt.rn.bf16x2.f32 %0, %1, %2;" : "=r"(u) : "f"(p1), "f"(p0));
    return u;
}

// -------- mma.sync + ldmatrix (family-portable, sm_80+) --------
__device__ __forceinline__ void ldsm_x4(uint32_t* r, uint32_t a) {
    asm volatile("ldmatrix.sync.aligned.m8n8.x4.shared.b16 {%0,%1,%2,%3}, [%4];"
        : "=r"(r[0]), "=r"(r[1]), "=r"(r[2]), "=r"(r[3]) : "r"(a));
}
__device__ __forceinline__ void ldsm_x2t(uint32_t* r, uint32_t a) {
    asm volatile("ldmatrix.sync.aligned.m8n8.x2.trans.shared.b16 {%0,%1}, [%2];"
        : "=r"(r[0]), "=r"(r[1]) : "r"(a));
}
__device__ __forceinline__ void mma_bf16(float* d, const uint32_t* a,
                                         const uint32_t* b) {
    asm volatile(
        "mma.sync.aligned.m16n8k16.row.col.f32.bf16.bf16.f32 "
        "{%0,%1,%2,%3},{%4,%5,%6,%7},{%8,%9},{%0,%1,%2,%3};"
        : "+f"(d[0]), "+f"(d[1]), "+f"(d[2]), "+f"(d[3])
        : "r"(a[0]), "r"(a[1]), "r"(a[2]), "r"(a[3]), "r"(b[0]), "r"(b[1]));
}
__device__ __forceinline__ void mma_tf32(float* d, const uint32_t* a,
                                         const uint32_t* b) {
    asm volatile(
        "mma.sync.aligned.m16n8k8.row.col.f32.tf32.tf32.f32 "
        "{%0,%1,%2,%3},{%4,%5,%6,%7},{%8,%9},{%0,%1,%2,%3};"
        : "+f"(d[0]), "+f"(d[1]), "+f"(d[2]), "+f"(d[3])
        : "r"(a[0]), "r"(a[1]), "r"(a[2]), "r"(a[3]), "r"(b[0]), "r"(b[1]));
}

// ============================================================================
// conv128: Y = relu( scale * (W @ X) + bias ),  O = 128. (R8 verbatim)
// ============================================================================
__global__ void __launch_bounds__(256, 2) conv128_kernel(
    const float* __restrict__ X, size_t xStride, int CIN,
    const float* __restrict__ W,
    const float* __restrict__ gam, const float* __restrict__ bet,
    const float* __restrict__ mean, const float* __restrict__ var,
    float* __restrict__ Yf, size_t yStride, uint16_t* __restrict__ Yh)
{
    __shared__ __align__(16) float Ws[2][128 * 20];
    __shared__ __align__(16) float Xs[2][16 * 132];
    __shared__ float scale_s[128], bias_s[128];

    const int t  = threadIdx.x;
    const int b  = blockIdx.y;
    const int n0 = blockIdx.x * 128;
    const int ty = t >> 4, tx = t & 15;

    if (t < 128) {
        float s = gam[t] * rsqrtf(var[t] + BN_EPS);
        scale_s[t] = s;
        bias_s[t]  = bet[t] - mean[t] * s;
    }

    const float* Xb = X + (size_t)b * xStride + n0;
    const uint32_t sW = smem_to_u32(Ws), sX = smem_to_u32(Xs);
    const int NCHK = CIN >> 4;

    auto load_chunk = [&](int c0, int buf) {
        {
            int o = t >> 1, h = t & 1;
            uint32_t dst = sW + (uint32_t)(buf * 128 * 20 + o * 20 + h * 8) * 4;
            const float* src = W + (size_t)o * CIN + c0 + h * 8;
            cp16(dst, src); cp16(dst + 16, src + 4);
        }
        {
            int k = t >> 4, seg = t & 15;
            uint32_t dst = sX + (uint32_t)(buf * 16 * 132 + k * 132 + seg * 8) * 4;
            const float* src = Xb + (size_t)(c0 + k) * NPIX + seg * 8;
            cp16(dst, src); cp16(dst + 16, src + 4);
        }
    };

    load_chunk(0, 0);
    CP_COMMIT();

    unsigned long long acc[8][4];
#pragma unroll
    for (int i = 0; i < 8; i++)
#pragma unroll
        for (int j = 0; j < 4; j++) acc[i][j] = 0ull;

    for (int ch = 0; ch < NCHK; ch++) {
        const int buf = ch & 1;
        CP_WAIT0();
        __syncthreads();
        if (ch + 1 < NCHK) { load_chunk((ch + 1) << 4, buf ^ 1); CP_COMMIT(); }

        const float* Wb2 = Ws[buf];
        const float* Xb2 = Xs[buf];
#pragma unroll
        for (int k4 = 0; k4 < 4; k4++) {
            unsigned long long bx[4][4];
#pragma unroll
            for (int kk = 0; kk < 4; kk++)
#pragma unroll
                for (int j = 0; j < 4; j++)
                    bx[kk][j] = *(const unsigned long long*)
                        &Xb2[(k4 * 4 + kk) * 132 + 2 * tx + 32 * j];
#pragma unroll
            for (int i = 0; i < 8; i++) {
                float4 w4 = *(const float4*)&Wb2[(ty * 8 + i) * 20 + k4 * 4];
                unsigned long long d0 = pk2(w4.x, w4.x);
                unsigned long long d1 = pk2(w4.y, w4.y);
                unsigned long long d2 = pk2(w4.z, w4.z);
                unsigned long long d3 = pk2(w4.w, w4.w);
#pragma unroll
                for (int j = 0; j < 4; j++) {
                    fma2(acc[i][j], d0, bx[0][j]);
                    fma2(acc[i][j], d1, bx[1][j]);
                    fma2(acc[i][j], d2, bx[2][j]);
                    fma2(acc[i][j], d3, bx[3][j]);
                }
            }
        }
        __syncthreads();
    }

    if (Yh == nullptr) {
        float* Yb = Yf + (size_t)b * yStride + n0 + 2 * tx;
#pragma unroll
        for (int i = 0; i < 8; i++) {
            int o = ty * 8 + i;
            float s = scale_s[o], bi = bias_s[o];
#pragma unroll
            for (int j = 0; j < 4; j++) {
                float2 p = up2(acc[i][j]);
                *(float2*)&Yb[(size_t)o * NPIX + 32 * j] =
                    make_float2(fmaxf(p.x * s + bi, 0.f), fmaxf(p.y * s + bi, 0.f));
            }
        }
    } else {
        uint16_t* Yb = Yh + (size_t)b * CC * NPIX + n0 + 2 * tx;
#pragma unroll
        for (int i = 0; i < 8; i++) {
            int o = ty * 8 + i;
            float s = scale_s[o], bi = bias_s[o];
#pragma unroll
            for (int j = 0; j < 4; j++) {
                float2 p = up2(acc[i][j]);
                *(uint32_t*)&Yb[(size_t)o * NPIX + 32 * j] =
                    bfpack(fmaxf(p.x * s + bi, 0.f), fmaxf(p.y * s + bi, 0.f));
            }
        }
    }
}

// ============================================================================
// conv_kq: z=0 -> K[b][k][n] ; z=1 -> QT[b][m][k]  (R8 verbatim)
// ============================================================================
__global__ void __launch_bounds__(256, 2) conv_kq_kernel(
    const float* __restrict__ Xen, const float* __restrict__ Xde,
    const float* __restrict__ W,
    const float* __restrict__ gam, const float* __restrict__ bet,
    const float* __restrict__ mean, const float* __restrict__ var)
{
    __shared__ __align__(16) float Ws[2][32 * 20];
    __shared__ __align__(16) float Xs[2][16 * 132];
    __shared__ float scale_s[32], bias_s[32];

    const int t  = threadIdx.x;
    const int b  = blockIdx.y;
    const int n0 = blockIdx.x * 128;
    const int ty = t >> 4, tx = t & 15;
    const float* X = (blockIdx.z == 0) ? Xen : Xde;

    if (t < 32) {
        float s = gam[t] * rsqrtf(var[t] + BN_EPS);
        scale_s[t] = s;
        bias_s[t]  = bet[t] - mean[t] * s;
    }

    const float* Xb = X + (size_t)b * CC * NPIX + n0;
    const uint32_t sW = smem_to_u32(Ws), sX = smem_to_u32(Xs);

    auto load_chunk = [&](int c0, int buf) {
        if (t < 128) {
            int o = t >> 2, q = t & 3;
            cp16(sW + (uint32_t)(buf * 32 * 20 + o * 20 + q * 4) * 4,
                 W + (size_t)o * CC + c0 + q * 4);
        }
        {
            int k = t >> 4, seg = t & 15;
            uint32_t dst = sX + (uint32_t)(buf * 16 * 132 + k * 132 + seg * 8) * 4;
            const float* src = Xb + (size_t)(c0 + k) * NPIX + seg * 8;
            cp16(dst, src); cp16(dst + 16, src + 4);
        }
    };

    load_chunk(0, 0);
    CP_COMMIT();

    unsigned long long acc[2][4];
#pragma unroll
    for (int i = 0; i < 2; i++)
#pragma unroll
        for (int j = 0; j < 4; j++) acc[i][j] = 0ull;

    for (int ch = 0; ch < 8; ch++) {
        const int buf = ch & 1;
        CP_WAIT0();
        __syncthreads();
        if (ch + 1 < 8) { load_chunk((ch + 1) << 4, buf ^ 1); CP_COMMIT(); }

        const float* Wb2 = Ws[buf];
        const float* Xb2 = Xs[buf];
#pragma unroll
        for (int k4 = 0; k4 < 4; k4++) {
            unsigned long long bx[4][4];
#pragma unroll
            for (int kk = 0; kk < 4; kk++)
#pragma unroll
                for (int j = 0; j < 4; j++)
                    bx[kk][j] = *(const unsigned long long*)
                        &Xb2[(k4 * 4 + kk) * 132 + 2 * tx + 32 * j];
#pragma unroll
            for (int i = 0; i < 2; i++) {
                float4 w4 = *(const float4*)&Wb2[(ty * 2 + i) * 20 + k4 * 4];
                unsigned long long d0 = pk2(w4.x, w4.x);
                unsigned long long d1 = pk2(w4.y, w4.y);
                unsigned long long d2 = pk2(w4.z, w4.z);
                unsigned long long d3 = pk2(w4.w, w4.w);
#pragma unroll
                for (int j = 0; j < 4; j++) {
                    fma2(acc[i][j], d0, bx[0][j]);
                    fma2(acc[i][j], d1, bx[1][j]);
                    fma2(acc[i][j], d2, bx[2][j]);
                    fma2(acc[i][j], d3, bx[3][j]);
                }
            }
        }
        __syncthreads();
    }

    if (blockIdx.z == 0) {
        float* Yb = g_K + (size_t)b * C4C * NPIX + n0 + 2 * tx;
#pragma unroll
        for (int i = 0; i < 2; i++) {
            int o = ty * 2 + i;
            float s = scale_s[o], bi = bias_s[o];
#pragma unroll
            for (int j = 0; j < 4; j++) {
                float2 p = up2(acc[i][j]);
                *(float2*)&Yb[(size_t)o * NPIX + 32 * j] =
                    make_float2(fmaxf(p.x * s + bi, 0.f), fmaxf(p.y * s + bi, 0.f));
            }
        }
    } else {
        float* Yb = g_QT + (size_t)b * NPIX * C4C;
#pragma unroll
        for (int i = 0; i < 2; i++) {
            int o = ty * 2 + i;
            float s = scale_s[o], bi = bias_s[o];
#pragma unroll
            for (int j = 0; j < 4; j++) {
                float2 p = up2(acc[i][j]);
                int n = n0 + 2 * tx + 32 * j;
                Yb[(size_t)n * C4C + o]       = fmaxf(p.x * s + bi, 0.f);
                Yb[(size_t)(n + 1) * C4C + o] = fmaxf(p.y * s + bi, 0.f);
            }
        }
    }
}

// ============================================================================
// norm: M'[b] = max_n ||K[b,:,n]|| * max_m ||QT[b,m,:]||  (Cauchy-Schwarz)
// ============================================================================
__global__ void __launch_bounds__(256) norm_kernel()
{
    __shared__ float r1[256], r2[256];
    const int b = blockIdx.x, t = threadIdx.x;
    const float* Kb  = g_K  + (size_t)b * C4C * NPIX;
    const float* QTb = g_QT + (size_t)b * NPIX * C4C;

    float mk = 0.f, mq = 0.f;
    for (int n = t; n < NPIX; n += 256) {
        float sk = 0.f;
#pragma unroll
        for (int k = 0; k < C4C; k++) {
            float vk = Kb[(size_t)k * NPIX + n];
            sk += vk * vk;
        }
        mk = fmaxf(mk, sk);
        float sq = 0.f;
        const float4* qr = (const float4*)(QTb + (size_t)n * C4C);
#pragma unroll
        for (int j = 0; j < 8; j++) {
            float4 q = qr[j];
            sq += q.x * q.x + q.y * q.y + q.z * q.z + q.w * q.w;
        }
        mq = fmaxf(mq, sq);
    }
    r1[t] = mk; r2[t] = mq;
    __syncthreads();
    for (int s = 128; s > 0; s >>= 1) {
        if (t < s) { r1[t] = fmaxf(r1[t], r1[t + s]); r2[t] = fmaxf(r2[t], r2[t + s]); }
        __syncthreads();
    }
    if (t == 0) g_M[b] = sqrtf(r1[0]) * sqrtf(r2[0]);
}

// ============================================================================
// fused attention: per (n-tile 128, b), K tile resident; 36 m-chunks of 64:
//   GEMM1 (tf32 mma): L(64m x 128n) = QT @ K ; exp(L - M') -> bf16 Psm, + Z
//   GEMM2 (bf16 mma, ldmatrix): feat(128c x 128n) += Vh(128c x 64m) @ Psm
// Writes UNNORMALIZED feat; scale kernel divides by Z. No P in DRAM.
// grid (NT, B), 256 thr.
// ============================================================================
// smem layout (bytes from base):
//   Ks  f32 [32][136]           @ 0       (17408)
//   QTs f32 [2][64][36]         @ 17408   (18432)
//   Vhs bf16 [2][128][72]       @ 35840   (36864)
//   Psm bf16 [64][136]          @ 72704   (17408)
#define FS_QT_OFF  17408
#define FS_VH_OFF  35840
#define FS_PS_OFF  72704
#define FS_QT_BSZ  9216              // bytes per QT buffer
#define FS_VH_BSZ  18432             // bytes per Vh buffer
#define FS_SMEM_BYTES 90112

__global__ void __launch_bounds__(256, 2) fused_kernel(float* __restrict__ out)
{
    extern __shared__ __align__(16) char fsm[];
    __shared__ float zred[256];

    const int t  = threadIdx.x;
    const int b  = blockIdx.y;
    const int n0 = blockIdx.x * 128;
    const int lane = t & 31, wid = t >> 5;
    const int g = lane >> 2, t2 = lane & 3;
    // GEMM1 warp grid: 2m x 4n ; GEMM2 warp grid: 2c x 4n
    const int wr = wid >> 2, wn = wid & 3;
    const float Mb = g_M[b];

    const uint32_t sb  = smem_to_u32(fsm);
    float*       Ksf   = (float*)fsm;
    const float* Kg  = g_K  + (size_t)b * C4C * NPIX + n0;
    const float* QTg = g_QT + (size_t)b * NPIX * C4C;
    const uint16_t* Vg = g_Vh + (size_t)b * CC * NPIX;

    // K tile: 32 rows x 128 f32 (pad 136), 4 cp16/thread
    {
        int k = t >> 3, seg = t & 7;
        uint32_t dst = sb + (uint32_t)(k * 136 + seg * 16) * 4;
        const float* src = Kg + (size_t)k * NPIX + seg * 16;
        cp16(dst, src); cp16(dst + 16, src + 4);
        cp16(dst + 32, src + 8); cp16(dst + 48, src + 12);
    }
    // chunk loader: QT 64 rows x 32 f32 (pad 36) ; Vh 128 rows x 64 bf16 (pad 72)
    auto load_chunk = [&](int m0, int buf) {
        {
            int m = t >> 2, h = t & 3;
            uint32_t dst = sb + FS_QT_OFF + (uint32_t)buf * FS_QT_BSZ
                         + (uint32_t)(m * 36 + h * 8) * 4;
            const float* src = QTg + (size_t)(m0 + m) * C4C + h * 8;
            cp16(dst, src); cp16(dst + 16, src + 4);
        }
        {
            int c = t >> 1, h = t & 1;
            uint32_t dst = sb + FS_VH_OFF + (uint32_t)buf * FS_VH_BSZ
                         + (uint32_t)(c * 72 + h * 32) * 2;
            const uint16_t* src = Vg + (size_t)c * NPIX + m0 + h * 32;
            cp16(dst, src);      cp16(dst + 16, src + 8);
            cp16(dst + 32, src + 16); cp16(dst + 48, src + 24);
        }
    };
    load_chunk(0, 0);
    CP_COMMIT();

    // GEMM2 ldmatrix lane addressing (R7 feat pattern)
    const int arow = wr * 64 + ((lane >> 3) & 1) * 8 + (lane & 7);
    const int acol = (lane >> 4) * 8;
    const uint32_t aBase0 = sb + FS_VH_OFF + (uint32_t)(arow * 72 + acol) * 2;
    const int l16 = lane & 15;
    const uint32_t bBaseP = sb + FS_PS_OFF + (uint32_t)(l16 * 136 + wn * 32) * 2;

    float acc[4][4][4];
#pragma unroll
    for (int ct = 0; ct < 4; ct++)
#pragma unroll
        for (int nt = 0; nt < 4; nt++)
#pragma unroll
            for (int j = 0; j < 4; j++) acc[ct][nt][j] = 0.f;
    float zacc = 0.f;

    for (int ch = 0; ch < 36; ch++) {
        const int buf = ch & 1;
        CP_WAIT0();
        __syncthreads();                 // chunk ready; Psm free (GEMM2 done)
        if (ch + 1 < 36) { load_chunk((ch + 1) * 64, buf ^ 1); CP_COMMIT(); }

        const float* Qs = (const float*)(fsm + FS_QT_OFF + buf * FS_QT_BSZ);

        // ---- GEMM1: L(64m x 128n) tf32, warp tile 32m x 32n ----
        float d1[2][4][4];
#pragma unroll
        for (int i = 0; i < 2; i++)
#pragma unroll
            for (int j = 0; j < 4; j++)
#pragma unroll
                for (int q = 0; q < 4; q++) d1[i][j][q] = 0.f;

#pragma unroll
        for (int ks = 0; ks < 4; ks++) {
            const int k0 = ks * 8;
            uint32_t A[2][4];
#pragma unroll
            for (int m2 = 0; m2 < 2; m2++) {
                int m = wr * 32 + m2 * 16 + g;
                A[m2][0] = __float_as_uint(Qs[m * 36 + k0 + t2]);
                A[m2][1] = __float_as_uint(Qs[(m + 8) * 36 + k0 + t2]);
                A[m2][2] = __float_as_uint(Qs[m * 36 + k0 + 4 + t2]);
                A[m2][3] = __float_as_uint(Qs[(m + 8) * 36 + k0 + 4 + t2]);
            }
            uint32_t Bf[4][2];
#pragma unroll
            for (int nt = 0; nt < 4; nt++) {
                int n = wn * 32 + nt * 8 + g;
                Bf[nt][0] = __float_as_uint(Ksf[(k0 + t2) * 136 + n]);
                Bf[nt][1] = __float_as_uint(Ksf[(k0 + 4 + t2) * 136 + n]);
            }
#pragma unroll
            for (int m2 = 0; m2 < 2; m2++)
#pragma unroll
                for (int nt = 0; nt < 4; nt++)
                    mma_tf32(d1[m2][nt], A[m2], Bf[nt]);
        }

        // ---- exp + Z + bf16 store to Psm (banks 4g+t2: conflict-free) ----
#pragma unroll
        for (int m2 = 0; m2 < 2; m2++) {
            int mrow = wr * 32 + m2 * 16 + g;
#pragma unroll
            for (int nt = 0; nt < 4; nt++) {
                int ncol = wn * 32 + nt * 8 + 2 * t2;
                float e0 = __expf(d1[m2][nt][0] - Mb);
                float e1 = __expf(d1[m2][nt][1] - Mb);
                float e2 = __expf(d1[m2][nt][2] - Mb);
                float e3 = __expf(d1[m2][nt][3] - Mb);
                zacc += (e0 + e1) + (e2 + e3);
                *(uint32_t*)(fsm + FS_PS_OFF + (size_t)(mrow * 136 + ncol) * 2)
                    = bfpack(e0, e1);
                *(uint32_t*)(fsm + FS_PS_OFF + (size_t)((mrow + 8) * 136 + ncol) * 2)
                    = bfpack(e2, e3);
            }
        }
        __syncthreads();                 // Psm complete

        // ---- GEMM2: feat += Vh @ Psm (bf16, ldmatrix) ----
        const uint32_t aB = aBase0 + (uint32_t)buf * FS_VH_BSZ;
#pragma unroll
        for (int kk = 0; kk < 4; kk++) {
            uint32_t A2[4][4];
#pragma unroll
            for (int ct = 0; ct < 4; ct++)
                ldsm_x4(A2[ct], aB + (uint32_t)(ct * 16 * 72) * 2 + kk * 32);
            uint32_t B2[4][2];
#pragma unroll
            for (int nt = 0; nt < 4; nt++)
                ldsm_x2t(B2[nt], bBaseP + (uint32_t)(kk * 16 * 136) * 2 + nt * 16);
#pragma unroll
            for (int ct = 0; ct < 4; ct++)
#pragma unroll
                for (int nt = 0; nt < 4; nt++)
                    mma_bf16(acc[ct][nt], A2[ct], B2[nt]);
        }
    }

    // Z partial
    zred[t] = zacc;
    __syncthreads();
    for (int s = 128; s > 0; s >>= 1) {
        if (t < s) zred[t] += zred[t + s];
        __syncthreads();
    }
    if (t == 0) g_pZ[b * NT + blockIdx.x] = zred[0];

    // store unnormalized feat
    float* Ob = out + (size_t)b * (2 * CC) * NPIX + (size_t)CC * NPIX + n0;
#pragma unroll
    for (int ct = 0; ct < 4; ct++) {
        int row = wr * 64 + ct * 16 + g;
#pragma unroll
        for (int nt = 0; nt < 4; nt++) {
            int col = wn * 32 + nt * 8 + 2 * t2;
            *(float2*)&Ob[(size_t)row * NPIX + col] =
                make_float2(acc[ct][nt][0], acc[ct][nt][1]);
            *(float2*)&Ob[(size_t)(row + 8) * NPIX + col] =
                make_float2(acc[ct][nt][2], acc[ct][nt][3]);
        }
    }
}

// ============================================================================
// scale: Z[b] = sum of NT partials; feat half *= 1/Z.  grid (NT, B).
// ============================================================================
__global__ void __launch_bounds__(256) scale_kernel(float* __restrict__ out)
{
    __shared__ float zinv;
    const int t  = threadIdx.x;
    const int b  = blockIdx.y;
    const int n0 = blockIdx.x * 128;
    if (t == 0) {
        float z = 0.f;
#pragma unroll
        for (int j = 0; j < NT; j++) z += g_pZ[b * NT + j];
        zinv = 1.f / z;
    }
    __syncthreads();
    const float inv = zinv;

    const int c = t >> 1, h = t & 1;
    float* O = out + (size_t)b * (2 * CC) * NPIX + (size_t)(CC + c) * NPIX
                   + n0 + h * 64;
#pragma unroll
    for (int q = 0; q < 16; q++) {
        float4 v = *(float4*)&O[q * 4];
        v.x *= inv; v.y *= inv; v.z *= inv; v.w *= inv;
        *(float4*)&O[q * 4] = v;
    }
}

// ============================================================================
// launch
// ============================================================================
extern "C" void kernel_launch(void* const* d_in, const int* in_sizes, int n_in,
                              void* d_out, int out_size)
{
    const float* x_en   = (const float*)d_in[0];
    const float* x_de   = (const float*)d_in[1];
    const float* x_cat  = (const float*)d_in[2];
    const float* w_kq   = (const float*)d_in[3];
    const float* kq_g   = (const float*)d_in[4];
    const float* kq_b   = (const float*)d_in[5];
    const float* kq_m   = (const float*)d_in[6];
    const float* kq_v   = (const float*)d_in[7];
    const float* w_v    = (const float*)d_in[8];
    const float* v_g    = (const float*)d_in[9];
    const float* v_b    = (const float*)d_in[10];
    const float* v_m    = (const float*)d_in[11];
    const float* v_v    = (const float*)d_in[12];
    const float* w_red  = (const float*)d_in[13];
    const float* red_g  = (const float*)d_in[14];
    const float* red_b  = (const float*)d_in[15];
    const float* red_m  = (const float*)d_in[16];
    const float* red_v  = (const float*)d_in[17];
    float* out = (float*)d_out;

    uint16_t* pVh = nullptr;
    cudaGetSymbolAddress((void**)&pVh, g_Vh);

    cudaFuncSetAttribute(fused_kernel,
                         cudaFuncAttributeMaxDynamicSharedMemorySize, FS_SMEM_BYTES);

    const size_t twoCN = (size_t)2 * CC * NPIX;

    // K [k][n], QT [m][k]
    conv_kq_kernel<<<dim3(NT, BB, 2), 256>>>(x_en, x_de, w_kq,
                                             kq_g, kq_b, kq_m, kq_v);
    // M' per batch
    norm_kernel<<<BB, 256>>>();
    // x -> output channels [0, C), fp32
    conv128_kernel<<<dim3(NT, BB), 256>>>(x_cat, twoCN, 2 * CC, w_red,
                                          red_g, red_b, red_m, red_v,
                                          out, twoCN, nullptr);
    // V -> bf16
    conv128_kernel<<<dim3(NT, BB), 256>>>(out, twoCN, CC, w_v,
                                          v_g, v_b, v_m, v_v,
                                          nullptr, 0, pVh);
    // fused attention: exp(QK - M') -> feat, no P in DRAM; Z partials
    fused_kernel<<<dim3(NT, BB), 256, FS_SMEM_BYTES>>>(out);
    // normalize feat half by 1/Z
    scale_kernel<<<dim3(NT, BB), 256>>>(out);
}

// round 10
// speedup vs baseline: 2.6975x; 1.0676x over previous
#include <cuda_runtime.h>
#include <cstdint>

// Problem constants
#define BB   16
#define CC   128
#define C4C  32
#define NPIX 2304                      // H*W = 48*48
#define NT   18                        // NPIX / 128
#define BN_EPS 1e-5f

// -------- scratch (device globals; no allocation allowed) --------
__device__ float    g_K  [BB * C4C * NPIX];          // [b][k][n]
__device__ float    g_QT [BB * NPIX * C4C];          // [b][m][k]
__device__ uint16_t g_Vh [BB * CC  * NPIX];          // bf16 V [b][c][m]
__device__ uint16_t g_Wvh[CC * CC];                  // bf16 (w_v * bn_scale)
__device__ float    g_pZ [BB * NT];
__device__ float    g_M  [BB];

// -------- packed f32x2 helpers --------
__device__ __forceinline__ unsigned long long pk2(float lo, float hi) {
    unsigned long long r;
    asm("mov.b64 %0, {%1,%2};" : "=l"(r) : "f"(lo), "f"(hi));
    return r;
}
__device__ __forceinline__ float2 up2(unsigned long long v) {
    float2 r;
    asm("mov.b64 {%0,%1}, %2;" : "=f"(r.x), "=f"(r.y) : "l"(v));
    return r;
}
__device__ __forceinline__ void fma2(unsigned long long& d,
                                     unsigned long long a,
                                     unsigned long long b) {
    asm("fma.rn.f32x2 %0, %1, %2, %0;" : "+l"(d) : "l"(a), "l"(b));
}
__device__ __forceinline__ uint32_t smem_to_u32(const void* p) {
    uint32_t a;
    asm("{ .reg .u64 t; cvta.to.shared.u64 t, %1; cvt.u32.u64 %0, t; }"
        : "=r"(a) : "l"(p));
    return a;
}
__device__ __forceinline__ void cp16(uint32_t dst, const void* src) {
    asm volatile("cp.async.cg.shared.global [%0], [%1], 16;"
                 :: "r"(dst), "l"(src) : "memory");
}
#define CP_COMMIT() asm volatile("cp.async.commit_group;" ::: "memory")
#define CP_WAIT0()  asm volatile("cp.async.wait_group 0;" ::: "memory")

// pack two f32 -> bf16x2 (lo = p0, hi = p1)
__device__ __forceinline__ uint32_t bfpack(float p0, float p1) {
    uint32_t u;
    asm("cvt.rn.bf16x2.f32 %0, %1, %2;" : "=r"(u) : "f"(p1), "f"(p0));
    return u;
}

// -------- mma.sync + ldmatrix (family-portable, sm_80+) --------
__device__ __forceinline__ void ldsm_x4(uint32_t* r, uint32_t a) {
    asm volatile("ldmatrix.sync.aligned.m8n8.x4.shared.b16 {%0,%1,%2,%3}, [%4];"
        : "=r"(r[0]), "=r"(r[1]), "=r"(r[2]), "=r"(r[3]) : "r"(a));
}
__device__ __forceinline__ void ldsm_x2t(uint32_t* r, uint32_t a) {
    asm volatile("ldmatrix.sync.aligned.m8n8.x2.trans.shared.b16 {%0,%1}, [%2];"
        : "=r"(r[0]), "=r"(r[1]) : "r"(a));
}
__device__ __forceinline__ void mma_bf16(float* d, const uint32_t* a,
                                         const uint32_t* b) {
    asm volatile(
        "mma.sync.aligned.m16n8k16.row.col.f32.bf16.bf16.f32 "
        "{%0,%1,%2,%3},{%4,%5,%6,%7},{%8,%9},{%0,%1,%2,%3};"
        : "+f"(d[0]), "+f"(d[1]), "+f"(d[2]), "+f"(d[3])
        : "r"(a[0]), "r"(a[1]), "r"(a[2]), "r"(a[3]), "r"(b[0]), "r"(b[1]));
}
__device__ __forceinline__ void mma_tf32(float* d, const uint32_t* a,
                                         const uint32_t* b) {
    asm volatile(
        "mma.sync.aligned.m16n8k8.row.col.f32.tf32.tf32.f32 "
        "{%0,%1,%2,%3},{%4,%5,%6,%7},{%8,%9},{%0,%1,%2,%3};"
        : "+f"(d[0]), "+f"(d[1]), "+f"(d[2]), "+f"(d[3])
        : "r"(a[0]), "r"(a[1]), "r"(a[2]), "r"(a[3]), "r"(b[0]), "r"(b[1]));
}

// ============================================================================
// prep_wv: g_Wvh[o][c] = bf16( w_v[o][c] * gamma[o]*rsqrt(var[o]+eps) )
// ============================================================================
__global__ void __launch_bounds__(256) prep_wv_kernel(
    const float* __restrict__ W,
    const float* __restrict__ gam, const float* __restrict__ var)
{
    int i = blockIdx.x * 256 + threadIdx.x;   // over CC*CC = 16384
    if (i < CC * CC) {
        int o = i >> 7;
        float s = gam[o] * rsqrtf(var[o] + BN_EPS);
        g_Wvh[i] = (uint16_t)(bfpack(W[i] * s, 0.f) & 0xFFFF);
    }
}

// ============================================================================
// convfused: phase 1: x = relu(BN(w_red @ x_cat)) -> out fp32 + smem bf16
//            phase 2: V = relu(Wvh @ x_bf16 + bias_v) -> g_Vh (bf16 mma)
// grid (NT, B), 256 thr, dynamic smem 69632 B.
//   conv phase:  Wsf f32 [2][128*20] @ 0 (20480) ; Xsf f32 [2][16*132] @ 20480 (16896)
//   phase 2:     xh bf16 [128][136] @ 0 (34816)  ; Wvh bf16 [128][136] @ 34816
// ============================================================================
#define CF_XS_OFF   20480
#define CF_WVH_OFF  34816
#define CF_SMEM_BYTES 69632

__global__ void __launch_bounds__(256, 2) convfused_kernel(
    const float* __restrict__ X,            // x_cat [2C][N] per batch
    const float* __restrict__ W,            // w_red [C][2C]
    const float* __restrict__ gam, const float* __restrict__ bet,
    const float* __restrict__ mean, const float* __restrict__ var,
    const float* __restrict__ v_g, const float* __restrict__ v_b,
    const float* __restrict__ v_m, const float* __restrict__ v_v,
    float* __restrict__ out)
{
    extern __shared__ __align__(16) char csm[];
    __shared__ float scale_s[128], bias_s[128], biasv_s[128];

    const int t  = threadIdx.x;
    const int b  = blockIdx.y;
    const int n0 = blockIdx.x * 128;
    const int ty = t >> 4, tx = t & 15;
    const int CIN = 2 * CC;

    if (t < 128) {
        float s = gam[t] * rsqrtf(var[t] + BN_EPS);
        scale_s[t] = s;
        bias_s[t]  = bet[t] - mean[t] * s;
        float sv = v_g[t] * rsqrtf(v_v[t] + BN_EPS);
        biasv_s[t] = v_b[t] - v_m[t] * sv;
    }

    const float* Xb = X + (size_t)b * CIN * NPIX + n0;
    const uint32_t sb = smem_to_u32(csm);
    float* Wsf = (float*)csm;                       // [2][128*20]
    float* Xsf = (float*)(csm + CF_XS_OFF);         // [2][16*132]

    auto load_chunk = [&](int c0, int buf) {
        {
            int o = t >> 1, h = t & 1;
            uint32_t dst = sb + (uint32_t)(buf * 128 * 20 + o * 20 + h * 8) * 4;
            const float* src = W + (size_t)o * CIN + c0 + h * 8;
            cp16(dst, src); cp16(dst + 16, src + 4);
        }
        {
            int k = t >> 4, seg = t & 15;
            uint32_t dst = sb + CF_XS_OFF + (uint32_t)(buf * 16 * 132 + k * 132 + seg * 8) * 4;
            const float* src = Xb + (size_t)(c0 + k) * NPIX + seg * 8;
            cp16(dst, src); cp16(dst + 16, src + 4);
        }
    };

    load_chunk(0, 0);
    CP_COMMIT();

    unsigned long long acc[8][4];
#pragma unroll
    for (int i = 0; i < 8; i++)
#pragma unroll
        for (int j = 0; j < 4; j++) acc[i][j] = 0ull;

    for (int ch = 0; ch < 16; ch++) {
        const int buf = ch & 1;
        CP_WAIT0();
        __syncthreads();
        if (ch + 1 < 16) { load_chunk((ch + 1) << 4, buf ^ 1); CP_COMMIT(); }

        const float* Wb2 = Wsf + buf * 128 * 20;
        const float* Xb2 = Xsf + buf * 16 * 132;
#pragma unroll
        for (int k4 = 0; k4 < 4; k4++) {
            unsigned long long bx[4][4];
#pragma unroll
            for (int kk = 0; kk < 4; kk++)
#pragma unroll
                for (int j = 0; j < 4; j++)
                    bx[kk][j] = *(const unsigned long long*)
                        &Xb2[(k4 * 4 + kk) * 132 + 2 * tx + 32 * j];
#pragma unroll
            for (int i = 0; i < 8; i++) {
                float4 w4 = *(const float4*)&Wb2[(ty * 8 + i) * 20 + k4 * 4];
                unsigned long long d0 = pk2(w4.x, w4.x);
                unsigned long long d1 = pk2(w4.y, w4.y);
                unsigned long long d2 = pk2(w4.z, w4.z);
                unsigned long long d3 = pk2(w4.w, w4.w);
#pragma unroll
                for (int j = 0; j < 4; j++) {
                    fma2(acc[i][j], d0, bx[0][j]);
                    fma2(acc[i][j], d1, bx[1][j]);
                    fma2(acc[i][j], d2, bx[2][j]);
                    fma2(acc[i][j], d3, bx[3][j]);
                }
            }
        }
        __syncthreads();
    }
    // conv buffers now dead; smem is repurposed: xh @ 0, Wvh @ 34816

    // kick off Wvh load (bf16, scale pre-folded): 128 rows x 128 bf16 (pad 136)
    {
        int o = t >> 1, h = t & 1;
        uint32_t dst = sb + CF_WVH_OFF + (uint32_t)(o * 136 + h * 64) * 2;
        const uint16_t* src = g_Wvh + (size_t)o * CC + h * 64;
#pragma unroll
        for (int q = 0; q < 8; q++) cp16(dst + q * 16, src + q * 8);
    }
    CP_COMMIT();

    // phase-1 epilogue: BN+relu, write fp32 out + bf16 xh
    {
        uint16_t* xh = (uint16_t*)csm;              // [128][136]
        float* Yb = out + (size_t)b * (2 * CC) * NPIX + n0 + 2 * tx;
#pragma unroll
        for (int i = 0; i < 8; i++) {
            int o = ty * 8 + i;
            float s = scale_s[o], bi = bias_s[o];
#pragma unroll
            for (int j = 0; j < 4; j++) {
                float2 p = up2(acc[i][j]);
                float r0 = fmaxf(p.x * s + bi, 0.f);
                float r1 = fmaxf(p.y * s + bi, 0.f);
                *(float2*)&Yb[(size_t)o * NPIX + 32 * j] = make_float2(r0, r1);
                *(uint32_t*)&xh[o * 136 + 2 * tx + 32 * j] = bfpack(r0, r1);
            }
        }
    }
    CP_WAIT0();
    __syncthreads();

    // ---- phase 2: V(128o x 128n) = Wvh(128o x 128c) @ xh(128c x 128n) ----
    const int lane = t & 31, wid = t >> 5;
    const int wr = wid >> 2, wn = wid & 3;
    const int g = lane >> 2, t2 = lane & 3;

    const int arow = wr * 64 + ((lane >> 3) & 1) * 8 + (lane & 7);
    const int acol = (lane >> 4) * 8;
    const uint32_t aBase = sb + CF_WVH_OFF + (uint32_t)(arow * 136 + acol) * 2;
    const int l16 = lane & 15;
    const uint32_t bBase = sb + (uint32_t)(l16 * 136 + wn * 32) * 2;

    float vac[4][4][4];
#pragma unroll
    for (int ct = 0; ct < 4; ct++)
#pragma unroll
        for (int nt = 0; nt < 4; nt++)
#pragma unroll
            for (int j = 0; j < 4; j++) vac[ct][nt][j] = 0.f;

#pragma unroll
    for (int kk = 0; kk < 8; kk++) {
        uint32_t A2[4][4];
#pragma unroll
        for (int ct = 0; ct < 4; ct++)
            ldsm_x4(A2[ct], aBase + (uint32_t)(ct * 16 * 136) * 2 + kk * 32);
        uint32_t B2[4][2];
#pragma unroll
        for (int nt = 0; nt < 4; nt++)
            ldsm_x2t(B2[nt], bBase + (uint32_t)(kk * 16 * 136) * 2 + nt * 16);
#pragma unroll
        for (int ct = 0; ct < 4; ct++)
#pragma unroll
            for (int nt = 0; nt < 4; nt++)
                mma_bf16(vac[ct][nt], A2[ct], B2[nt]);
    }

    uint16_t* Vb = g_Vh + (size_t)b * CC * NPIX + n0;
#pragma unroll
    for (int ct = 0; ct < 4; ct++) {
        int row = wr * 64 + ct * 16 + g;
        float b0 = biasv_s[row], b1 = biasv_s[row + 8];
#pragma unroll
        for (int nt = 0; nt < 4; nt++) {
            int col = wn * 32 + nt * 8 + 2 * t2;
            *(uint32_t*)&Vb[(size_t)row * NPIX + col] =
                bfpack(fmaxf(vac[ct][nt][0] + b0, 0.f),
                       fmaxf(vac[ct][nt][1] + b0, 0.f));
            *(uint32_t*)&Vb[(size_t)(row + 8) * NPIX + col] =
                bfpack(fmaxf(vac[ct][nt][2] + b1, 0.f),
                       fmaxf(vac[ct][nt][3] + b1, 0.f));
        }
    }
}

// ============================================================================
// conv_kq: z=0 -> K[b][k][n] ; z=1 -> QT[b][m][k]  (R9 verbatim)
// ============================================================================
__global__ void __launch_bounds__(256, 2) conv_kq_kernel(
    const float* __restrict__ Xen, const float* __restrict__ Xde,
    const float* __restrict__ W,
    const float* __restrict__ gam, const float* __restrict__ bet,
    const float* __restrict__ mean, const float* __restrict__ var)
{
    __shared__ __align__(16) float Ws[2][32 * 20];
    __shared__ __align__(16) float Xs[2][16 * 132];
    __shared__ float scale_s[32], bias_s[32];

    const int t  = threadIdx.x;
    const int b  = blockIdx.y;
    const int n0 = blockIdx.x * 128;
    const int ty = t >> 4, tx = t & 15;
    const float* X = (blockIdx.z == 0) ? Xen : Xde;

    if (t < 32) {
        float s = gam[t] * rsqrtf(var[t] + BN_EPS);
        scale_s[t] = s;
        bias_s[t]  = bet[t] - mean[t] * s;
    }

    const float* Xb = X + (size_t)b * CC * NPIX + n0;
    const uint32_t sW = smem_to_u32(Ws), sX = smem_to_u32(Xs);

    auto load_chunk = [&](int c0, int buf) {
        if (t < 128) {
            int o = t >> 2, q = t & 3;
            cp16(sW + (uint32_t)(buf * 32 * 20 + o * 20 + q * 4) * 4,
                 W + (size_t)o * CC + c0 + q * 4);
        }
        {
            int k = t >> 4, seg = t & 15;
            uint32_t dst = sX + (uint32_t)(buf * 16 * 132 + k * 132 + seg * 8) * 4;
            const float* src = Xb + (size_t)(c0 + k) * NPIX + seg * 8;
            cp16(dst, src); cp16(dst + 16, src + 4);
        }
    };

    load_chunk(0, 0);
    CP_COMMIT();

    unsigned long long acc[2][4];
#pragma unroll
    for (int i = 0; i < 2; i++)
#pragma unroll
        for (int j = 0; j < 4; j++) acc[i][j] = 0ull;

    for (int ch = 0; ch < 8; ch++) {
        const int buf = ch & 1;
        CP_WAIT0();
        __syncthreads();
        if (ch + 1 < 8) { load_chunk((ch + 1) << 4, buf ^ 1); CP_COMMIT(); }

        const float* Wb2 = Ws[buf];
        const float* Xb2 = Xs[buf];
#pragma unroll
        for (int k4 = 0; k4 < 4; k4++) {
            unsigned long long bx[4][4];
#pragma unroll
            for (int kk = 0; kk < 4; kk++)
#pragma unroll
                for (int j = 0; j < 4; j++)
                    bx[kk][j] = *(const unsigned long long*)
                        &Xb2[(k4 * 4 + kk) * 132 + 2 * tx + 32 * j];
#pragma unroll
            for (int i = 0; i < 2; i++) {
                float4 w4 = *(const float4*)&Wb2[(ty * 2 + i) * 20 + k4 * 4];
                unsigned long long d0 = pk2(w4.x, w4.x);
                unsigned long long d1 = pk2(w4.y, w4.y);
                unsigned long long d2 = pk2(w4.z, w4.z);
                unsigned long long d3 = pk2(w4.w, w4.w);
#pragma unroll
                for (int j = 0; j < 4; j++) {
                    fma2(acc[i][j], d0, bx[0][j]);
                    fma2(acc[i][j], d1, bx[1][j]);
                    fma2(acc[i][j], d2, bx[2][j]);
                    fma2(acc[i][j], d3, bx[3][j]);
                }
            }
        }
        __syncthreads();
    }

    if (blockIdx.z == 0) {
        float* Yb = g_K + (size_t)b * C4C * NPIX + n0 + 2 * tx;
#pragma unroll
        for (int i = 0; i < 2; i++) {
            int o = ty * 2 + i;
            float s = scale_s[o], bi = bias_s[o];
#pragma unroll
            for (int j = 0; j < 4; j++) {
                float2 p = up2(acc[i][j]);
                *(float2*)&Yb[(size_t)o * NPIX + 32 * j] =
                    make_float2(fmaxf(p.x * s + bi, 0.f), fmaxf(p.y * s + bi, 0.f));
            }
        }
    } else {
        float* Yb = g_QT + (size_t)b * NPIX * C4C;
#pragma unroll
        for (int i = 0; i < 2; i++) {
            int o = ty * 2 + i;
            float s = scale_s[o], bi = bias_s[o];
#pragma unroll
            for (int j = 0; j < 4; j++) {
                float2 p = up2(acc[i][j]);
                int n = n0 + 2 * tx + 32 * j;
                Yb[(size_t)n * C4C + o]       = fmaxf(p.x * s + bi, 0.f);
                Yb[(size_t)(n + 1) * C4C + o] = fmaxf(p.y * s + bi, 0.f);
            }
        }
    }
}

// ============================================================================
// norm: M'[b] = max_n ||K[b,:,n]|| * max_m ||QT[b,m,:]||  (Cauchy-Schwarz)
// ============================================================================
__global__ void __launch_bounds__(256) norm_kernel()
{
    __shared__ float r1[256], r2[256];
    const int b = blockIdx.x, t = threadIdx.x;
    const float* Kb  = g_K  + (size_t)b * C4C * NPIX;
    const float* QTb = g_QT + (size_t)b * NPIX * C4C;

    float mk = 0.f, mq = 0.f;
    for (int n = t; n < NPIX; n += 256) {
        float sk = 0.f;
#pragma unroll
        for (int k = 0; k < C4C; k++) {
            float vk = Kb[(size_t)k * NPIX + n];
            sk += vk * vk;
        }
        mk = fmaxf(mk, sk);
        float sq = 0.f;
        const float4* qr = (const float4*)(QTb + (size_t)n * C4C);
#pragma unroll
        for (int j = 0; j < 8; j++) {
            float4 q = qr[j];
            sq += q.x * q.x + q.y * q.y + q.z * q.z + q.w * q.w;
        }
        mq = fmaxf(mq, sq);
    }
    r1[t] = mk; r2[t] = mq;
    __syncthreads();
    for (int s = 128; s > 0; s >>= 1) {
        if (t < s) { r1[t] = fmaxf(r1[t], r1[t + s]); r2[t] = fmaxf(r2[t], r2[t + s]); }
        __syncthreads();
    }
    if (t == 0) g_M[b] = sqrtf(r1[0]) * sqrtf(r2[0]);
}

// ============================================================================
// fused attention (R9 verbatim): per (n-tile 128, b), K tile resident;
// 36 m-chunks: GEMM1 tf32 -> exp -> bf16 Psm (+Z) -> GEMM2 bf16 ldmatrix.
// ============================================================================
#define FS_QT_OFF  17408
#define FS_VH_OFF  35840
#define FS_PS_OFF  72704
#define FS_QT_BSZ  9216
#define FS_VH_BSZ  18432
#define FS_SMEM_BYTES 90112

__global__ void __launch_bounds__(256, 2) fused_kernel(float* __restrict__ out)
{
    extern __shared__ __align__(16) char fsm[];
    __shared__ float zred[256];

    const int t  = threadIdx.x;
    const int b  = blockIdx.y;
    const int n0 = blockIdx.x * 128;
    const int lane = t & 31, wid = t >> 5;
    const int g = lane >> 2, t2 = lane & 3;
    const int wr = wid >> 2, wn = wid & 3;
    const float Mb = g_M[b];

    const uint32_t sb  = smem_to_u32(fsm);
    float*       Ksf   = (float*)fsm;
    const float* Kg  = g_K  + (size_t)b * C4C * NPIX + n0;
    const float* QTg = g_QT + (size_t)b * NPIX * C4C;
    const uint16_t* Vg = g_Vh + (size_t)b * CC * NPIX;

    {
        int k = t >> 3, seg = t & 7;
        uint32_t dst = sb + (uint32_t)(k * 136 + seg * 16) * 4;
        const float* src = Kg + (size_t)k * NPIX + seg * 16;
        cp16(dst, src); cp16(dst + 16, src + 4);
        cp16(dst + 32, src + 8); cp16(dst + 48, src + 12);
    }
    auto load_chunk = [&](int m0, int buf) {
        {
            int m = t >> 2, h = t & 3;
            uint32_t dst = sb + FS_QT_OFF + (uint32_t)buf * FS_QT_BSZ
                         + (uint32_t)(m * 36 + h * 8) * 4;
            const float* src = QTg + (size_t)(m0 + m) * C4C + h * 8;
            cp16(dst, src); cp16(dst + 16, src + 4);
        }
        {
            int c = t >> 1, h = t & 1;
            uint32_t dst = sb + FS_VH_OFF + (uint32_t)buf * FS_VH_BSZ
                         + (uint32_t)(c * 72 + h * 32) * 2;
            const uint16_t* src = Vg + (size_t)c * NPIX + m0 + h * 32;
            cp16(dst, src);      cp16(dst + 16, src + 8);
            cp16(dst + 32, src + 16); cp16(dst + 48, src + 24);
        }
    };
    load_chunk(0, 0);
    CP_COMMIT();

    const int arow = wr * 64 + ((lane >> 3) & 1) * 8 + (lane & 7);
    const int acol = (lane >> 4) * 8;
    const uint32_t aBase0 = sb + FS_VH_OFF + (uint32_t)(arow * 72 + acol) * 2;
    const int l16 = lane & 15;
    const uint32_t bBaseP = sb + FS_PS_OFF + (uint32_t)(l16 * 136 + wn * 32) * 2;

    float acc[4][4][4];
#pragma unroll
    for (int ct = 0; ct < 4; ct++)
#pragma unroll
        for (int nt = 0; nt < 4; nt++)
#pragma unroll
            for (int j = 0; j < 4; j++) acc[ct][nt][j] = 0.f;
    float zacc = 0.f;

    for (int ch = 0; ch < 36; ch++) {
        const int buf = ch & 1;
        CP_WAIT0();
        __syncthreads();
        if (ch + 1 < 36) { load_chunk((ch + 1) * 64, buf ^ 1); CP_COMMIT(); }

        const float* Qs = (const float*)(fsm + FS_QT_OFF + buf * FS_QT_BSZ);

        float d1[2][4][4];
#pragma unroll
        for (int i = 0; i < 2; i++)
#pragma unroll
            for (int j = 0; j < 4; j++)
#pragma unroll
                for (int q = 0; q < 4; q++) d1[i][j][q] = 0.f;

#pragma unroll
        for (int ks = 0; ks < 4; ks++) {
            const int k0 = ks * 8;
            uint32_t A[2][4];
#pragma unroll
            for (int m2 = 0; m2 < 2; m2++) {
                int m = wr * 32 + m2 * 16 + g;
                A[m2][0] = __float_as_uint(Qs[m * 36 + k0 + t2]);
                A[m2][1] = __float_as_uint(Qs[(m + 8) * 36 + k0 + t2]);
                A[m2][2] = __float_as_uint(Qs[m * 36 + k0 + 4 + t2]);
                A[m2][3] = __float_as_uint(Qs[(m + 8) * 36 + k0 + 4 + t2]);
            }
            uint32_t Bf[4][2];
#pragma unroll
            for (int nt = 0; nt < 4; nt++) {
                int n = wn * 32 + nt * 8 + g;
                Bf[nt][0] = __float_as_uint(Ksf[(k0 + t2) * 136 + n]);
                Bf[nt][1] = __float_as_uint(Ksf[(k0 + 4 + t2) * 136 + n]);
            }
#pragma unroll
            for (int m2 = 0; m2 < 2; m2++)
#pragma unroll
                for (int nt = 0; nt < 4; nt++)
                    mma_tf32(d1[m2][nt], A[m2], Bf[nt]);
        }

#pragma unroll
        for (int m2 = 0; m2 < 2; m2++) {
            int mrow = wr * 32 + m2 * 16 + g;
#pragma unroll
            for (int nt = 0; nt < 4; nt++) {
                int ncol = wn * 32 + nt * 8 + 2 * t2;
                float e0 = __expf(d1[m2][nt][0] - Mb);
                float e1 = __expf(d1[m2][nt][1] - Mb);
                float e2 = __expf(d1[m2][nt][2] - Mb);
                float e3 = __expf(d1[m2][nt][3] - Mb);
                zacc += (e0 + e1) + (e2 + e3);
                *(uint32_t*)(fsm + FS_PS_OFF + (size_t)(mrow * 136 + ncol) * 2)
                    = bfpack(e0, e1);
                *(uint32_t*)(fsm + FS_PS_OFF + (size_t)((mrow + 8) * 136 + ncol) * 2)
                    = bfpack(e2, e3);
            }
        }
        __syncthreads();

        const uint32_t aB = aBase0 + (uint32_t)buf * FS_VH_BSZ;
#pragma unroll
        for (int kk = 0; kk < 4; kk++) {
            uint32_t A2[4][4];
#pragma unroll
            for (int ct = 0; ct < 4; ct++)
                ldsm_x4(A2[ct], aB + (uint32_t)(ct * 16 * 72) * 2 + kk * 32);
            uint32_t B2[4][2];
#pragma unroll
            for (int nt = 0; nt < 4; nt++)
                ldsm_x2t(B2[nt], bBaseP + (uint32_t)(kk * 16 * 136) * 2 + nt * 16);
#pragma unroll
            for (int ct = 0; ct < 4; ct++)
#pragma unroll
                for (int nt = 0; nt < 4; nt++)
                    mma_bf16(acc[ct][nt], A2[ct], B2[nt]);
        }
    }

    zred[t] = zacc;
    __syncthreads();
    for (int s = 128; s > 0; s >>= 1) {
        if (t < s) zred[t] += zred[t + s];
        __syncthreads();
    }
    if (t == 0) g_pZ[b * NT + blockIdx.x] = zred[0];

    float* Ob = out + (size_t)b * (2 * CC) * NPIX + (size_t)CC * NPIX + n0;
#pragma unroll
    for (int ct = 0; ct < 4; ct++) {
        int row = wr * 64 + ct * 16 + g;
#pragma unroll
        for (int nt = 0; nt < 4; nt++) {
            int col = wn * 32 + nt * 8 + 2 * t2;
            *(float2*)&Ob[(size_t)row * NPIX + col] =
                make_float2(acc[ct][nt][0], acc[ct][nt][1]);
            *(float2*)&Ob[(size_t)(row + 8) * NPIX + col] =
                make_float2(acc[ct][nt][2], acc[ct][nt][3]);
        }
    }
}

// ============================================================================
// scale: Z[b] = sum of NT partials; feat half *= 1/Z.  grid (NT, B).
// ============================================================================
__global__ void __launch_bounds__(256) scale_kernel(float* __restrict__ out)
{
    __shared__ float zinv;
    const int t  = threadIdx.x;
    const int b  = blockIdx.y;
    const int n0 = blockIdx.x * 128;
    if (t == 0) {
        float z = 0.f;
#pragma unroll
        for (int j = 0; j < NT; j++) z += g_pZ[b * NT + j];
        zinv = 1.f / z;
    }
    __syncthreads();
    const float inv = zinv;

    const int c = t >> 1, h = t & 1;
    float* O = out + (size_t)b * (2 * CC) * NPIX + (size_t)(CC + c) * NPIX
                   + n0 + h * 64;
#pragma unroll
    for (int q = 0; q < 16; q++) {
        float4 v = *(float4*)&O[q * 4];
        v.x *= inv; v.y *= inv; v.z *= inv; v.w *= inv;
        *(float4*)&O[q * 4] = v;
    }
}

// ============================================================================
// launch
// ============================================================================
extern "C" void kernel_launch(void* const* d_in, const int* in_sizes, int n_in,
                              void* d_out, int out_size)
{
    const float* x_en   = (const float*)d_in[0];
    const float* x_de   = (const float*)d_in[1];
    const float* x_cat  = (const float*)d_in[2];
    const float* w_kq   = (const float*)d_in[3];
    const float* kq_g   = (const float*)d_in[4];
    const float* kq_b   = (const float*)d_in[5];
    const float* kq_m   = (const float*)d_in[6];
    const float* kq_v   = (const float*)d_in[7];
    const float* w_v    = (const float*)d_in[8];
    const float* v_g    = (const float*)d_in[9];
    const float* v_b    = (const float*)d_in[10];
    const float* v_m    = (const float*)d_in[11];
    const float* v_v    = (const float*)d_in[12];
    const float* w_red  = (const float*)d_in[13];
    const float* red_g  = (const float*)d_in[14];
    const float* red_b  = (const float*)d_in[15];
    const float* red_m  = (const float*)d_in[16];
    const float* red_v  = (const float*)d_in[17];
    float* out = (float*)d_out;

    cudaFuncSetAttribute(convfused_kernel,
                         cudaFuncAttributeMaxDynamicSharedMemorySize, CF_SMEM_BYTES);
    cudaFuncSetAttribute(fused_kernel,
                         cudaFuncAttributeMaxDynamicSharedMemorySize, FS_SMEM_BYTES);

    // w_v * bn_scale -> bf16
    prep_wv_kernel<<<64, 256>>>(w_v, v_g, v_v);
    // K [k][n], QT [m][k]
    conv_kq_kernel<<<dim3(NT, BB, 2), 256>>>(x_en, x_de, w_kq,
                                             kq_g, kq_b, kq_m, kq_v);
    // M' per batch
    norm_kernel<<<BB, 256>>>();
    // x -> out[0:C) fp32 ; V = relu(BN(w_v @ x)) -> g_Vh bf16 (fused)
    convfused_kernel<<<dim3(NT, BB), 256, CF_SMEM_BYTES>>>(
        x_cat, w_red, red_g, red_b, red_m, red_v,
        v_g, v_b, v_m, v_v, out);
    // fused attention: exp(QK - M') -> feat (unnormalized) + Z partials
    fused_kernel<<<dim3(NT, BB), 256, FS_SMEM_BYTES>>>(out);
    // normalize feat half by 1/Z
    scale_kernel<<<dim3(NT, BB), 256>>>(out);
}

// round 11
// speedup vs baseline: 2.8997x; 1.0749x over previous
#include <cuda_runtime.h>
#include <cstdint>

// Problem constants
#define BB   16
#define CC   128
#define C4C  32
#define NPIX 2304                      // H*W = 48*48
#define NT   18                        // NPIX / 128
#define BN_EPS 1e-5f

// -------- scratch (device globals; no allocation allowed) --------
__device__ uint16_t g_Kh [BB * C4C * NPIX];          // bf16 K [b][k][n]
__device__ uint16_t g_QTh[BB * NPIX * C4C];          // bf16 QT [b][m][k]
__device__ uint16_t g_Vh [BB * CC  * NPIX];          // bf16 V [b][c][m]
__device__ uint16_t g_Wvh[CC * CC];                  // bf16 (w_v * bn_scale)
__device__ float    g_pZ [BB * NT];
__device__ float    g_M  [BB];

// -------- packed f32x2 helpers --------
__device__ __forceinline__ unsigned long long pk2(float lo, float hi) {
    unsigned long long r;
    asm("mov.b64 %0, {%1,%2};" : "=l"(r) : "f"(lo), "f"(hi));
    return r;
}
__device__ __forceinline__ float2 up2(unsigned long long v) {
    float2 r;
    asm("mov.b64 {%0,%1}, %2;" : "=f"(r.x), "=f"(r.y) : "l"(v));
    return r;
}
__device__ __forceinline__ void fma2(unsigned long long& d,
                                     unsigned long long a,
                                     unsigned long long b) {
    asm("fma.rn.f32x2 %0, %1, %2, %0;" : "+l"(d) : "l"(a), "l"(b));
}
__device__ __forceinline__ uint32_t smem_to_u32(const void* p) {
    uint32_t a;
    asm("{ .reg .u64 t; cvta.to.shared.u64 t, %1; cvt.u32.u64 %0, t; }"
        : "=r"(a) : "l"(p));
    return a;
}
__device__ __forceinline__ void cp16(uint32_t dst, const void* src) {
    asm volatile("cp.async.cg.shared.global [%0], [%1], 16;"
                 :: "r"(dst), "l"(src) : "memory");
}
#define CP_COMMIT() asm volatile("cp.async.commit_group;" ::: "memory")
#define CP_WAIT0()  asm volatile("cp.async.wait_group 0;" ::: "memory")

// pack two f32 -> bf16x2 (lo = p0, hi = p1)
__device__ __forceinline__ uint32_t bfpack(float p0, float p1) {
    uint32_t u;
    asm("cvt.rn.bf16x2.f32 %0, %1, %2;" : "=r"(u) : "f"(p1), "f"(p0));
    return u;
}
__device__ __forceinline__ float bflo(uint32_t u) {
    return __uint_as_float(u << 16);
}
__device__ __forceinline__ float bfhi(uint32_t u) {
    return __uint_as_float(u & 0xFFFF0000u);
}

// -------- mma.sync + ldmatrix (family-portable, sm_80+) --------
__device__ __forceinline__ void ldsm_x4(uint32_t* r, uint32_t a) {
    asm volatile("ldmatrix.sync.aligned.m8n8.x4.shared.b16 {%0,%1,%2,%3}, [%4];"
        : "=r"(r[0]), "=r"(r[1]), "=r"(r[2]), "=r"(r[3]) : "r"(a));
}
__device__ __forceinline__ void ldsm_x2t(uint32_t* r, uint32_t a) {
    asm volatile("ldmatrix.sync.aligned.m8n8.x2.trans.shared.b16 {%0,%1}, [%2];"
        : "=r"(r[0]), "=r"(r[1]) : "r"(a));
}
__device__ __forceinline__ void mma_bf16(float* d, const uint32_t* a,
                                         const uint32_t* b) {
    asm volatile(
        "mma.sync.aligned.m16n8k16.row.col.f32.bf16.bf16.f32 "
        "{%0,%1,%2,%3},{%4,%5,%6,%7},{%8,%9},{%0,%1,%2,%3};"
        : "+f"(d[0]), "+f"(d[1]), "+f"(d[2]), "+f"(d[3])
        : "r"(a[0]), "r"(a[1]), "r"(a[2]), "r"(a[3]), "r"(b[0]), "r"(b[1]));
}

// ============================================================================
// prep_wv: g_Wvh[o][c] = bf16( w_v[o][c] * gamma[o]*rsqrt(var[o]+eps) )
// ============================================================================
__global__ void __launch_bounds__(256) prep_wv_kernel(
    const float* __restrict__ W,
    const float* __restrict__ gam, const float* __restrict__ var)
{
    int i = blockIdx.x * 256 + threadIdx.x;
    if (i < CC * CC) {
        int o = i >> 7;
        float s = gam[o] * rsqrtf(var[o] + BN_EPS);
        g_Wvh[i] = (uint16_t)(bfpack(W[i] * s, 0.f) & 0xFFFF);
    }
}

// ============================================================================
// convfused (R10 verbatim): phase 1 fp32 SIMT x-conv -> out + smem bf16;
// phase 2 bf16 mma V-conv -> g_Vh.
// ============================================================================
#define CF_XS_OFF   20480
#define CF_WVH_OFF  34816
#define CF_SMEM_BYTES 69632

__global__ void __launch_bounds__(256, 2) convfused_kernel(
    const float* __restrict__ X,
    const float* __restrict__ W,
    const float* __restrict__ gam, const float* __restrict__ bet,
    const float* __restrict__ mean, const float* __restrict__ var,
    const float* __restrict__ v_g, const float* __restrict__ v_b,
    const float* __restrict__ v_m, const float* __restrict__ v_v,
    float* __restrict__ out)
{
    extern __shared__ __align__(16) char csm[];
    __shared__ float scale_s[128], bias_s[128], biasv_s[128];

    const int t  = threadIdx.x;
    const int b  = blockIdx.y;
    const int n0 = blockIdx.x * 128;
    const int ty = t >> 4, tx = t & 15;
    const int CIN = 2 * CC;

    if (t < 128) {
        float s = gam[t] * rsqrtf(var[t] + BN_EPS);
        scale_s[t] = s;
        bias_s[t]  = bet[t] - mean[t] * s;
        float sv = v_g[t] * rsqrtf(v_v[t] + BN_EPS);
        biasv_s[t] = v_b[t] - v_m[t] * sv;
    }

    const float* Xb = X + (size_t)b * CIN * NPIX + n0;
    const uint32_t sb = smem_to_u32(csm);
    float* Wsf = (float*)csm;
    float* Xsf = (float*)(csm + CF_XS_OFF);

    auto load_chunk = [&](int c0, int buf) {
        {
            int o = t >> 1, h = t & 1;
            uint32_t dst = sb + (uint32_t)(buf * 128 * 20 + o * 20 + h * 8) * 4;
            const float* src = W + (size_t)o * CIN + c0 + h * 8;
            cp16(dst, src); cp16(dst + 16, src + 4);
        }
        {
            int k = t >> 4, seg = t & 15;
            uint32_t dst = sb + CF_XS_OFF + (uint32_t)(buf * 16 * 132 + k * 132 + seg * 8) * 4;
            const float* src = Xb + (size_t)(c0 + k) * NPIX + seg * 8;
            cp16(dst, src); cp16(dst + 16, src + 4);
        }
    };

    load_chunk(0, 0);
    CP_COMMIT();

    unsigned long long acc[8][4];
#pragma unroll
    for (int i = 0; i < 8; i++)
#pragma unroll
        for (int j = 0; j < 4; j++) acc[i][j] = 0ull;

    for (int ch = 0; ch < 16; ch++) {
        const int buf = ch & 1;
        CP_WAIT0();
        __syncthreads();
        if (ch + 1 < 16) { load_chunk((ch + 1) << 4, buf ^ 1); CP_COMMIT(); }

        const float* Wb2 = Wsf + buf * 128 * 20;
        const float* Xb2 = Xsf + buf * 16 * 132;
#pragma unroll
        for (int k4 = 0; k4 < 4; k4++) {
            unsigned long long bx[4][4];
#pragma unroll
            for (int kk = 0; kk < 4; kk++)
#pragma unroll
                for (int j = 0; j < 4; j++)
                    bx[kk][j] = *(const unsigned long long*)
                        &Xb2[(k4 * 4 + kk) * 132 + 2 * tx + 32 * j];
#pragma unroll
            for (int i = 0; i < 8; i++) {
                float4 w4 = *(const float4*)&Wb2[(ty * 8 + i) * 20 + k4 * 4];
                unsigned long long d0 = pk2(w4.x, w4.x);
                unsigned long long d1 = pk2(w4.y, w4.y);
                unsigned long long d2 = pk2(w4.z, w4.z);
                unsigned long long d3 = pk2(w4.w, w4.w);
#pragma unroll
                for (int j = 0; j < 4; j++) {
                    fma2(acc[i][j], d0, bx[0][j]);
                    fma2(acc[i][j], d1, bx[1][j]);
                    fma2(acc[i][j], d2, bx[2][j]);
                    fma2(acc[i][j], d3, bx[3][j]);
                }
            }
        }
        __syncthreads();
    }

    {
        int o = t >> 1, h = t & 1;
        uint32_t dst = sb + CF_WVH_OFF + (uint32_t)(o * 136 + h * 64) * 2;
        const uint16_t* src = g_Wvh + (size_t)o * CC + h * 64;
#pragma unroll
        for (int q = 0; q < 8; q++) cp16(dst + q * 16, src + q * 8);
    }
    CP_COMMIT();

    {
        uint16_t* xh = (uint16_t*)csm;
        float* Yb = out + (size_t)b * (2 * CC) * NPIX + n0 + 2 * tx;
#pragma unroll
        for (int i = 0; i < 8; i++) {
            int o = ty * 8 + i;
            float s = scale_s[o], bi = bias_s[o];
#pragma unroll
            for (int j = 0; j < 4; j++) {
                float2 p = up2(acc[i][j]);
                float r0 = fmaxf(p.x * s + bi, 0.f);
                float r1 = fmaxf(p.y * s + bi, 0.f);
                *(float2*)&Yb[(size_t)o * NPIX + 32 * j] = make_float2(r0, r1);
                *(uint32_t*)&xh[o * 136 + 2 * tx + 32 * j] = bfpack(r0, r1);
            }
        }
    }
    CP_WAIT0();
    __syncthreads();

    const int lane = t & 31, wid = t >> 5;
    const int wr = wid >> 2, wn = wid & 3;
    const int g = lane >> 2, t2 = lane & 3;

    const int arow = wr * 64 + ((lane >> 3) & 1) * 8 + (lane & 7);
    const int acol = (lane >> 4) * 8;
    const uint32_t aBase = sb + CF_WVH_OFF + (uint32_t)(arow * 136 + acol) * 2;
    const int l16 = lane & 15;
    const uint32_t bBase = sb + (uint32_t)(l16 * 136 + wn * 32) * 2;

    float vac[4][4][4];
#pragma unroll
    for (int ct = 0; ct < 4; ct++)
#pragma unroll
        for (int nt = 0; nt < 4; nt++)
#pragma unroll
            for (int j = 0; j < 4; j++) vac[ct][nt][j] = 0.f;

#pragma unroll
    for (int kk = 0; kk < 8; kk++) {
        uint32_t A2[4][4];
#pragma unroll
        for (int ct = 0; ct < 4; ct++)
            ldsm_x4(A2[ct], aBase + (uint32_t)(ct * 16 * 136) * 2 + kk * 32);
        uint32_t B2[4][2];
#pragma unroll
        for (int nt = 0; nt < 4; nt++)
            ldsm_x2t(B2[nt], bBase + (uint32_t)(kk * 16 * 136) * 2 + nt * 16);
#pragma unroll
        for (int ct = 0; ct < 4; ct++)
#pragma unroll
            for (int nt = 0; nt < 4; nt++)
                mma_bf16(vac[ct][nt], A2[ct], B2[nt]);
    }

    uint16_t* Vb = g_Vh + (size_t)b * CC * NPIX + n0;
#pragma unroll
    for (int ct = 0; ct < 4; ct++) {
        int row = wr * 64 + ct * 16 + g;
        float b0 = biasv_s[row], b1 = biasv_s[row + 8];
#pragma unroll
        for (int nt = 0; nt < 4; nt++) {
            int col = wn * 32 + nt * 8 + 2 * t2;
            *(uint32_t*)&Vb[(size_t)row * NPIX + col] =
                bfpack(fmaxf(vac[ct][nt][0] + b0, 0.f),
                       fmaxf(vac[ct][nt][1] + b0, 0.f));
            *(uint32_t*)&Vb[(size_t)(row + 8) * NPIX + col] =
                bfpack(fmaxf(vac[ct][nt][2] + b1, 0.f),
                       fmaxf(vac[ct][nt][3] + b1, 0.f));
        }
    }
}

// ============================================================================
// conv_kq: z=0 -> Kh bf16 [b][k][n] ; z=1 -> QTh bf16 [b][m][k]
// ============================================================================
__global__ void __launch_bounds__(256, 2) conv_kq_kernel(
    const float* __restrict__ Xen, const float* __restrict__ Xde,
    const float* __restrict__ W,
    const float* __restrict__ gam, const float* __restrict__ bet,
    const float* __restrict__ mean, const float* __restrict__ var)
{
    __shared__ __align__(16) float Ws[2][32 * 20];
    __shared__ __align__(16) float Xs[2][16 * 132];
    __shared__ float scale_s[32], bias_s[32];

    const int t  = threadIdx.x;
    const int b  = blockIdx.y;
    const int n0 = blockIdx.x * 128;
    const int ty = t >> 4, tx = t & 15;
    const float* X = (blockIdx.z == 0) ? Xen : Xde;

    if (t < 32) {
        float s = gam[t] * rsqrtf(var[t] + BN_EPS);
        scale_s[t] = s;
        bias_s[t]  = bet[t] - mean[t] * s;
    }

    const float* Xb = X + (size_t)b * CC * NPIX + n0;
    const uint32_t sW = smem_to_u32(Ws), sX = smem_to_u32(Xs);

    auto load_chunk = [&](int c0, int buf) {
        if (t < 128) {
            int o = t >> 2, q = t & 3;
            cp16(sW + (uint32_t)(buf * 32 * 20 + o * 20 + q * 4) * 4,
                 W + (size_t)o * CC + c0 + q * 4);
        }
        {
            int k = t >> 4, seg = t & 15;
            uint32_t dst = sX + (uint32_t)(buf * 16 * 132 + k * 132 + seg * 8) * 4;
            const float* src = Xb + (size_t)(c0 + k) * NPIX + seg * 8;
            cp16(dst, src); cp16(dst + 16, src + 4);
        }
    };

    load_chunk(0, 0);
    CP_COMMIT();

    unsigned long long acc[2][4];
#pragma unroll
    for (int i = 0; i < 2; i++)
#pragma unroll
        for (int j = 0; j < 4; j++) acc[i][j] = 0ull;

    for (int ch = 0; ch < 8; ch++) {
        const int buf = ch & 1;
        CP_WAIT0();
        __syncthreads();
        if (ch + 1 < 8) { load_chunk((ch + 1) << 4, buf ^ 1); CP_COMMIT(); }

        const float* Wb2 = Ws[buf];
        const float* Xb2 = Xs[buf];
#pragma unroll
        for (int k4 = 0; k4 < 4; k4++) {
            unsigned long long bx[4][4];
#pragma unroll
            for (int kk = 0; kk < 4; kk++)
#pragma unroll
                for (int j = 0; j < 4; j++)
                    bx[kk][j] = *(const unsigned long long*)
                        &Xb2[(k4 * 4 + kk) * 132 + 2 * tx + 32 * j];
#pragma unroll
            for (int i = 0; i < 2; i++) {
                float4 w4 = *(const float4*)&Wb2[(ty * 2 + i) * 20 + k4 * 4];
                unsigned long long d0 = pk2(w4.x, w4.x);
                unsigned long long d1 = pk2(w4.y, w4.y);
                unsigned long long d2 = pk2(w4.z, w4.z);
                unsigned long long d3 = pk2(w4.w, w4.w);
#pragma unroll
                for (int j = 0; j < 4; j++) {
                    fma2(acc[i][j], d0, bx[0][j]);
                    fma2(acc[i][j], d1, bx[1][j]);
                    fma2(acc[i][j], d2, bx[2][j]);
                    fma2(acc[i][j], d3, bx[3][j]);
                }
            }
        }
        __syncthreads();
    }

    if (blockIdx.z == 0) {
        uint16_t* Yb = g_Kh + (size_t)b * C4C * NPIX + n0 + 2 * tx;
#pragma unroll
        for (int i = 0; i < 2; i++) {
            int o = ty * 2 + i;
            float s = scale_s[o], bi = bias_s[o];
#pragma unroll
            for (int j = 0; j < 4; j++) {
                float2 p = up2(acc[i][j]);
                *(uint32_t*)&Yb[(size_t)o * NPIX + 32 * j] =
                    bfpack(fmaxf(p.x * s + bi, 0.f), fmaxf(p.y * s + bi, 0.f));
            }
        }
    } else {
        uint16_t* Yb = g_QTh + (size_t)b * NPIX * C4C;
#pragma unroll
        for (int i = 0; i < 2; i++) {
            int o = ty * 2 + i;
            float s = scale_s[o], bi = bias_s[o];
#pragma unroll
            for (int j = 0; j < 4; j++) {
                float2 p = up2(acc[i][j]);
                int n = n0 + 2 * tx + 32 * j;
                Yb[(size_t)n * C4C + o] =
                    (uint16_t)(bfpack(fmaxf(p.x * s + bi, 0.f), 0.f) & 0xFFFF);
                Yb[(size_t)(n + 1) * C4C + o] =
                    (uint16_t)(bfpack(fmaxf(p.y * s + bi, 0.f), 0.f) & 0xFFFF);
            }
        }
    }
}

// ============================================================================
// norm: M'[b] = max_n ||Kh[b,:,n]|| * max_m ||QTh[b,m,:]|| on bf16 values
// (Cauchy-Schwarz bound on the logits as actually computed).
// ============================================================================
__global__ void __launch_bounds__(256) norm_kernel()
{
    __shared__ float r1[256], r2[256];
    const int b = blockIdx.x, t = threadIdx.x;
    const uint16_t* Kb  = g_Kh  + (size_t)b * C4C * NPIX;
    const uint16_t* QTb = g_QTh + (size_t)b * NPIX * C4C;

    float mk = 0.f, mq = 0.f;
    for (int n = t; n < NPIX; n += 256) {
        float sk = 0.f;
#pragma unroll
        for (int k = 0; k < C4C; k++) {
            float vk = bflo((uint32_t)Kb[(size_t)k * NPIX + n]);
            sk += vk * vk;
        }
        mk = fmaxf(mk, sk);
        float sq = 0.f;
        const uint32_t* qr = (const uint32_t*)(QTb + (size_t)n * C4C);
#pragma unroll
        for (int j = 0; j < 16; j++) {
            uint32_t u = qr[j];
            float lo = bflo(u), hi = bfhi(u);
            sq += lo * lo + hi * hi;
        }
        mq = fmaxf(mq, sq);
    }
    r1[t] = mk; r2[t] = mq;
    __syncthreads();
    for (int s = 128; s > 0; s >>= 1) {
        if (t < s) { r1[t] = fmaxf(r1[t], r1[t + s]); r2[t] = fmaxf(r2[t], r2[t + s]); }
        __syncthreads();
    }
    if (t == 0) g_M[b] = sqrtf(r1[0]) * sqrtf(r2[0]);
}

// ============================================================================
// fused attention: K tile resident (bf16); 36 m-chunks of 64:
//   GEMM1 (bf16 mma, ldmatrix): L(64m x 128n) = QTh @ Kh
//   exp(L - M') -> bf16 Psm, +Z
//   GEMM2 (bf16 mma, ldmatrix): feat(128c x 128n) += Vh @ Psm
// grid (NT, B), 256 thr.
// smem (bytes): Ks bf16[32][136] @0 (8704) ; QT bf16[2][64][40] @8704 (10240) ;
//               Vh bf16[2][128][72] @18944 (36864) ; Psm bf16[64][136] @55808 (17408)
// ============================================================================
#define FS_QT_OFF  8704
#define FS_VH_OFF  18944
#define FS_PS_OFF  55808
#define FS_QT_BSZ  5120
#define FS_VH_BSZ  18432
#define FS_SMEM_BYTES 73216

__global__ void __launch_bounds__(256, 2) fused_kernel(float* __restrict__ out)
{
    extern __shared__ __align__(16) char fsm[];
    __shared__ float zred[256];

    const int t  = threadIdx.x;
    const int b  = blockIdx.y;
    const int n0 = blockIdx.x * 128;
    const int lane = t & 31, wid = t >> 5;
    const int g = lane >> 2, t2 = lane & 3;
    const int wr = wid >> 2, wn = wid & 3;
    const float Mb = g_M[b];

    const uint32_t sb = smem_to_u32(fsm);
    const uint16_t* Kg  = g_Kh  + (size_t)b * C4C * NPIX + n0;
    const uint16_t* QTg = g_QTh + (size_t)b * NPIX * C4C;
    const uint16_t* Vg  = g_Vh  + (size_t)b * CC * NPIX;

    // K tile: 32 rows x 128 bf16 (pad 136): 8 thr/row x 2 cp16
    {
        int k = t >> 3, seg = t & 7;
        uint32_t dst = sb + (uint32_t)(k * 136 + seg * 16) * 2;
        const uint16_t* src = Kg + (size_t)k * NPIX + seg * 16;
        cp16(dst, src); cp16(dst + 16, src + 8);
    }
    // chunk loader: QTh 64 rows x 32 bf16 (pad 40) ; Vh 128 rows x 64 bf16 (pad 72)
    auto load_chunk = [&](int m0, int buf) {
        {
            int m = t >> 2, sg = t & 3;
            uint32_t dst = sb + FS_QT_OFF + (uint32_t)buf * FS_QT_BSZ
                         + (uint32_t)(m * 40 + sg * 8) * 2;
            const uint16_t* src = QTg + (size_t)(m0 + m) * C4C + sg * 8;
            cp16(dst, src);
        }
        {
            int c = t >> 1, h = t & 1;
            uint32_t dst = sb + FS_VH_OFF + (uint32_t)buf * FS_VH_BSZ
                         + (uint32_t)(c * 72 + h * 32) * 2;
            const uint16_t* src = Vg + (size_t)c * NPIX + m0 + h * 32;
            cp16(dst, src);      cp16(dst + 16, src + 8);
            cp16(dst + 32, src + 16); cp16(dst + 48, src + 24);
        }
    };
    load_chunk(0, 0);
    CP_COMMIT();

    // GEMM1 ldmatrix addressing: A from QTh [64][40], B from Ks [32][136]
    const int lrow = ((lane >> 3) & 1) * 8 + (lane & 7);   // = lane&15 pattern
    const int l16  = lane & 15;
    const uint32_t aQ0 = sb + FS_QT_OFF
        + (uint32_t)((wr * 32 + lrow) * 40 + (lane >> 4) * 8) * 2;
    const uint32_t bK0 = sb + (uint32_t)(l16 * 136 + wn * 32) * 2;

    // GEMM2 ldmatrix addressing: A from Vh [128][72], B from Psm [64][136]
    const uint32_t aV0 = sb + FS_VH_OFF
        + (uint32_t)((wr * 64 + lrow) * 72 + (lane >> 4) * 8) * 2;
    const uint32_t bP0 = sb + FS_PS_OFF + (uint32_t)(l16 * 136 + wn * 32) * 2;

    float acc[4][4][4];
#pragma unroll
    for (int ct = 0; ct < 4; ct++)
#pragma unroll
        for (int nt = 0; nt < 4; nt++)
#pragma unroll
            for (int j = 0; j < 4; j++) acc[ct][nt][j] = 0.f;
    float zacc = 0.f;

    for (int ch = 0; ch < 36; ch++) {
        const int buf = ch & 1;
        CP_WAIT0();
        __syncthreads();
        if (ch + 1 < 36) { load_chunk((ch + 1) * 64, buf ^ 1); CP_COMMIT(); }

        // ---- GEMM1 (bf16): L(64m x 128n), warp tile 32m x 32n, K=32 ----
        float d1[2][4][4];
#pragma unroll
        for (int i = 0; i < 2; i++)
#pragma unroll
            for (int j = 0; j < 4; j++)
#pragma unroll
                for (int q = 0; q < 4; q++) d1[i][j][q] = 0.f;

        const uint32_t aQ = aQ0 + (uint32_t)buf * FS_QT_BSZ;
#pragma unroll
        for (int kk = 0; kk < 2; kk++) {
            uint32_t A[2][4];
#pragma unroll
            for (int m2 = 0; m2 < 2; m2++)
                ldsm_x4(A[m2], aQ + (uint32_t)(m2 * 16 * 40) * 2 + kk * 32);
            uint32_t Bf[4][2];
#pragma unroll
            for (int nt = 0; nt < 4; nt++)
                ldsm_x2t(Bf[nt], bK0 + (uint32_t)(kk * 16 * 136) * 2 + nt * 16);
#pragma unroll
            for (int m2 = 0; m2 < 2; m2++)
#pragma unroll
                for (int nt = 0; nt < 4; nt++)
                    mma_bf16(d1[m2][nt], A[m2], Bf[nt]);
        }

        // ---- exp + Z + bf16 store to Psm ----
#pragma unroll
        for (int m2 = 0; m2 < 2; m2++) {
            int mrow = wr * 32 + m2 * 16 + g;
#pragma unroll
            for (int nt = 0; nt < 4; nt++) {
                int ncol = wn * 32 + nt * 8 + 2 * t2;
                float e0 = __expf(d1[m2][nt][0] - Mb);
                float e1 = __expf(d1[m2][nt][1] - Mb);
                float e2 = __expf(d1[m2][nt][2] - Mb);
                float e3 = __expf(d1[m2][nt][3] - Mb);
                zacc += (e0 + e1) + (e2 + e3);
                *(uint32_t*)(fsm + FS_PS_OFF + (size_t)(mrow * 136 + ncol) * 2)
                    = bfpack(e0, e1);
                *(uint32_t*)(fsm + FS_PS_OFF + (size_t)((mrow + 8) * 136 + ncol) * 2)
                    = bfpack(e2, e3);
            }
        }
        __syncthreads();

        // ---- GEMM2 (bf16): feat += Vh @ Psm ----
        const uint32_t aV = aV0 + (uint32_t)buf * FS_VH_BSZ;
#pragma unroll
        for (int kk = 0; kk < 4; kk++) {
            uint32_t A2[4][4];
#pragma unroll
            for (int ct = 0; ct < 4; ct++)
                ldsm_x4(A2[ct], aV + (uint32_t)(ct * 16 * 72) * 2 + kk * 32);
            uint32_t B2[4][2];
#pragma unroll
            for (int nt = 0; nt < 4; nt++)
                ldsm_x2t(B2[nt], bP0 + (uint32_t)(kk * 16 * 136) * 2 + nt * 16);
#pragma unroll
            for (int ct = 0; ct < 4; ct++)
#pragma unroll
                for (int nt = 0; nt < 4; nt++)
                    mma_bf16(acc[ct][nt], A2[ct], B2[nt]);
        }
    }

    zred[t] = zacc;
    __syncthreads();
    for (int s = 128; s > 0; s >>= 1) {
        if (t < s) zred[t] += zred[t + s];
        __syncthreads();
    }
    if (t == 0) g_pZ[b * NT + blockIdx.x] = zred[0];

    float* Ob = out + (size_t)b * (2 * CC) * NPIX + (size_t)CC * NPIX + n0;
#pragma unroll
    for (int ct = 0; ct < 4; ct++) {
        int row = wr * 64 + ct * 16 + g;
#pragma unroll
        for (int nt = 0; nt < 4; nt++) {
            int col = wn * 32 + nt * 8 + 2 * t2;
            *(float2*)&Ob[(size_t)row * NPIX + col] =
                make_float2(acc[ct][nt][0], acc[ct][nt][1]);
            *(float2*)&Ob[(size_t)(row + 8) * NPIX + col] =
                make_float2(acc[ct][nt][2], acc[ct][nt][3]);
        }
    }
}

// ============================================================================
// scale: Z[b] = sum of NT partials; feat half *= 1/Z.  grid (NT, B).
// ============================================================================
__global__ void __launch_bounds__(256) scale_kernel(float* __restrict__ out)
{
    __shared__ float zinv;
    const int t  = threadIdx.x;
    const int b  = blockIdx.y;
    const int n0 = blockIdx.x * 128;
    if (t == 0) {
        float z = 0.f;
#pragma unroll
        for (int j = 0; j < NT; j++) z += g_pZ[b * NT + j];
        zinv = 1.f / z;
    }
    __syncthreads();
    const float inv = zinv;

    const int c = t >> 1, h = t & 1;
    float* O = out + (size_t)b * (2 * CC) * NPIX + (size_t)(CC + c) * NPIX
                   + n0 + h * 64;
#pragma unroll
    for (int q = 0; q < 16; q++) {
        float4 v = *(float4*)&O[q * 4];
        v.x *= inv; v.y *= inv; v.z *= inv; v.w *= inv;
        *(float4*)&O[q * 4] = v;
    }
}

// ============================================================================
// launch
// ============================================================================
extern "C" void kernel_launch(void* const* d_in, const int* in_sizes, int n_in,
                              void* d_out, int out_size)
{
    const float* x_en   = (const float*)d_in[0];
    const float* x_de   = (const float*)d_in[1];
    const float* x_cat  = (const float*)d_in[2];
    const float* w_kq   = (const float*)d_in[3];
    const float* kq_g   = (const float*)d_in[4];
    const float* kq_b   = (const float*)d_in[5];
    const float* kq_m   = (const float*)d_in[6];
    const float* kq_v   = (const float*)d_in[7];
    const float* w_v    = (const float*)d_in[8];
    const float* v_g    = (const float*)d_in[9];
    const float* v_b    = (const float*)d_in[10];
    const float* v_m    = (const float*)d_in[11];
    const float* v_v    = (const float*)d_in[12];
    const float* w_red  = (const float*)d_in[13];
    const float* red_g  = (const float*)d_in[14];
    const float* red_b  = (const float*)d_in[15];
    const float* red_m  = (const float*)d_in[16];
    const float* red_v  = (const float*)d_in[17];
    float* out = (float*)d_out;

    cudaFuncSetAttribute(convfused_kernel,
                         cudaFuncAttributeMaxDynamicSharedMemorySize, CF_SMEM_BYTES);
    cudaFuncSetAttribute(fused_kernel,
                         cudaFuncAttributeMaxDynamicSharedMemorySize, FS_SMEM_BYTES);

    // w_v * bn_scale -> bf16
    prep_wv_kernel<<<64, 256>>>(w_v, v_g, v_v);
    // Kh bf16 [k][n], QTh bf16 [m][k]
    conv_kq_kernel<<<dim3(NT, BB, 2), 256>>>(x_en, x_de, w_kq,
                                             kq_g, kq_b, kq_m, kq_v);
    // M' per batch (on bf16 values)
    norm_kernel<<<BB, 256>>>();
    // x -> out[0:C) fp32 ; V -> g_Vh bf16 (fused)
    convfused_kernel<<<dim3(NT, BB), 256, CF_SMEM_BYTES>>>(
        x_cat, w_red, red_g, red_b, red_m, red_v,
        v_g, v_b, v_m, v_v, out);
    // fused attention, all-bf16 tensor path
    fused_kernel<<<dim3(NT, BB), 256, FS_SMEM_BYTES>>>(out);
    // normalize feat half by 1/Z
    scale_kernel<<<dim3(NT, BB), 256>>>(out);
}

// round 12
// speedup vs baseline: 3.2418x; 1.1180x over previous
#include <cuda_runtime.h>
#include <cstdint>

// Problem constants
#define BB   16
#define CC   128
#define C4C  32
#define NPIX 2304                      // H*W = 48*48
#define NT   18                        // NPIX / 128
#define BN_EPS 1e-5f

// -------- scratch (device globals; no allocation allowed) --------
__device__ uint16_t g_Kh   [BB * C4C * NPIX];        // bf16 K [b][k][n]
__device__ uint16_t g_QTh  [BB * NPIX * C4C];        // bf16 QT [b][m][k]
__device__ uint16_t g_Vh   [BB * CC  * NPIX];        // bf16 V [b][c][m]
__device__ uint16_t g_Wvh  [CC * CC];                // bf16 (w_v * bn_scale)
__device__ float    g_Wredt[CC * 2 * CC];            // tf32-rounded w_red
__device__ float    g_pZ   [BB * NT];
__device__ float    g_M    [BB];

// -------- packed f32x2 helpers --------
__device__ __forceinline__ unsigned long long pk2(float lo, float hi) {
    unsigned long long r;
    asm("mov.b64 %0, {%1,%2};" : "=l"(r) : "f"(lo), "f"(hi));
    return r;
}
__device__ __forceinline__ float2 up2(unsigned long long v) {
    float2 r;
    asm("mov.b64 {%0,%1}, %2;" : "=f"(r.x), "=f"(r.y) : "l"(v));
    return r;
}
__device__ __forceinline__ void fma2(unsigned long long& d,
                                     unsigned long long a,
                                     unsigned long long b) {
    asm("fma.rn.f32x2 %0, %1, %2, %0;" : "+l"(d) : "l"(a), "l"(b));
}
__device__ __forceinline__ uint32_t smem_to_u32(const void* p) {
    uint32_t a;
    asm("{ .reg .u64 t; cvta.to.shared.u64 t, %1; cvt.u32.u64 %0, t; }"
        : "=r"(a) : "l"(p));
    return a;
}
__device__ __forceinline__ void cp16(uint32_t dst, const void* src) {
    asm volatile("cp.async.cg.shared.global [%0], [%1], 16;"
                 :: "r"(dst), "l"(src) : "memory");
}
#define CP_COMMIT() asm volatile("cp.async.commit_group;" ::: "memory")
#define CP_WAIT0()  asm volatile("cp.async.wait_group 0;" ::: "memory")

// pack two f32 -> bf16x2 (lo = p0, hi = p1)
__device__ __forceinline__ uint32_t bfpack(float p0, float p1) {
    uint32_t u;
    asm("cvt.rn.bf16x2.f32 %0, %1, %2;" : "=r"(u) : "f"(p1), "f"(p0));
    return u;
}
__device__ __forceinline__ float bflo(uint32_t u) {
    return __uint_as_float(u << 16);
}
__device__ __forceinline__ float bfhi(uint32_t u) {
    return __uint_as_float(u & 0xFFFF0000u);
}
__device__ __forceinline__ float tf32r(float x) {
    uint32_t u;
    asm("cvt.rna.tf32.f32 %0, %1;" : "=r"(u) : "f"(x));
    return __uint_as_float(u);
}

// -------- mma.sync + ldmatrix (family-portable, sm_80+) --------
__device__ __forceinline__ void ldsm_x4(uint32_t* r, uint32_t a) {
    asm volatile("ldmatrix.sync.aligned.m8n8.x4.shared.b16 {%0,%1,%2,%3}, [%4];"
        : "=r"(r[0]), "=r"(r[1]), "=r"(r[2]), "=r"(r[3]) : "r"(a));
}
__device__ __forceinline__ void ldsm_x2t(uint32_t* r, uint32_t a) {
    asm volatile("ldmatrix.sync.aligned.m8n8.x2.trans.shared.b16 {%0,%1}, [%2];"
        : "=r"(r[0]), "=r"(r[1]) : "r"(a));
}
__device__ __forceinline__ void mma_bf16(float* d, const uint32_t* a,
                                         const uint32_t* b) {
    asm volatile(
        "mma.sync.aligned.m16n8k16.row.col.f32.bf16.bf16.f32 "
        "{%0,%1,%2,%3},{%4,%5,%6,%7},{%8,%9},{%0,%1,%2,%3};"
        : "+f"(d[0]), "+f"(d[1]), "+f"(d[2]), "+f"(d[3])
        : "r"(a[0]), "r"(a[1]), "r"(a[2]), "r"(a[3]), "r"(b[0]), "r"(b[1]));
}
__device__ __forceinline__ void mma_tf32(float* d, const uint32_t* a,
                                         const uint32_t* b) {
    asm volatile(
        "mma.sync.aligned.m16n8k8.row.col.f32.tf32.tf32.f32 "
        "{%0,%1,%2,%3},{%4,%5,%6,%7},{%8,%9},{%0,%1,%2,%3};"
        : "+f"(d[0]), "+f"(d[1]), "+f"(d[2]), "+f"(d[3])
        : "r"(a[0]), "r"(a[1]), "r"(a[2]), "r"(a[3]), "r"(b[0]), "r"(b[1]));
}

// ============================================================================
// prep: Wvh (bf16, scale folded) and Wredt (tf32-rounded, RNE, no scale)
// ============================================================================
__global__ void __launch_bounds__(256) prep_kernel(
    const float* __restrict__ Wv,
    const float* __restrict__ v_g, const float* __restrict__ v_v,
    const float* __restrict__ Wred)
{
    int i = blockIdx.x * 256 + threadIdx.x;
    if (i < CC * CC) {
        int o = i >> 7;
        float s = v_g[o] * rsqrtf(v_v[o] + BN_EPS);
        g_Wvh[i] = (uint16_t)(bfpack(Wv[i] * s, 0.f) & 0xFFFF);
    }
    if (i < CC * 2 * CC) g_Wredt[i] = tf32r(Wred[i]);
}

// ============================================================================
// convfused: phase 1 (tf32 mma): x = relu(BN(Wredt @ x_cat)), CIN=256
//            -> out fp32 + smem bf16 xh
//            phase 2 (bf16 mma): V = relu(Wvh @ xh + bias_v) -> g_Vh
// grid (NT, B), 256 thr.
// smem: Ws f32 [2][128][36] @0 (36864) ; Xs f32 [2][32][132] @36864 (33792)
// phase2 reuse: xh bf16 [128][136] @0 (34816) ; Wvh bf16 [128][136] @34816
// ============================================================================
#define CF_XS_OFF   36864
#define CF_WVH_OFF  34816
#define CF_SMEM_BYTES 70656

__global__ void __launch_bounds__(256, 2) convfused_kernel(
    const float* __restrict__ X,
    const float* __restrict__ gam, const float* __restrict__ bet,
    const float* __restrict__ mean, const float* __restrict__ var,
    const float* __restrict__ v_g, const float* __restrict__ v_b,
    const float* __restrict__ v_m, const float* __restrict__ v_v,
    float* __restrict__ out)
{
    extern __shared__ __align__(16) char csm[];
    __shared__ float scale_s[128], bias_s[128], biasv_s[128];

    const int t  = threadIdx.x;
    const int b  = blockIdx.y;
    const int n0 = blockIdx.x * 128;
    const int CIN = 2 * CC;
    const int lane = t & 31, wid = t >> 5;
    const int wr = wid >> 2, wn = wid & 3;
    const int g = lane >> 2, t2 = lane & 3;

    if (t < 128) {
        float s = gam[t] * rsqrtf(var[t] + BN_EPS);
        scale_s[t] = s;
        bias_s[t]  = bet[t] - mean[t] * s;
        float sv = v_g[t] * rsqrtf(v_v[t] + BN_EPS);
        biasv_s[t] = v_b[t] - v_m[t] * sv;
    }

    const float* Xb = X + (size_t)b * CIN * NPIX + n0;
    const uint32_t sb = smem_to_u32(csm);
    float* Wsf = (float*)csm;                       // [2][128][36]
    float* Xsf = (float*)(csm + CF_XS_OFF);         // [2][32][132]

    // chunk loader: W 128 rows x 32 f32 (pad 36); X 32 rows x 128 f32 (pad 132)
    auto load_chunk = [&](int c0, int buf) {
        {
            int o = t >> 1, h = t & 1;
            uint32_t dst = sb + (uint32_t)(buf * 128 * 36 + o * 36 + h * 16) * 4;
            const float* src = g_Wredt + (size_t)o * CIN + c0 + h * 16;
            cp16(dst, src);      cp16(dst + 16, src + 4);
            cp16(dst + 32, src + 8); cp16(dst + 48, src + 12);
        }
        {
            int k = t >> 3, seg = t & 7;
            uint32_t dst = sb + CF_XS_OFF
                         + (uint32_t)(buf * 32 * 132 + k * 132 + seg * 16) * 4;
            const float* src = Xb + (size_t)(c0 + k) * NPIX + seg * 16;
            cp16(dst, src);      cp16(dst + 16, src + 4);
            cp16(dst + 32, src + 8); cp16(dst + 48, src + 12);
        }
    };

    load_chunk(0, 0);
    CP_COMMIT();

    float acc[4][4][4];
#pragma unroll
    for (int ct = 0; ct < 4; ct++)
#pragma unroll
        for (int nt = 0; nt < 4; nt++)
#pragma unroll
            for (int j = 0; j < 4; j++) acc[ct][nt][j] = 0.f;

    for (int ch = 0; ch < 8; ch++) {
        const int buf = ch & 1;
        CP_WAIT0();
        __syncthreads();
        if (ch + 1 < 8) { load_chunk((ch + 1) << 5, buf ^ 1); CP_COMMIT(); }

        const float* Wb2 = Wsf + buf * 128 * 36;
        const float* Xb2 = Xsf + buf * 32 * 132;
#pragma unroll
        for (int ks = 0; ks < 4; ks++) {
            const int k0 = ks * 8;
            uint32_t A[4][4];
#pragma unroll
            for (int ct = 0; ct < 4; ct++) {
                int r0 = wr * 64 + ct * 16 + g;
                A[ct][0] = __float_as_uint(Wb2[r0 * 36 + k0 + t2]);
                A[ct][1] = __float_as_uint(Wb2[(r0 + 8) * 36 + k0 + t2]);
                A[ct][2] = __float_as_uint(Wb2[r0 * 36 + k0 + 4 + t2]);
                A[ct][3] = __float_as_uint(Wb2[(r0 + 8) * 36 + k0 + 4 + t2]);
            }
            uint32_t Bf[4][2];
#pragma unroll
            for (int nt = 0; nt < 4; nt++) {
                int col = wn * 32 + nt * 8 + g;
                Bf[nt][0] = __float_as_uint(Xb2[(k0 + t2) * 132 + col]);
                Bf[nt][1] = __float_as_uint(Xb2[(k0 + 4 + t2) * 132 + col]);
            }
#pragma unroll
            for (int ct = 0; ct < 4; ct++)
#pragma unroll
                for (int nt = 0; nt < 4; nt++)
                    mma_tf32(acc[ct][nt], A[ct], Bf[nt]);
        }
        __syncthreads();
    }
    __syncthreads();    // all Ws/Xs reads done before smem repurpose

    // kick off Wvh load
    {
        int o = t >> 1, h = t & 1;
        uint32_t dst = sb + CF_WVH_OFF + (uint32_t)(o * 136 + h * 64) * 2;
        const uint16_t* src = g_Wvh + (size_t)o * CC + h * 64;
#pragma unroll
        for (int q = 0; q < 8; q++) cp16(dst + q * 16, src + q * 8);
    }
    CP_COMMIT();

    // phase-1 epilogue: BN+relu in mma layout -> fp32 out + bf16 xh
    {
        uint16_t* xh = (uint16_t*)csm;              // [128][136]
        float* Yb = out + (size_t)b * (2 * CC) * NPIX + n0;
#pragma unroll
        for (int ct = 0; ct < 4; ct++) {
            int row = wr * 64 + ct * 16 + g;
            float s0 = scale_s[row],     b0 = bias_s[row];
            float s1 = scale_s[row + 8], b1 = bias_s[row + 8];
#pragma unroll
            for (int nt = 0; nt < 4; nt++) {
                int col = wn * 32 + nt * 8 + 2 * t2;
                float r0 = fmaxf(acc[ct][nt][0] * s0 + b0, 0.f);
                float r1 = fmaxf(acc[ct][nt][1] * s0 + b0, 0.f);
                float r2 = fmaxf(acc[ct][nt][2] * s1 + b1, 0.f);
                float r3 = fmaxf(acc[ct][nt][3] * s1 + b1, 0.f);
                *(float2*)&Yb[(size_t)row * NPIX + col]       = make_float2(r0, r1);
                *(float2*)&Yb[(size_t)(row + 8) * NPIX + col] = make_float2(r2, r3);
                *(uint32_t*)&xh[row * 136 + col]       = bfpack(r0, r1);
                *(uint32_t*)&xh[(row + 8) * 136 + col] = bfpack(r2, r3);
            }
        }
    }
    CP_WAIT0();
    __syncthreads();

    // ---- phase 2: V(128o x 128n) = Wvh @ xh (bf16 mma, ldmatrix) ----
    const int arow = wr * 64 + ((lane >> 3) & 1) * 8 + (lane & 7);
    const int acol = (lane >> 4) * 8;
    const uint32_t aBase = sb + CF_WVH_OFF + (uint32_t)(arow * 136 + acol) * 2;
    const int l16 = lane & 15;
    const uint32_t bBase = sb + (uint32_t)(l16 * 136 + wn * 32) * 2;

    float vac[4][4][4];
#pragma unroll
    for (int ct = 0; ct < 4; ct++)
#pragma unroll
        for (int nt = 0; nt < 4; nt++)
#pragma unroll
            for (int j = 0; j < 4; j++) vac[ct][nt][j] = 0.f;

#pragma unroll
    for (int kk = 0; kk < 8; kk++) {
        uint32_t A2[4][4];
#pragma unroll
        for (int ct = 0; ct < 4; ct++)
            ldsm_x4(A2[ct], aBase + (uint32_t)(ct * 16 * 136) * 2 + kk * 32);
        uint32_t B2[4][2];
#pragma unroll
        for (int nt = 0; nt < 4; nt++)
            ldsm_x2t(B2[nt], bBase + (uint32_t)(kk * 16 * 136) * 2 + nt * 16);
#pragma unroll
        for (int ct = 0; ct < 4; ct++)
#pragma unroll
            for (int nt = 0; nt < 4; nt++)
                mma_bf16(vac[ct][nt], A2[ct], B2[nt]);
    }

    uint16_t* Vb = g_Vh + (size_t)b * CC * NPIX + n0;
#pragma unroll
    for (int ct = 0; ct < 4; ct++) {
        int row = wr * 64 + ct * 16 + g;
        float b0 = biasv_s[row], b1 = biasv_s[row + 8];
#pragma unroll
        for (int nt = 0; nt < 4; nt++) {
            int col = wn * 32 + nt * 8 + 2 * t2;
            *(uint32_t*)&Vb[(size_t)row * NPIX + col] =
                bfpack(fmaxf(vac[ct][nt][0] + b0, 0.f),
                       fmaxf(vac[ct][nt][1] + b0, 0.f));
            *(uint32_t*)&Vb[(size_t)(row + 8) * NPIX + col] =
                bfpack(fmaxf(vac[ct][nt][2] + b1, 0.f),
                       fmaxf(vac[ct][nt][3] + b1, 0.f));
        }
    }
}

// ============================================================================
// conv_kq (R11 verbatim): z=0 -> Kh bf16 [b][k][n] ; z=1 -> QTh bf16 [b][m][k]
// ============================================================================
__global__ void __launch_bounds__(256, 2) conv_kq_kernel(
    const float* __restrict__ Xen, const float* __restrict__ Xde,
    const float* __restrict__ W,
    const float* __restrict__ gam, const float* __restrict__ bet,
    const float* __restrict__ mean, const float* __restrict__ var)
{
    __shared__ __align__(16) float Ws[2][32 * 20];
    __shared__ __align__(16) float Xs[2][16 * 132];
    __shared__ float scale_s[32], bias_s[32];

    const int t  = threadIdx.x;
    const int b  = blockIdx.y;
    const int n0 = blockIdx.x * 128;
    const int ty = t >> 4, tx = t & 15;
    const float* X = (blockIdx.z == 0) ? Xen : Xde;

    if (t < 32) {
        float s = gam[t] * rsqrtf(var[t] + BN_EPS);
        scale_s[t] = s;
        bias_s[t]  = bet[t] - mean[t] * s;
    }

    const float* Xb = X + (size_t)b * CC * NPIX + n0;
    const uint32_t sW = smem_to_u32(Ws), sX = smem_to_u32(Xs);

    auto load_chunk = [&](int c0, int buf) {
        if (t < 128) {
            int o = t >> 2, q = t & 3;
            cp16(sW + (uint32_t)(buf * 32 * 20 + o * 20 + q * 4) * 4,
                 W + (size_t)o * CC + c0 + q * 4);
        }
        {
            int k = t >> 4, seg = t & 15;
            uint32_t dst = sX + (uint32_t)(buf * 16 * 132 + k * 132 + seg * 8) * 4;
            const float* src = Xb + (size_t)(c0 + k) * NPIX + seg * 8;
            cp16(dst, src); cp16(dst + 16, src + 4);
        }
    };

    load_chunk(0, 0);
    CP_COMMIT();

    unsigned long long acc[2][4];
#pragma unroll
    for (int i = 0; i < 2; i++)
#pragma unroll
        for (int j = 0; j < 4; j++) acc[i][j] = 0ull;

    for (int ch = 0; ch < 8; ch++) {
        const int buf = ch & 1;
        CP_WAIT0();
        __syncthreads();
        if (ch + 1 < 8) { load_chunk((ch + 1) << 4, buf ^ 1); CP_COMMIT(); }

        const float* Wb2 = Ws[buf];
        const float* Xb2 = Xs[buf];
#pragma unroll
        for (int k4 = 0; k4 < 4; k4++) {
            unsigned long long bx[4][4];
#pragma unroll
            for (int kk = 0; kk < 4; kk++)
#pragma unroll
                for (int j = 0; j < 4; j++)
                    bx[kk][j] = *(const unsigned long long*)
                        &Xb2[(k4 * 4 + kk) * 132 + 2 * tx + 32 * j];
#pragma unroll
            for (int i = 0; i < 2; i++) {
                float4 w4 = *(const float4*)&Wb2[(ty * 2 + i) * 20 + k4 * 4];
                unsigned long long d0 = pk2(w4.x, w4.x);
                unsigned long long d1 = pk2(w4.y, w4.y);
                unsigned long long d2 = pk2(w4.z, w4.z);
                unsigned long long d3 = pk2(w4.w, w4.w);
#pragma unroll
                for (int j = 0; j < 4; j++) {
                    fma2(acc[i][j], d0, bx[0][j]);
                    fma2(acc[i][j], d1, bx[1][j]);
                    fma2(acc[i][j], d2, bx[2][j]);
                    fma2(acc[i][j], d3, bx[3][j]);
                }
            }
        }
        __syncthreads();
    }

    if (blockIdx.z == 0) {
        uint16_t* Yb = g_Kh + (size_t)b * C4C * NPIX + n0 + 2 * tx;
#pragma unroll
        for (int i = 0; i < 2; i++) {
            int o = ty * 2 + i;
            float s = scale_s[o], bi = bias_s[o];
#pragma unroll
            for (int j = 0; j < 4; j++) {
                float2 p = up2(acc[i][j]);
                *(uint32_t*)&Yb[(size_t)o * NPIX + 32 * j] =
                    bfpack(fmaxf(p.x * s + bi, 0.f), fmaxf(p.y * s + bi, 0.f));
            }
        }
    } else {
        uint16_t* Yb = g_QTh + (size_t)b * NPIX * C4C;
#pragma unroll
        for (int i = 0; i < 2; i++) {
            int o = ty * 2 + i;
            float s = scale_s[o], bi = bias_s[o];
#pragma unroll
            for (int j = 0; j < 4; j++) {
                float2 p = up2(acc[i][j]);
                int n = n0 + 2 * tx + 32 * j;
                Yb[(size_t)n * C4C + o] =
                    (uint16_t)(bfpack(fmaxf(p.x * s + bi, 0.f), 0.f) & 0xFFFF);
                Yb[(size_t)(n + 1) * C4C + o] =
                    (uint16_t)(bfpack(fmaxf(p.y * s + bi, 0.f), 0.f) & 0xFFFF);
            }
        }
    }
}

// ============================================================================
// norm (R11 verbatim): M'[b] from bf16 K/Q values (Cauchy-Schwarz bound)
// ============================================================================
__global__ void __launch_bounds__(256) norm_kernel()
{
    __shared__ float r1[256], r2[256];
    const int b = blockIdx.x, t = threadIdx.x;
    const uint16_t* Kb  = g_Kh  + (size_t)b * C4C * NPIX;
    const uint16_t* QTb = g_QTh + (size_t)b * NPIX * C4C;

    float mk = 0.f, mq = 0.f;
    for (int n = t; n < NPIX; n += 256) {
        float sk = 0.f;
#pragma unroll
        for (int k = 0; k < C4C; k++) {
            float vk = bflo((uint32_t)Kb[(size_t)k * NPIX + n]);
            sk += vk * vk;
        }
        mk = fmaxf(mk, sk);
        float sq = 0.f;
        const uint32_t* qr = (const uint32_t*)(QTb + (size_t)n * C4C);
#pragma unroll
        for (int j = 0; j < 16; j++) {
            uint32_t u = qr[j];
            float lo = bflo(u), hi = bfhi(u);
            sq += lo * lo + hi * hi;
        }
        mq = fmaxf(mq, sq);
    }
    r1[t] = mk; r2[t] = mq;
    __syncthreads();
    for (int s = 128; s > 0; s >>= 1) {
        if (t < s) { r1[t] = fmaxf(r1[t], r1[t + s]); r2[t] = fmaxf(r2[t], r2[t + s]); }
        __syncthreads();
    }
    if (t == 0) g_M[b] = sqrtf(r1[0]) * sqrtf(r2[0]);
}

// ============================================================================
// fused attention (R11 verbatim): all-bf16 tensor path.
// ============================================================================
#define FS_QT_OFF  8704
#define FS_VH_OFF  18944
#define FS_PS_OFF  55808
#define FS_QT_BSZ  5120
#define FS_VH_BSZ  18432
#define FS_SMEM_BYTES 73216

__global__ void __launch_bounds__(256, 2) fused_kernel(float* __restrict__ out)
{
    extern __shared__ __align__(16) char fsm[];
    __shared__ float zred[256];

    const int t  = threadIdx.x;
    const int b  = blockIdx.y;
    const int n0 = blockIdx.x * 128;
    const int lane = t & 31, wid = t >> 5;
    const int g = lane >> 2, t2 = lane & 3;
    const int wr = wid >> 2, wn = wid & 3;
    const float Mb = g_M[b];

    const uint32_t sb = smem_to_u32(fsm);
    const uint16_t* Kg  = g_Kh  + (size_t)b * C4C * NPIX + n0;
    const uint16_t* QTg = g_QTh + (size_t)b * NPIX * C4C;
    const uint16_t* Vg  = g_Vh  + (size_t)b * CC * NPIX;

    {
        int k = t >> 3, seg = t & 7;
        uint32_t dst = sb + (uint32_t)(k * 136 + seg * 16) * 2;
        const uint16_t* src = Kg + (size_t)k * NPIX + seg * 16;
        cp16(dst, src); cp16(dst + 16, src + 8);
    }
    auto load_chunk = [&](int m0, int buf) {
        {
            int m = t >> 2, sg = t & 3;
            uint32_t dst = sb + FS_QT_OFF + (uint32_t)buf * FS_QT_BSZ
                         + (uint32_t)(m * 40 + sg * 8) * 2;
            const uint16_t* src = QTg + (size_t)(m0 + m) * C4C + sg * 8;
            cp16(dst, src);
        }
        {
            int c = t >> 1, h = t & 1;
            uint32_t dst = sb + FS_VH_OFF + (uint32_t)buf * FS_VH_BSZ
                         + (uint32_t)(c * 72 + h * 32) * 2;
            const uint16_t* src = Vg + (size_t)c * NPIX + m0 + h * 32;
            cp16(dst, src);      cp16(dst + 16, src + 8);
            cp16(dst + 32, src + 16); cp16(dst + 48, src + 24);
        }
    };
    load_chunk(0, 0);
    CP_COMMIT();

    const int lrow = ((lane >> 3) & 1) * 8 + (lane & 7);
    const int l16  = lane & 15;
    const uint32_t aQ0 = sb + FS_QT_OFF
        + (uint32_t)((wr * 32 + lrow) * 40 + (lane >> 4) * 8) * 2;
    const uint32_t bK0 = sb + (uint32_t)(l16 * 136 + wn * 32) * 2;
    const uint32_t aV0 = sb + FS_VH_OFF
        + (uint32_t)((wr * 64 + lrow) * 72 + (lane >> 4) * 8) * 2;
    const uint32_t bP0 = sb + FS_PS_OFF + (uint32_t)(l16 * 136 + wn * 32) * 2;

    float acc[4][4][4];
#pragma unroll
    for (int ct = 0; ct < 4; ct++)
#pragma unroll
        for (int nt = 0; nt < 4; nt++)
#pragma unroll
            for (int j = 0; j < 4; j++) acc[ct][nt][j] = 0.f;
    float zacc = 0.f;

    for (int ch = 0; ch < 36; ch++) {
        const int buf = ch & 1;
        CP_WAIT0();
        __syncthreads();
        if (ch + 1 < 36) { load_chunk((ch + 1) * 64, buf ^ 1); CP_COMMIT(); }

        float d1[2][4][4];
#pragma unroll
        for (int i = 0; i < 2; i++)
#pragma unroll
            for (int j = 0; j < 4; j++)
#pragma unroll
                for (int q = 0; q < 4; q++) d1[i][j][q] = 0.f;

        const uint32_t aQ = aQ0 + (uint32_t)buf * FS_QT_BSZ;
#pragma unroll
        for (int kk = 0; kk < 2; kk++) {
            uint32_t A[2][4];
#pragma unroll
            for (int m2 = 0; m2 < 2; m2++)
                ldsm_x4(A[m2], aQ + (uint32_t)(m2 * 16 * 40) * 2 + kk * 32);
            uint32_t Bf[4][2];
#pragma unroll
            for (int nt = 0; nt < 4; nt++)
                ldsm_x2t(Bf[nt], bK0 + (uint32_t)(kk * 16 * 136) * 2 + nt * 16);
#pragma unroll
            for (int m2 = 0; m2 < 2; m2++)
#pragma unroll
                for (int nt = 0; nt < 4; nt++)
                    mma_bf16(d1[m2][nt], A[m2], Bf[nt]);
        }

#pragma unroll
        for (int m2 = 0; m2 < 2; m2++) {
            int mrow = wr * 32 + m2 * 16 + g;
#pragma unroll
            for (int nt = 0; nt < 4; nt++) {
                int ncol = wn * 32 + nt * 8 + 2 * t2;
                float e0 = __expf(d1[m2][nt][0] - Mb);
                float e1 = __expf(d1[m2][nt][1] - Mb);
                float e2 = __expf(d1[m2][nt][2] - Mb);
                float e3 = __expf(d1[m2][nt][3] - Mb);
                zacc += (e0 + e1) + (e2 + e3);
                *(uint32_t*)(fsm + FS_PS_OFF + (size_t)(mrow * 136 + ncol) * 2)
                    = bfpack(e0, e1);
                *(uint32_t*)(fsm + FS_PS_OFF + (size_t)((mrow + 8) * 136 + ncol) * 2)
                    = bfpack(e2, e3);
            }
        }
        __syncthreads();

        const uint32_t aV = aV0 + (uint32_t)buf * FS_VH_BSZ;
#pragma unroll
        for (int kk = 0; kk < 4; kk++) {
            uint32_t A2[4][4];
#pragma unroll
            for (int ct = 0; ct < 4; ct++)
                ldsm_x4(A2[ct], aV + (uint32_t)(ct * 16 * 72) * 2 + kk * 32);
            uint32_t B2[4][2];
#pragma unroll
            for (int nt = 0; nt < 4; nt++)
                ldsm_x2t(B2[nt], bP0 + (uint32_t)(kk * 16 * 136) * 2 + nt * 16);
#pragma unroll
            for (int ct = 0; ct < 4; ct++)
#pragma unroll
                for (int nt = 0; nt < 4; nt++)
                    mma_bf16(acc[ct][nt], A2[ct], B2[nt]);
        }
    }

    zred[t] = zacc;
    __syncthreads();
    for (int s = 128; s > 0; s >>= 1) {
        if (t < s) zred[t] += zred[t + s];
        __syncthreads();
    }
    if (t == 0) g_pZ[b * NT + blockIdx.x] = zred[0];

    float* Ob = out + (size_t)b * (2 * CC) * NPIX + (size_t)CC * NPIX + n0;
#pragma unroll
    for (int ct = 0; ct < 4; ct++) {
        int row = wr * 64 + ct * 16 + g;
#pragma unroll
        for (int nt = 0; nt < 4; nt++) {
            int col = wn * 32 + nt * 8 + 2 * t2;
            *(float2*)&Ob[(size_t)row * NPIX + col] =
                make_float2(acc[ct][nt][0], acc[ct][nt][1]);
            *(float2*)&Ob[(size_t)(row + 8) * NPIX + col] =
                make_float2(acc[ct][nt][2], acc[ct][nt][3]);
        }
    }
}

// ============================================================================
// scale (R11 verbatim)
// ============================================================================
__global__ void __launch_bounds__(256) scale_kernel(float* __restrict__ out)
{
    __shared__ float zinv;
    const int t  = threadIdx.x;
    const int b  = blockIdx.y;
    const int n0 = blockIdx.x * 128;
    if (t == 0) {
        float z = 0.f;
#pragma unroll
        for (int j = 0; j < NT; j++) z += g_pZ[b * NT + j];
        zinv = 1.f / z;
    }
    __syncthreads();
    const float inv = zinv;

    const int c = t >> 1, h = t & 1;
    float* O = out + (size_t)b * (2 * CC) * NPIX + (size_t)(CC + c) * NPIX
                   + n0 + h * 64;
#pragma unroll
    for (int q = 0; q < 16; q++) {
        float4 v = *(float4*)&O[q * 4];
        v.x *= inv; v.y *= inv; v.z *= inv; v.w *= inv;
        *(float4*)&O[q * 4] = v;
    }
}

// ============================================================================
// launch
// ============================================================================
extern "C" void kernel_launch(void* const* d_in, const int* in_sizes, int n_in,
                              void* d_out, int out_size)
{
    const float* x_en   = (const float*)d_in[0];
    const float* x_de   = (const float*)d_in[1];
    const float* x_cat  = (const float*)d_in[2];
    const float* w_kq   = (const float*)d_in[3];
    const float* kq_g   = (const float*)d_in[4];
    const float* kq_b   = (const float*)d_in[5];
    const float* kq_m   = (const float*)d_in[6];
    const float* kq_v   = (const float*)d_in[7];
    const float* w_v    = (const float*)d_in[8];
    const float* v_g    = (const float*)d_in[9];
    const float* v_b    = (const float*)d_in[10];
    const float* v_m    = (const float*)d_in[11];
    const float* v_v    = (const float*)d_in[12];
    const float* w_red  = (const float*)d_in[13];
    const float* red_g  = (const float*)d_in[14];
    const float* red_b  = (const float*)d_in[15];
    const float* red_m  = (const float*)d_in[16];
    const float* red_v  = (const float*)d_in[17];
    float* out = (float*)d_out;

    cudaFuncSetAttribute(convfused_kernel,
                         cudaFuncAttributeMaxDynamicSharedMemorySize, CF_SMEM_BYTES);
    cudaFuncSetAttribute(fused_kernel,
                         cudaFuncAttributeMaxDynamicSharedMemorySize, FS_SMEM_BYTES);

    // Wvh bf16 (scale folded) + Wredt tf32 (RNE)
    prep_kernel<<<128, 256>>>(w_v, v_g, v_v, w_red);
    // Kh bf16 [k][n], QTh bf16 [m][k]
    conv_kq_kernel<<<dim3(NT, BB, 2), 256>>>(x_en, x_de, w_kq,
                                             kq_g, kq_b, kq_m, kq_v);
    // M' per batch (on bf16 values)
    norm_kernel<<<BB, 256>>>();
    // x (tf32 mma) -> out[0:C) fp32 ; V (bf16 mma) -> g_Vh
    convfused_kernel<<<dim3(NT, BB), 256, CF_SMEM_BYTES>>>(
        x_cat, red_g, red_b, red_m, red_v,
        v_g, v_b, v_m, v_v, out);
    // fused attention, all-bf16 tensor path
    fused_kernel<<<dim3(NT, BB), 256, FS_SMEM_BYTES>>>(out);
    // normalize feat half by 1/Z
    scale_kernel<<<dim3(NT, BB), 256>>>(out);
}